// round 11
// baseline (speedup 1.0000x reference)
#include <cuda_runtime.h>
#include <cuda_fp16.h>
#include <math.h>
#include <stdint.h>

// ---------------- problem constants ----------------
#define N_ROWS   1024
#define E_DIM    512
#define QKV_DIM  1536
#define FF_DIM   2048
#define V_DIM    32000
#define N_BH     32
#define S_LEN    256

// ---------------- scratch ----------------
__device__ float g_x [N_ROWS * E_DIM];
__device__ __half g_qr[N_BH * S_LEN * 512];

// ---------------- packed fp16 planes (word = 2 consecutive-k halves) ----------------
__device__ uint32_t p_h_hi  [N_ROWS * 256],  p_h_lo  [N_ROWS * 256];
__device__ uint32_t p_qkv_hi[N_ROWS * 768];
__device__ uint32_t p_pr_hi [N_BH * S_LEN * 128];
__device__ uint32_t p_vT    [N_BH * 64 * 128];
__device__ uint32_t p_o_hi  [N_ROWS * 256],  p_o_lo  [N_ROWS * 256];
__device__ uint32_t p_g_hi  [N_ROWS * 1024], p_g_lo  [N_ROWS * 1024];

// ---------------- helpers ----------------
__device__ __forceinline__ void splitpack(float v0, float v1, uint32_t& hi, uint32_t& lo) {
    __half h0 = __float2half_rn(v0);
    __half h1 = __float2half_rn(v1);
    float r0 = v0 - __half2float(h0);
    float r1 = v1 - __half2float(h1);
    __half l0 = __float2half_rn(r0);
    __half l1 = __float2half_rn(r1);
    hi = (uint32_t)__half_as_ushort(h0) | ((uint32_t)__half_as_ushort(h1) << 16);
    lo = (uint32_t)__half_as_ushort(l0) | ((uint32_t)__half_as_ushort(l1) << 16);
}
__device__ __forceinline__ uint32_t pack_hi(float v0, float v1) {
    __half h0 = __float2half_rn(v0);
    __half h1 = __float2half_rn(v1);
    return (uint32_t)__half_as_ushort(h0) | ((uint32_t)__half_as_ushort(h1) << 16);
}

__device__ __forceinline__ float warpSum(float v) {
    #pragma unroll
    for (int o = 16; o; o >>= 1) v += __shfl_xor_sync(0xffffffffu, v, o);
    return v;
}
__device__ __forceinline__ float blockSum(float v) {
    __shared__ float sm[8];
    int lane = threadIdx.x & 31, w = threadIdx.x >> 5;
    v = warpSum(v);
    __syncthreads();
    if (lane == 0) sm[w] = v;
    __syncthreads();
    float r = 0.f;
    #pragma unroll
    for (int i = 0; i < 8; i++) r += sm[i];
    return r;
}

// ---------------- embed + input layernorm -> f32 x ----------------
__global__ void embed_ln_k(const int* __restrict__ src, const float* __restrict__ emb,
                           const float* __restrict__ s, const float* __restrict__ b,
                           float* __restrict__ out) {
    int row = blockIdx.x, t = threadIdx.x;
    int tok = src[row];
    const float SC = 22.62741699796952f;
    float v0 = emb[(size_t)tok * E_DIM + t]       * SC;
    float v1 = emb[(size_t)tok * E_DIM + t + 256] * SC;
    float mean = blockSum(v0 + v1) * (1.f / E_DIM);
    float d0 = v0 - mean, d1 = v1 - mean;
    float var = blockSum(d0 * d0 + d1 * d1) * (1.f / E_DIM);
    float r = rsqrtf(var + 1e-5f);
    out[(size_t)row * E_DIM + t]       = d0 * r * s[t]       + b[t];
    out[(size_t)row * E_DIM + t + 256] = d1 * r * s[t + 256] + b[t + 256];
}

// ---------------- layernorm f32 -> split planes ----------------
__global__ void layernorm_split_k(const float* __restrict__ in, const float* __restrict__ s,
                                  const float* __restrict__ b,
                                  uint32_t* __restrict__ oh, uint32_t* __restrict__ ol) {
    int row = blockIdx.x, t = threadIdx.x;
    float2 v = *(const float2*)(in + (size_t)row * E_DIM + 2 * t);
    float mean = blockSum(v.x + v.y) * (1.f / E_DIM);
    float d0 = v.x - mean, d1 = v.y - mean;
    float var = blockSum(d0 * d0 + d1 * d1) * (1.f / E_DIM);
    float r = rsqrtf(var + 1e-5f);
    float y0 = d0 * r * s[2 * t]     + b[2 * t];
    float y1 = d1 * r * s[2 * t + 1] + b[2 * t + 1];
    uint32_t h, l;
    splitpack(y0, y1, h, l);
    oh[(size_t)row * 256 + t] = h;
    ol[(size_t)row * 256 + t] = l;
}

// ---------------- mma / ldmatrix / cp.async primitives ----------------
#define MMA_F16(C, A0, A1, A2, A3, B0, B1)                                      \
    asm volatile("mma.sync.aligned.m16n8k16.row.col.f32.f16.f16.f32 "           \
                 "{%0,%1,%2,%3},{%4,%5,%6,%7},{%8,%9},{%0,%1,%2,%3};"           \
                 : "+f"(C[0]), "+f"(C[1]), "+f"(C[2]), "+f"(C[3])               \
                 : "r"(A0), "r"(A1), "r"(A2), "r"(A3), "r"(B0), "r"(B1))

__device__ __forceinline__ void ldsm4(uint32_t& r0, uint32_t& r1, uint32_t& r2, uint32_t& r3,
                                      uint32_t addr) {
    asm volatile("ldmatrix.sync.aligned.m8n8.x4.shared.b16 {%0,%1,%2,%3}, [%4];"
                 : "=r"(r0), "=r"(r1), "=r"(r2), "=r"(r3) : "r"(addr));
}

__device__ __forceinline__ void cp16w(uint32_t* dst, const uint32_t* src, bool pred) {
    uint32_t d = (uint32_t)__cvta_generic_to_shared(dst);
    int sz = pred ? 16 : 0;
    asm volatile("cp.async.cg.shared.global [%0], [%1], 16, %2;"
                 :: "r"(d), "l"(src), "r"(sz));
}

// ---------------- fused attention: scores + rel-bias gather + mask + softmax ----------
#define ATT_STRIDE 36
#define ATT_SMEM ((128 * ATT_STRIDE + 256 * ATT_STRIDE) * 4 + 128 * 4 * 4)
__global__ __launch_bounds__(256, 1)
void attn_k(const uint32_t* __restrict__ qkvH, const __half* __restrict__ qr,
            uint32_t* __restrict__ ph) {
    extern __shared__ uint32_t asm_[];
    uint32_t* qs = asm_;
    uint32_t* ks = asm_ + 128 * ATT_STRIDE;
    float* red = (float*)(ks + 256 * ATT_STRIDE);

    int tile = blockIdx.x;
    int bh = blockIdx.y;
    int zb = bh >> 3, zh = bh & 7;
    const uint32_t* Q = qkvH + (size_t)zb * (256 * 768) + zh * 32;
    const uint32_t* K = Q + 256;
    const __half* qrb = qr + (size_t)bh * (256 * 512);
    int l0 = tile * 128;

    int tid = threadIdx.x, lane = tid & 31, wid = tid >> 5;

    {
        int lrow = tid >> 1, seg = (tid & 1) * 16;
        const uint32_t* qrow = Q + (size_t)(l0 + lrow) * 768 + seg;
        uint32_t* qd = qs + lrow * ATT_STRIDE + seg;
        #pragma unroll
        for (int j = 0; j < 4; j++) cp16w(qd + j * 4, qrow + j * 4, true);
        const uint32_t* krow = K + (size_t)tid * 768;
        uint32_t* kd = ks + tid * ATT_STRIDE;
        #pragma unroll
        for (int j = 0; j < 8; j++) cp16w(kd + j * 4, krow + j * 4, true);
    }
    asm volatile("cp.async.commit_group;");
    asm volatile("cp.async.wait_group 0;");
    __syncthreads();

    int warpM = wid >> 2, warpN = wid & 3;
    int wm0 = warpM * 64, wn0 = warpN * 64;
    int g = lane >> 2, tg = lane & 3;
    uint32_t smQ = (uint32_t)__cvta_generic_to_shared(qs);
    uint32_t smK = (uint32_t)__cvta_generic_to_shared(ks);
    uint32_t a_base = smQ + ((uint32_t)(wm0 + (lane & 15)) * ATT_STRIDE + ((lane & 16) ? 4 : 0)) * 4;
    uint32_t b_base = smK + ((uint32_t)(wn0 + (lane & 7) + ((lane & 16) ? 8 : 0)) * ATT_STRIDE
                             + ((lane & 8) ? 4 : 0)) * 4;

    float acc[4][8][4] = {};
    #pragma unroll
    for (int c = 0; c < 4; c++) {
        uint32_t koff = (uint32_t)c * 32;
        uint32_t Bf[8][2];
        #pragma unroll
        for (int t = 0; t < 4; t++)
            ldsm4(Bf[2 * t][0], Bf[2 * t][1], Bf[2 * t + 1][0], Bf[2 * t + 1][1],
                  b_base + koff + (uint32_t)t * 16 * ATT_STRIDE * 4);
        #pragma unroll
        for (int mi = 0; mi < 4; mi++) {
            uint32_t Af[4];
            ldsm4(Af[0], Af[1], Af[2], Af[3],
                  a_base + koff + (uint32_t)mi * 16 * ATT_STRIDE * 4);
            #pragma unroll
            for (int ni = 0; ni < 8; ni++)
                MMA_F16(acc[mi][ni], Af[0], Af[1], Af[2], Af[3], Bf[ni][0], Bf[ni][1]);
        }
    }
    __syncthreads();

    #pragma unroll
    for (int mi = 0; mi < 4; mi++) {
        #pragma unroll
        for (int rr = 0; rr < 2; rr++) {
            int lrow = wm0 + mi * 16 + g + rr * 8;
            int lglob = l0 + lrow;
            const __half* qrl = qrb + (size_t)lglob * 512 + (255 - lglob);
            #pragma unroll
            for (int ni = 0; ni < 8; ni++) {
                int m = wn0 + ni * 8 + tg * 2;
                float b0 = __half2float(qrl[m]);
                float b1 = __half2float(qrl[m + 1]);
                acc[mi][ni][rr * 2]     = acc[mi][ni][rr * 2]     * 0.125f + b0 + ((m     > lglob) ? 1.f : 0.f);
                acc[mi][ni][rr * 2 + 1] = acc[mi][ni][rr * 2 + 1] * 0.125f + b1 + ((m + 1 > lglob) ? 1.f : 0.f);
            }
        }
    }

    float rmax[4][2];
    #pragma unroll
    for (int mi = 0; mi < 4; mi++)
        #pragma unroll
        for (int rr = 0; rr < 2; rr++) {
            float mx = -3.4e38f;
            #pragma unroll
            for (int ni = 0; ni < 8; ni++) {
                mx = fmaxf(mx, acc[mi][ni][rr * 2]);
                mx = fmaxf(mx, acc[mi][ni][rr * 2 + 1]);
            }
            mx = fmaxf(mx, __shfl_xor_sync(0xffffffffu, mx, 1));
            mx = fmaxf(mx, __shfl_xor_sync(0xffffffffu, mx, 2));
            int lrow = wm0 + mi * 16 + g + rr * 8;
            if (tg == 0) red[lrow * 4 + warpN] = mx;
            rmax[mi][rr] = 0.f;
        }
    __syncthreads();
    #pragma unroll
    for (int mi = 0; mi < 4; mi++)
        #pragma unroll
        for (int rr = 0; rr < 2; rr++) {
            int lrow = wm0 + mi * 16 + g + rr * 8;
            rmax[mi][rr] = fmaxf(fmaxf(red[lrow * 4 + 0], red[lrow * 4 + 1]),
                                 fmaxf(red[lrow * 4 + 2], red[lrow * 4 + 3]));
        }
    __syncthreads();

    float rsum[4][2];
    #pragma unroll
    for (int mi = 0; mi < 4; mi++)
        #pragma unroll
        for (int rr = 0; rr < 2; rr++) {
            float s = 0.f;
            #pragma unroll
            for (int ni = 0; ni < 8; ni++) {
                float e0 = expf(acc[mi][ni][rr * 2]     - rmax[mi][rr]);
                float e1 = expf(acc[mi][ni][rr * 2 + 1] - rmax[mi][rr]);
                acc[mi][ni][rr * 2] = e0; acc[mi][ni][rr * 2 + 1] = e1;
                s += e0 + e1;
            }
            s += __shfl_xor_sync(0xffffffffu, s, 1);
            s += __shfl_xor_sync(0xffffffffu, s, 2);
            int lrow = wm0 + mi * 16 + g + rr * 8;
            if (tg == 0) red[lrow * 4 + warpN] = s;
            rsum[mi][rr] = 0.f;
        }
    __syncthreads();
    #pragma unroll
    for (int mi = 0; mi < 4; mi++)
        #pragma unroll
        for (int rr = 0; rr < 2; rr++) {
            int lrow = wm0 + mi * 16 + g + rr * 8;
            rsum[mi][rr] = red[lrow * 4 + 0] + red[lrow * 4 + 1]
                         + red[lrow * 4 + 2] + red[lrow * 4 + 3];
        }

    uint32_t* pb = ph + (size_t)bh * (S_LEN * 128);
    #pragma unroll
    for (int mi = 0; mi < 4; mi++)
        #pragma unroll
        for (int rr = 0; rr < 2; rr++) {
            int lglob = l0 + wm0 + mi * 16 + g + rr * 8;
            float inv = 1.f / rsum[mi][rr];
            #pragma unroll
            for (int ni = 0; ni < 8; ni++) {
                float p0 = acc[mi][ni][rr * 2] * inv;
                float p1 = acc[mi][ni][rr * 2 + 1] * inv;
                pb[(size_t)lglob * 128 + (wn0 >> 1) + ni * 4 + tg] = pack_hi(p0, p1);
            }
        }
}

// ---------------- V transpose ----------------
__global__ void vtrans_k(const uint32_t* __restrict__ qkvH, uint32_t* __restrict__ vT) {
    __shared__ uint32_t vs[256][33];
    int bh = blockIdx.x;
    int zb = bh >> 3, zh = bh & 7;
    const uint32_t* V = qkvH + (size_t)zb * (256 * 768) + 512 + zh * 32;
    int tid = threadIdx.x;
    #pragma unroll
    for (int j = 0; j < 32; j++) {
        int idx = tid + j * 256;
        int row = idx >> 5, w = idx & 31;
        vs[row][w] = V[(size_t)row * 768 + w];
    }
    __syncthreads();
    uint32_t* o = vT + (size_t)bh * 8192;
    #pragma unroll
    for (int j = 0; j < 32; j++) {
        int idx = tid + j * 256;
        int d = idx >> 7, sw = idx & 127;
        uint32_t w0 = vs[2 * sw][d >> 1], w1 = vs[2 * sw + 1][d >> 1];
        int sh = (d & 1) * 16;
        o[idx] = ((w0 >> sh) & 0xffffu) | (((w1 >> sh) & 0xffffu) << 16);
    }
}

#define STAGES 3

// ---------------- fp16 GEMM, MT x 128 CTA tile, chunk k=16 (8 words) ----------------
// ALO: A hi+lo (2-term) vs hi only.  BF32: B is f32 in gmem, converted in-loader.
// EPI: 0 f32 out (+bias); 1 f32 splitK atomicAdd; 2 planes out bias+GELU;
//      3 planes out (+bias, Cl optional); 4 fp16 out (no bias).
template<int EPI, int NSPLIT, int ALO, int MT, int BF32>
__global__ __launch_bounds__(256, 2)
void bgemm(const uint32_t* __restrict__ Ah, const uint32_t* __restrict__ Al,
           const void* __restrict__ Bv,
           const float* __restrict__ bias,
           float* __restrict__ Cf, uint32_t* __restrict__ Ch, uint32_t* __restrict__ Cl,
           int M, int N, int Kw, int ldaw, int ldbw, int ldc,
           int aOffB, int aOffH, int bOffB, int bOffH, int cOffB, int cOffH) {
    extern __shared__ uint32_t smu[];
    constexpr int APW   = MT * 12;
    constexpr int BPW   = 128 * 12;
    constexpr int BOFFW = (1 + ALO) * APW;
    constexpr int STW   = BOFFW + BPW;
    constexpr int STB   = STW * 4;
    constexpr int WM    = MT / 2;
    constexpr int NMI   = MT / 32;

    const uint32_t* Bh = (const uint32_t*)Bv;
    const float*    Bf = (const float*)Bv;

    int z = blockIdx.z;
    int sk = z % NSPLIT;
    int zz = z / NSPLIT;
    int zb = zz >> 3, zh = zz & 7;
    Ah += (size_t)zb * aOffB + (size_t)zh * aOffH;
    if (ALO) Al += (size_t)zb * aOffB + (size_t)zh * aOffH;
    Bh += (size_t)zb * bOffB + (size_t)zh * bOffH;
    Bf += (size_t)zb * bOffB + (size_t)zh * bOffH;
    size_t cAdj = (size_t)zb * cOffB + (size_t)zh * cOffH;
    __half* C16 = 0;
    if (EPI == 4) C16 = (__half*)Cf + cAdj;
    else if (EPI <= 1) Cf += cAdj;
    else { Ch += cAdj; if (Cl) Cl += cAdj; }

    int kLenW = Kw / NSPLIT;
    int kw0   = sk * kLenW;
    int nk    = kLenW >> 3;

    int tid  = threadIdx.x;
    int lane = tid & 31, wid = tid >> 5;
    int wm0 = (wid >> 2) * WM;
    int wn0 = (wid & 3) * 32;
    int g   = lane >> 2;
    int tg  = lane & 3;
    int row0 = blockIdx.y * MT, col0 = blockIdx.x * 128;

    uint32_t smBase = (uint32_t)__cvta_generic_to_shared(smu);
    uint32_t a_off = ((uint32_t)(wm0 + (lane & 15)) * 12 + ((lane & 16) ? 4 : 0)) * 4;
    uint32_t b_off = ((uint32_t)(wn0 + (lane & 7) + ((lane & 16) ? 8 : 0)) * 12
                      + ((lane & 8) ? 4 : 0)) * 4;

    float acc[NMI][4][4] = {};

    // B loader state
    int rb = tid >> 1, sb2 = (tid & 1) * 4;     // 128 rows x 2 threads, 4-word segments
    bool bp = (col0 + rb) < N;
    float4 br[3][2];                            // f32 reg ring (BF32 path)

    auto COMPUTE = [&](int buf) {
        uint32_t sb = smBase + (uint32_t)buf * STB;
        uint32_t aH = sb + a_off;
        uint32_t aL = aH + APW * 4;
        uint32_t bH = sb + BOFFW * 4 + b_off;
        uint32_t Bhf[4][2];
        ldsm4(Bhf[0][0], Bhf[0][1], Bhf[1][0], Bhf[1][1], bH);
        ldsm4(Bhf[2][0], Bhf[2][1], Bhf[3][0], Bhf[3][1], bH + 16 * 12 * 4);
        #pragma unroll
        for (int mi = 0; mi < NMI; mi++) {
            uint32_t Af[4];
            ldsm4(Af[0], Af[1], Af[2], Af[3], aH + (uint32_t)mi * 16 * 12 * 4);
            uint32_t Lf[4];
            if (ALO) ldsm4(Lf[0], Lf[1], Lf[2], Lf[3], aL + (uint32_t)mi * 16 * 12 * 4);
            #pragma unroll
            for (int ni = 0; ni < 4; ni++) {
                MMA_F16(acc[mi][ni], Af[0], Af[1], Af[2], Af[3], Bhf[ni][0], Bhf[ni][1]);
                if (ALO)
                    MMA_F16(acc[mi][ni], Lf[0], Lf[1], Lf[2], Lf[3], Bhf[ni][0], Bhf[ni][1]);
            }
        }
    };

    auto LOADA = [&](int chunk, int buf) {
        int kws = kw0 + (chunk << 3);
        uint32_t* st = smu + buf * STW;
        if (MT == 128) {
            int r = tid >> 1, s = (tid & 1) * 4;
            cp16w(st + r * 12 + s, Ah + (size_t)(row0 + r) * ldaw + kws + s, true);
            if (ALO)
                cp16w(st + APW + r * 12 + s, Al + (size_t)(row0 + r) * ldaw + kws + s, true);
        } else {
            int r = (tid & 127) >> 1, s = (tid & 1) * 4;
            if (!ALO) {
                if (tid < 128)
                    cp16w(st + r * 12 + s, Ah + (size_t)(row0 + r) * ldaw + kws + s, true);
            } else {
                const uint32_t* srcp = (tid < 128) ? Ah : Al;
                uint32_t* dstp = st + ((tid < 128) ? 0 : APW);
                cp16w(dstp + r * 12 + s, srcp + (size_t)(row0 + r) * ldaw + kws + s, true);
            }
        }
        if (!BF32) {
            bool p = (col0 + rb) < N;
            cp16w(st + BOFFW + rb * 12 + sb2, Bh + (size_t)(col0 + rb) * ldbw + kws + sb2, p);
        }
    };

    auto LDGB = [&](int chunk, int set) {
        if (BF32) {
            int kf = (kw0 + (chunk << 3) + sb2) * 2;  // f32 column
            const float* src = Bf + (size_t)(col0 + rb) * ldbw + kf;
            float4 z4 = make_float4(0.f, 0.f, 0.f, 0.f);
            br[set][0] = bp ? *(const float4*)src : z4;
            br[set][1] = bp ? *(const float4*)(src + 4) : z4;
        }
    };
    auto STSB = [&](int set, int buf) {
        if (BF32) {
            uint32_t* d = smu + buf * STW + BOFFW + rb * 12 + sb2;
            d[0] = pack_hi(br[set][0].x, br[set][0].y);
            d[1] = pack_hi(br[set][0].z, br[set][0].w);
            d[2] = pack_hi(br[set][1].x, br[set][1].y);
            d[3] = pack_hi(br[set][1].z, br[set][1].w);
        }
    };

    int pre = (nk < STAGES - 1) ? nk : (STAGES - 1);
    for (int s = 0; s < pre; s++) {
        LOADA(s, s);
        LDGB(s, s % 3);
        asm volatile("cp.async.commit_group;");
    }
    for (int i = 0; i < nk; i++) {
        int buf = i % STAGES;
        STSB(i % 3, buf);
        asm volatile("cp.async.wait_group %0;" :: "n"(STAGES - 2));
        __syncthreads();
        COMPUTE(buf);
        int nxt = i + STAGES - 1;
        if (nxt < nk) { LOADA(nxt, nxt % STAGES); LDGB(nxt, nxt % 3); }
        asm volatile("cp.async.commit_group;");
    }

    // ---------------- epilogue ----------------
    #pragma unroll
    for (int mi = 0; mi < NMI; mi++) {
        #pragma unroll
        for (int rr = 0; rr < 2; rr++) {
            int r = row0 + wm0 + mi * 16 + g + rr * 8;
            #pragma unroll
            for (int ni = 0; ni < 4; ni++) {
                int c = col0 + wn0 + ni * 8 + tg * 2;
                float v0 = acc[mi][ni][rr * 2];
                float v1 = acc[mi][ni][rr * 2 + 1];
                if (EPI == 0) {
                    float* Crow = Cf + (size_t)r * ldc;
                    if (c + 1 < N) {
                        if (bias) { v0 += bias[c]; v1 += bias[c + 1]; }
                        *(float2*)&Crow[c] = make_float2(v0, v1);
                    } else if (c < N) {
                        if (bias) v0 += bias[c];
                        Crow[c] = v0;
                    }
                } else if (EPI == 1) {
                    float* Crow = Cf + (size_t)r * ldc;
                    if (bias && sk == 0) {
                        if (c < N)     v0 += bias[c];
                        if (c + 1 < N) v1 += bias[c + 1];
                    }
                    if (c < N)     atomicAdd(&Crow[c], v0);
                    if (c + 1 < N) atomicAdd(&Crow[c + 1], v1);
                } else if (EPI == 4) {
                    __half* Hrow = C16 + (size_t)r * ldc;
                    if (c < N)     Hrow[c]     = __float2half_rn(v0);
                    if (c + 1 < N) Hrow[c + 1] = __float2half_rn(v1);
                } else {
                    if (c < N) {
                        if (bias) { v0 += bias[c]; v1 += bias[c + 1]; }
                        if (EPI == 2) {
                            v0 = 0.5f * v0 * (1.f + erff(v0 * 0.7071067811865476f));
                            v1 = 0.5f * v1 * (1.f + erff(v1 * 0.7071067811865476f));
                        }
                        uint32_t h, l;
                        splitpack(v0, v1, h, l);
                        size_t idx = (size_t)r * ldc + (c >> 1);
                        Ch[idx] = h;
                        if (Cl) Cl[idx] = l;
                    }
                }
            }
        }
    }
}

#define SM_B(MT, ALO) (STAGES * (((1 + (ALO)) * (MT) * 12) + 128 * 12) * 4)

// ---------------- driver ----------------
extern "C" void kernel_launch(void* const* d_in, const int* in_sizes, int n_in,
                              void* d_out, int out_size) {
    const int*   src   = (const int*)  d_in[0];
    const float* emb   = (const float*)d_in[1];
    const float* rel   = (const float*)d_in[2];
    const float* nin_s = (const float*)d_in[3];
    const float* nin_b = (const float*)d_in[4];
    const float* inW   = (const float*)d_in[5];
    const float* inB   = (const float*)d_in[6];
    const float* outW  = (const float*)d_in[7];
    const float* outB  = (const float*)d_in[8];
    const float* ln1s  = (const float*)d_in[9];
    const float* ln1b  = (const float*)d_in[10];
    const float* ln2s  = (const float*)d_in[11];
    const float* ln2b  = (const float*)d_in[12];
    const float* w1    = (const float*)d_in[13];
    const float* b1    = (const float*)d_in[14];
    const float* w2    = (const float*)d_in[15];
    const float* b2    = (const float*)d_in[16];
    const float* nfs   = (const float*)d_in[17];
    const float* nfb   = (const float*)d_in[18];
    const float* decW  = (const float*)d_in[19];
    const float* decB  = (const float*)d_in[20];
    float* out = (float*)d_out;

    float *x;
    __half *qrH;
    cudaGetSymbolAddress((void**)&x,   g_x);
    cudaGetSymbolAddress((void**)&qrH, g_qr);
    uint32_t *hH,*hL,*qkvH,*prH,*vT,*oH,*oL,*gH,*gL;
    cudaGetSymbolAddress((void**)&hH,   p_h_hi);   cudaGetSymbolAddress((void**)&hL,   p_h_lo);
    cudaGetSymbolAddress((void**)&qkvH, p_qkv_hi);
    cudaGetSymbolAddress((void**)&prH,  p_pr_hi);
    cudaGetSymbolAddress((void**)&vT,   p_vT);
    cudaGetSymbolAddress((void**)&oH,   p_o_hi);   cudaGetSymbolAddress((void**)&oL,   p_o_lo);
    cudaGetSymbolAddress((void**)&gH,   p_g_hi);   cudaGetSymbolAddress((void**)&gL,   p_g_lo);

    cudaFuncSetAttribute(bgemm<3,1,1,64,1>,  cudaFuncAttributeMaxDynamicSharedMemorySize, SM_B(64,1));
    cudaFuncSetAttribute(bgemm<4,1,0,128,1>, cudaFuncAttributeMaxDynamicSharedMemorySize, SM_B(128,0));
    cudaFuncSetAttribute(bgemm<3,1,0,64,0>,  cudaFuncAttributeMaxDynamicSharedMemorySize, SM_B(64,0));
    cudaFuncSetAttribute(bgemm<1,2,1,64,1>,  cudaFuncAttributeMaxDynamicSharedMemorySize, SM_B(64,1));
    cudaFuncSetAttribute(bgemm<2,1,1,64,1>,  cudaFuncAttributeMaxDynamicSharedMemorySize, SM_B(64,1));
    cudaFuncSetAttribute(bgemm<0,1,0,128,1>, cudaFuncAttributeMaxDynamicSharedMemorySize, SM_B(128,0));
    cudaFuncSetAttribute(attn_k,             cudaFuncAttributeMaxDynamicSharedMemorySize, ATT_SMEM);

    embed_ln_k<<<N_ROWS, 256>>>(src, emb, nin_s, nin_b, x);

    for (int l = 0; l < 4; l++) {
        const float* inW_l  = inW  + (size_t)l * QKV_DIM * E_DIM;
        const float* outW_l = outW + (size_t)l * E_DIM * E_DIM;
        const float* w1_l   = w1   + (size_t)l * FF_DIM * E_DIM;
        const float* w2_l   = w2   + (size_t)l * E_DIM * FF_DIM;
        const float* inB_l  = inB  + (size_t)l * QKV_DIM;
        const float* outB_l = outB + (size_t)l * E_DIM;
        const float* b1_l   = b1   + (size_t)l * FF_DIM;
        const float* b2_l   = b2   + (size_t)l * E_DIM;

        layernorm_split_k<<<N_ROWS, 256>>>(x, ln1s + l*E_DIM, ln1b + l*E_DIM, hH, hL);

        // qkv hi plane = h @ inW^T + inB   (2-term A, B f32-direct)
        bgemm<3,1,1,64,1><<<dim3(12, 16, 1), 256, SM_B(64,1)>>>(hH, hL, inW_l, inB_l,
            (float*)0, qkvH, (uint32_t*)0, N_ROWS, QKV_DIM, 256, 256, E_DIM, 768,
            0,0, 0,0, 0,0);

        // V transpose
        vtrans_k<<<N_BH, 256>>>(qkvH, vT);

        // qr fp16 = Q @ rel^T  (1-term, B f32-direct; per-head offset 64 f32)
        bgemm<4,1,0,128,1><<<dim3(4, 2, N_BH), 256, SM_B(128,0)>>>(qkvH, (const uint32_t*)0, rel,
            (const float*)0, (float*)qrH, (uint32_t*)0, (uint32_t*)0,
            S_LEN, 511, 32, 768, E_DIM, 512,
            256*768, 32, 0, 64, 8*131072, 131072);

        // fused scores + bias + mask + softmax
        attn_k<<<dim3(2, N_BH), 256, ATT_SMEM>>>(qkvH, qrH, prH);

        // o planes = probs @ V^T  (1-term, B = vT planes)
        bgemm<3,1,0,64,0><<<dim3(1, 4, N_BH), 256, SM_B(64,0)>>>(prH, (const uint32_t*)0, vT,
            (const float*)0, (float*)0, oH, oL,
            S_LEN, 64, 128, 128, 128, 256,
            8*32768, 32768, 8*8192, 8192, 65536, 32);

        // x += o @ outW^T + outB   (splitK 2, 2-term A, B f32-direct)
        bgemm<1,2,1,64,1><<<dim3(4, 16, 2), 256, SM_B(64,1)>>>(oH, oL, outW_l, outB_l,
            x, (uint32_t*)0, (uint32_t*)0, N_ROWS, E_DIM, 256, 256, E_DIM, E_DIM,
            0,0, 0,0, 0,0);

        layernorm_split_k<<<N_ROWS, 256>>>(x, ln2s + l*E_DIM, ln2b + l*E_DIM, hH, hL);

        // g planes = gelu(h @ w1^T + b1)  (2-term A, B f32-direct)
        bgemm<2,1,1,64,1><<<dim3(16, 16, 1), 256, SM_B(64,1)>>>(hH, hL, w1_l, b1_l,
            (float*)0, gH, gL, N_ROWS, FF_DIM, 256, 256, E_DIM, 1024,
            0,0, 0,0, 0,0);

        // x += g @ w2^T + b2   (splitK 2, 2-term A, B f32-direct)
        bgemm<1,2,1,64,1><<<dim3(4, 16, 2), 256, SM_B(64,1)>>>(gH, gL, w2_l, b2_l,
            x, (uint32_t*)0, (uint32_t*)0, N_ROWS, E_DIM, 1024, 1024, FF_DIM, E_DIM,
            0,0, 0,0, 0,0);
    }

    layernorm_split_k<<<N_ROWS, 256>>>(x, nfs, nfb, hH, hL);

    // out f32 = h @ dec_w^T + dec_b   (1-term, B f32-direct)
    bgemm<0,1,0,128,1><<<dim3(250, 8, 1), 256, SM_B(128,0)>>>(hH, (const uint32_t*)0, decW, decB,
        out, (uint32_t*)0, (uint32_t*)0, N_ROWS, V_DIM, 256, 256, E_DIM, V_DIM,
        0,0, 0,0, 0,0);
}

// round 12
// speedup vs baseline: 1.5530x; 1.5530x over previous
#include <cuda_runtime.h>
#include <cuda_fp16.h>
#include <math.h>
#include <stdint.h>

// ---------------- problem constants ----------------
#define N_ROWS   1024
#define E_DIM    512
#define QKV_DIM  1536
#define FF_DIM   2048
#define V_DIM    32000
#define N_BH     32
#define S_LEN    256

// ---------------- scratch ----------------
__device__ float  g_x [N_ROWS * E_DIM];
__device__ __half g_qr[N_BH * S_LEN * 512];

// ---------------- packed fp16 planes (word = 2 consecutive-k halves) ----------------
__device__ uint32_t p_h_hi  [N_ROWS * 256],  p_h_lo  [N_ROWS * 256];
__device__ uint32_t p_qkv_hi[N_ROWS * 768];
__device__ uint32_t p_pr_hi [N_BH * S_LEN * 128];
__device__ uint32_t p_vT    [N_BH * 64 * 128];
__device__ uint32_t p_o_hi  [N_ROWS * 256],  p_o_lo  [N_ROWS * 256];
__device__ uint32_t p_g_hi  [N_ROWS * 1024], p_g_lo  [N_ROWS * 1024];
__device__ uint32_t p_Wi_hi [4 * 1536 * 256];
__device__ uint32_t p_Wo_hi [4 * 512 * 256];
__device__ uint32_t p_W1_hi [4 * 2048 * 256];
__device__ uint32_t p_W2_hi [4 * 512 * 1024];
__device__ uint32_t p_Wd_hi [V_DIM * 256];
__device__ uint32_t p_rel_hi[511 * 256];

// ---------------- helpers ----------------
__device__ __forceinline__ void splitpack(float v0, float v1, uint32_t& hi, uint32_t& lo) {
    __half h0 = __float2half_rn(v0);
    __half h1 = __float2half_rn(v1);
    float r0 = v0 - __half2float(h0);
    float r1 = v1 - __half2float(h1);
    __half l0 = __float2half_rn(r0);
    __half l1 = __float2half_rn(r1);
    hi = (uint32_t)__half_as_ushort(h0) | ((uint32_t)__half_as_ushort(h1) << 16);
    lo = (uint32_t)__half_as_ushort(l0) | ((uint32_t)__half_as_ushort(l1) << 16);
}
__device__ __forceinline__ uint32_t pack_hi(float v0, float v1) {
    __half h0 = __float2half_rn(v0);
    __half h1 = __float2half_rn(v1);
    return (uint32_t)__half_as_ushort(h0) | ((uint32_t)__half_as_ushort(h1) << 16);
}

__device__ __forceinline__ float warpSum(float v) {
    #pragma unroll
    for (int o = 16; o; o >>= 1) v += __shfl_xor_sync(0xffffffffu, v, o);
    return v;
}
__device__ __forceinline__ float blockSum(float v) {
    __shared__ float sm[8];
    int lane = threadIdx.x & 31, w = threadIdx.x >> 5;
    v = warpSum(v);
    __syncthreads();
    if (lane == 0) sm[w] = v;
    __syncthreads();
    float r = 0.f;
    #pragma unroll
    for (int i = 0; i < 8; i++) r += sm[i];
    return r;
}

// ---------------- f32 -> fp16 hi plane (8 words / 32B out per thread) ----------------
__global__ void split_hi_k(const float* __restrict__ in, uint32_t* __restrict__ hi, int nWords) {
    int i = (blockIdx.x * 256 + threadIdx.x) * 8;
    if (i < nWords) {
        #pragma unroll
        for (int j = 0; j < 2; j++) {
            float4 a = *(const float4*)(in + 2 * (size_t)(i + j * 4));
            float4 b = *(const float4*)(in + 2 * (size_t)(i + j * 4) + 4);
            uint4 o;
            o.x = pack_hi(a.x, a.y); o.y = pack_hi(a.z, a.w);
            o.z = pack_hi(b.x, b.y); o.w = pack_hi(b.z, b.w);
            *(uint4*)(hi + i + j * 4) = o;
        }
    }
}

// ---------------- embed + input layernorm -> f32 x ----------------
__global__ void embed_ln_k(const int* __restrict__ src, const float* __restrict__ emb,
                           const float* __restrict__ s, const float* __restrict__ b,
                           float* __restrict__ out) {
    int row = blockIdx.x, t = threadIdx.x;
    int tok = src[row];
    const float SC = 22.62741699796952f;
    float v0 = emb[(size_t)tok * E_DIM + t]       * SC;
    float v1 = emb[(size_t)tok * E_DIM + t + 256] * SC;
    float mean = blockSum(v0 + v1) * (1.f / E_DIM);
    float d0 = v0 - mean, d1 = v1 - mean;
    float var = blockSum(d0 * d0 + d1 * d1) * (1.f / E_DIM);
    float r = rsqrtf(var + 1e-5f);
    out[(size_t)row * E_DIM + t]       = d0 * r * s[t]       + b[t];
    out[(size_t)row * E_DIM + t + 256] = d1 * r * s[t + 256] + b[t + 256];
}

// ---------------- layernorm f32 -> split planes ----------------
__global__ void layernorm_split_k(const float* __restrict__ in, const float* __restrict__ s,
                                  const float* __restrict__ b,
                                  uint32_t* __restrict__ oh, uint32_t* __restrict__ ol) {
    int row = blockIdx.x, t = threadIdx.x;
    float2 v = *(const float2*)(in + (size_t)row * E_DIM + 2 * t);
    float mean = blockSum(v.x + v.y) * (1.f / E_DIM);
    float d0 = v.x - mean, d1 = v.y - mean;
    float var = blockSum(d0 * d0 + d1 * d1) * (1.f / E_DIM);
    float r = rsqrtf(var + 1e-5f);
    float y0 = d0 * r * s[2 * t]     + b[2 * t];
    float y1 = d1 * r * s[2 * t + 1] + b[2 * t + 1];
    uint32_t h, l;
    splitpack(y0, y1, h, l);
    oh[(size_t)row * 256 + t] = h;
    ol[(size_t)row * 256 + t] = l;
}

// ---------------- mma / ldmatrix / cp.async primitives ----------------
#define MMA_F16(C, A0, A1, A2, A3, B0, B1)                                      \
    asm volatile("mma.sync.aligned.m16n8k16.row.col.f32.f16.f16.f32 "           \
                 "{%0,%1,%2,%3},{%4,%5,%6,%7},{%8,%9},{%0,%1,%2,%3};"           \
                 : "+f"(C[0]), "+f"(C[1]), "+f"(C[2]), "+f"(C[3])               \
                 : "r"(A0), "r"(A1), "r"(A2), "r"(A3), "r"(B0), "r"(B1))

__device__ __forceinline__ void ldsm4(uint32_t& r0, uint32_t& r1, uint32_t& r2, uint32_t& r3,
                                      uint32_t addr) {
    asm volatile("ldmatrix.sync.aligned.m8n8.x4.shared.b16 {%0,%1,%2,%3}, [%4];"
                 : "=r"(r0), "=r"(r1), "=r"(r2), "=r"(r3) : "r"(addr));
}

__device__ __forceinline__ void cp16w(uint32_t* dst, const uint32_t* src, bool pred) {
    uint32_t d = (uint32_t)__cvta_generic_to_shared(dst);
    int sz = pred ? 16 : 0;
    asm volatile("cp.async.cg.shared.global [%0], [%1], 16, %2;"
                 :: "r"(d), "l"(src), "r"(sz));
}

// ---------------- fused attention: scores + rel-bias gather + mask + softmax ----------
#define ATT_STRIDE 36
#define ATT_SMEM ((128 * ATT_STRIDE + 256 * ATT_STRIDE) * 4 + 128 * 4 * 4)
__global__ __launch_bounds__(256, 1)
void attn_k(const uint32_t* __restrict__ qkvH, const __half* __restrict__ qr,
            uint32_t* __restrict__ ph) {
    extern __shared__ uint32_t asm_[];
    uint32_t* qs = asm_;
    uint32_t* ks = asm_ + 128 * ATT_STRIDE;
    float* red = (float*)(ks + 256 * ATT_STRIDE);

    int tile = blockIdx.x;
    int bh = blockIdx.y;
    int zb = bh >> 3, zh = bh & 7;
    const uint32_t* Q = qkvH + (size_t)zb * (256 * 768) + zh * 32;
    const uint32_t* K = Q + 256;
    const __half* qrb = qr + (size_t)bh * (256 * 512);
    int l0 = tile * 128;

    int tid = threadIdx.x, lane = tid & 31, wid = tid >> 5;

    {
        int lrow = tid >> 1, seg = (tid & 1) * 16;
        const uint32_t* qrow = Q + (size_t)(l0 + lrow) * 768 + seg;
        uint32_t* qd = qs + lrow * ATT_STRIDE + seg;
        #pragma unroll
        for (int j = 0; j < 4; j++) cp16w(qd + j * 4, qrow + j * 4, true);
        const uint32_t* krow = K + (size_t)tid * 768;
        uint32_t* kd = ks + tid * ATT_STRIDE;
        #pragma unroll
        for (int j = 0; j < 8; j++) cp16w(kd + j * 4, krow + j * 4, true);
    }
    asm volatile("cp.async.commit_group;");
    asm volatile("cp.async.wait_group 0;");
    __syncthreads();

    int warpM = wid >> 2, warpN = wid & 3;
    int wm0 = warpM * 64, wn0 = warpN * 64;
    int g = lane >> 2, tg = lane & 3;
    uint32_t smQ = (uint32_t)__cvta_generic_to_shared(qs);
    uint32_t smK = (uint32_t)__cvta_generic_to_shared(ks);
    uint32_t a_base = smQ + ((uint32_t)(wm0 + (lane & 15)) * ATT_STRIDE + ((lane & 16) ? 4 : 0)) * 4;
    uint32_t b_base = smK + ((uint32_t)(wn0 + (lane & 7) + ((lane & 16) ? 8 : 0)) * ATT_STRIDE
                             + ((lane & 8) ? 4 : 0)) * 4;

    float acc[4][8][4] = {};
    #pragma unroll
    for (int c = 0; c < 4; c++) {
        uint32_t koff = (uint32_t)c * 32;
        uint32_t Bf[8][2];
        #pragma unroll
        for (int t = 0; t < 4; t++)
            ldsm4(Bf[2 * t][0], Bf[2 * t][1], Bf[2 * t + 1][0], Bf[2 * t + 1][1],
                  b_base + koff + (uint32_t)t * 16 * ATT_STRIDE * 4);
        #pragma unroll
        for (int mi = 0; mi < 4; mi++) {
            uint32_t Af[4];
            ldsm4(Af[0], Af[1], Af[2], Af[3],
                  a_base + koff + (uint32_t)mi * 16 * ATT_STRIDE * 4);
            #pragma unroll
            for (int ni = 0; ni < 8; ni++)
                MMA_F16(acc[mi][ni], Af[0], Af[1], Af[2], Af[3], Bf[ni][0], Bf[ni][1]);
        }
    }
    __syncthreads();

    #pragma unroll
    for (int mi = 0; mi < 4; mi++) {
        #pragma unroll
        for (int rr = 0; rr < 2; rr++) {
            int lrow = wm0 + mi * 16 + g + rr * 8;
            int lglob = l0 + lrow;
            const __half* qrl = qrb + (size_t)lglob * 512 + (255 - lglob);
            #pragma unroll
            for (int ni = 0; ni < 8; ni++) {
                int m = wn0 + ni * 8 + tg * 2;
                float b0 = __half2float(qrl[m]);
                float b1 = __half2float(qrl[m + 1]);
                acc[mi][ni][rr * 2]     = acc[mi][ni][rr * 2]     * 0.125f + b0 + ((m     > lglob) ? 1.f : 0.f);
                acc[mi][ni][rr * 2 + 1] = acc[mi][ni][rr * 2 + 1] * 0.125f + b1 + ((m + 1 > lglob) ? 1.f : 0.f);
            }
        }
    }

    float rmax[4][2];
    #pragma unroll
    for (int mi = 0; mi < 4; mi++)
        #pragma unroll
        for (int rr = 0; rr < 2; rr++) {
            float mx = -3.4e38f;
            #pragma unroll
            for (int ni = 0; ni < 8; ni++) {
                mx = fmaxf(mx, acc[mi][ni][rr * 2]);
                mx = fmaxf(mx, acc[mi][ni][rr * 2 + 1]);
            }
            mx = fmaxf(mx, __shfl_xor_sync(0xffffffffu, mx, 1));
            mx = fmaxf(mx, __shfl_xor_sync(0xffffffffu, mx, 2));
            int lrow = wm0 + mi * 16 + g + rr * 8;
            if (tg == 0) red[lrow * 4 + warpN] = mx;
            rmax[mi][rr] = 0.f;
        }
    __syncthreads();
    #pragma unroll
    for (int mi = 0; mi < 4; mi++)
        #pragma unroll
        for (int rr = 0; rr < 2; rr++) {
            int lrow = wm0 + mi * 16 + g + rr * 8;
            rmax[mi][rr] = fmaxf(fmaxf(red[lrow * 4 + 0], red[lrow * 4 + 1]),
                                 fmaxf(red[lrow * 4 + 2], red[lrow * 4 + 3]));
        }
    __syncthreads();

    float rsum[4][2];
    #pragma unroll
    for (int mi = 0; mi < 4; mi++)
        #pragma unroll
        for (int rr = 0; rr < 2; rr++) {
            float s = 0.f;
            #pragma unroll
            for (int ni = 0; ni < 8; ni++) {
                float e0 = expf(acc[mi][ni][rr * 2]     - rmax[mi][rr]);
                float e1 = expf(acc[mi][ni][rr * 2 + 1] - rmax[mi][rr]);
                acc[mi][ni][rr * 2] = e0; acc[mi][ni][rr * 2 + 1] = e1;
                s += e0 + e1;
            }
            s += __shfl_xor_sync(0xffffffffu, s, 1);
            s += __shfl_xor_sync(0xffffffffu, s, 2);
            int lrow = wm0 + mi * 16 + g + rr * 8;
            if (tg == 0) red[lrow * 4 + warpN] = s;
            rsum[mi][rr] = 0.f;
        }
    __syncthreads();
    #pragma unroll
    for (int mi = 0; mi < 4; mi++)
        #pragma unroll
        for (int rr = 0; rr < 2; rr++) {
            int lrow = wm0 + mi * 16 + g + rr * 8;
            rsum[mi][rr] = red[lrow * 4 + 0] + red[lrow * 4 + 1]
                         + red[lrow * 4 + 2] + red[lrow * 4 + 3];
        }

    uint32_t* pb = ph + (size_t)bh * (S_LEN * 128);
    #pragma unroll
    for (int mi = 0; mi < 4; mi++)
        #pragma unroll
        for (int rr = 0; rr < 2; rr++) {
            int lglob = l0 + wm0 + mi * 16 + g + rr * 8;
            float inv = 1.f / rsum[mi][rr];
            #pragma unroll
            for (int ni = 0; ni < 8; ni++) {
                float p0 = acc[mi][ni][rr * 2] * inv;
                float p1 = acc[mi][ni][rr * 2 + 1] * inv;
                pb[(size_t)lglob * 128 + (wn0 >> 1) + ni * 4 + tg] = pack_hi(p0, p1);
            }
        }
}

// ---------------- V transpose ----------------
__global__ void vtrans_k(const uint32_t* __restrict__ qkvH, uint32_t* __restrict__ vT) {
    __shared__ uint32_t vs[256][33];
    int bh = blockIdx.x;
    int zb = bh >> 3, zh = bh & 7;
    const uint32_t* V = qkvH + (size_t)zb * (256 * 768) + 512 + zh * 32;
    int tid = threadIdx.x;
    #pragma unroll
    for (int j = 0; j < 32; j++) {
        int idx = tid + j * 256;
        int row = idx >> 5, w = idx & 31;
        vs[row][w] = V[(size_t)row * 768 + w];
    }
    __syncthreads();
    uint32_t* o = vT + (size_t)bh * 8192;
    #pragma unroll
    for (int j = 0; j < 32; j++) {
        int idx = tid + j * 256;
        int d = idx >> 7, sw = idx & 127;
        uint32_t w0 = vs[2 * sw][d >> 1], w1 = vs[2 * sw + 1][d >> 1];
        int sh = (d & 1) * 16;
        o[idx] = ((w0 >> sh) & 0xffffu) | (((w1 >> sh) & 0xffffu) << 16);
    }
}

#define STAGES 3

// ---------------- fp16 GEMM, MT x 128 CTA tile, chunk k=16 (8 words) ----------------
// ALO: A hi+lo (2-term) vs hi only. B: pre-split hi plane.
// EPI: 0 f32 out (+bias); 1 f32 splitK atomicAdd (+bias at sk==0);
//      2 planes out bias+GELU; 3 planes out (+bias, Cl optional); 4 fp16 out (no bias).
template<int EPI, int NSPLIT, int ALO, int MT>
__global__ __launch_bounds__(256, 2)
void bgemm(const uint32_t* __restrict__ Ah, const uint32_t* __restrict__ Al,
           const uint32_t* __restrict__ Bh,
           const float* __restrict__ bias,
           float* __restrict__ Cf, uint32_t* __restrict__ Ch, uint32_t* __restrict__ Cl,
           int M, int N, int Kw, int ldaw, int ldbw, int ldc,
           int aOffB, int aOffH, int bOffB, int bOffH, int cOffB, int cOffH) {
    extern __shared__ uint32_t smu[];
    constexpr int APW   = MT * 12;
    constexpr int BPW   = 128 * 12;
    constexpr int BOFFW = (1 + ALO) * APW;
    constexpr int STW   = BOFFW + BPW;
    constexpr int STB   = STW * 4;
    constexpr int WM    = MT / 2;
    constexpr int NMI   = MT / 32;

    int z = blockIdx.z;
    int sk = z % NSPLIT;
    int zz = z / NSPLIT;
    int zb = zz >> 3, zh = zz & 7;
    Ah += (size_t)zb * aOffB + (size_t)zh * aOffH;
    if (ALO) Al += (size_t)zb * aOffB + (size_t)zh * aOffH;
    Bh += (size_t)zb * bOffB + (size_t)zh * bOffH;
    size_t cAdj = (size_t)zb * cOffB + (size_t)zh * cOffH;
    __half* C16 = 0;
    if (EPI == 4) C16 = (__half*)Cf + cAdj;
    else if (EPI <= 1) Cf += cAdj;
    else { Ch += cAdj; if (Cl) Cl += cAdj; }

    int kLenW = Kw / NSPLIT;
    int kw0   = sk * kLenW;
    int nk    = kLenW >> 3;

    int tid  = threadIdx.x;
    int lane = tid & 31, wid = tid >> 5;
    int wm0 = (wid >> 2) * WM;
    int wn0 = (wid & 3) * 32;
    int g   = lane >> 2;
    int tg  = lane & 3;
    int row0 = blockIdx.y * MT, col0 = blockIdx.x * 128;

    uint32_t smBase = (uint32_t)__cvta_generic_to_shared(smu);
    uint32_t a_off = ((uint32_t)(wm0 + (lane & 15)) * 12 + ((lane & 16) ? 4 : 0)) * 4;
    uint32_t b_off = ((uint32_t)(wn0 + (lane & 7) + ((lane & 16) ? 8 : 0)) * 12
                      + ((lane & 8) ? 4 : 0)) * 4;

    float acc[NMI][4][4] = {};

    auto COMPUTE = [&](int buf) {
        uint32_t sb = smBase + (uint32_t)buf * STB;
        uint32_t aH = sb + a_off;
        uint32_t aL = aH + APW * 4;
        uint32_t bH = sb + BOFFW * 4 + b_off;
        uint32_t Bhf[4][2];
        ldsm4(Bhf[0][0], Bhf[0][1], Bhf[1][0], Bhf[1][1], bH);
        ldsm4(Bhf[2][0], Bhf[2][1], Bhf[3][0], Bhf[3][1], bH + 16 * 12 * 4);
        #pragma unroll
        for (int mi = 0; mi < NMI; mi++) {
            uint32_t Af[4];
            ldsm4(Af[0], Af[1], Af[2], Af[3], aH + (uint32_t)mi * 16 * 12 * 4);
            uint32_t Lf[4];
            if (ALO) ldsm4(Lf[0], Lf[1], Lf[2], Lf[3], aL + (uint32_t)mi * 16 * 12 * 4);
            #pragma unroll
            for (int ni = 0; ni < 4; ni++) {
                MMA_F16(acc[mi][ni], Af[0], Af[1], Af[2], Af[3], Bhf[ni][0], Bhf[ni][1]);
                if (ALO)
                    MMA_F16(acc[mi][ni], Lf[0], Lf[1], Lf[2], Lf[3], Bhf[ni][0], Bhf[ni][1]);
            }
        }
    };

    auto LOADNT = [&](int chunk, int buf) {
        int kws = kw0 + (chunk << 3);
        uint32_t* st = smu + buf * STW;
        if (MT == 128) {
            int r = tid >> 1, s = (tid & 1) * 4;
            cp16w(st + r * 12 + s, Ah + (size_t)(row0 + r) * ldaw + kws + s, true);
            if (ALO)
                cp16w(st + APW + r * 12 + s, Al + (size_t)(row0 + r) * ldaw + kws + s, true);
        } else {
            int r = (tid & 127) >> 1, s = (tid & 1) * 4;
            if (!ALO) {
                if (tid < 128)
                    cp16w(st + r * 12 + s, Ah + (size_t)(row0 + r) * ldaw + kws + s, true);
            } else {
                const uint32_t* srcp = (tid < 128) ? Ah : Al;
                uint32_t* dstp = st + ((tid < 128) ? 0 : APW);
                cp16w(dstp + r * 12 + s, srcp + (size_t)(row0 + r) * ldaw + kws + s, true);
            }
        }
        int rb = tid >> 1, sb2 = (tid & 1) * 4;
        bool p = (col0 + rb) < N;
        cp16w(st + BOFFW + rb * 12 + sb2, Bh + (size_t)(col0 + rb) * ldbw + kws + sb2, p);
    };

    int pre = (nk < STAGES - 1) ? nk : (STAGES - 1);
    for (int s = 0; s < pre; s++) {
        LOADNT(s, s);
        asm volatile("cp.async.commit_group;");
    }
    for (int i = 0; i < nk; i++) {
        int buf = i % STAGES;
        asm volatile("cp.async.wait_group %0;" :: "n"(STAGES - 2));
        __syncthreads();
        COMPUTE(buf);
        int nxt = i + STAGES - 1;
        if (nxt < nk) LOADNT(nxt, nxt % STAGES);
        asm volatile("cp.async.commit_group;");
    }

    // ---------------- epilogue ----------------
    #pragma unroll
    for (int mi = 0; mi < NMI; mi++) {
        #pragma unroll
        for (int rr = 0; rr < 2; rr++) {
            int r = row0 + wm0 + mi * 16 + g + rr * 8;
            #pragma unroll
            for (int ni = 0; ni < 4; ni++) {
                int c = col0 + wn0 + ni * 8 + tg * 2;
                float v0 = acc[mi][ni][rr * 2];
                float v1 = acc[mi][ni][rr * 2 + 1];
                if (EPI == 0) {
                    float* Crow = Cf + (size_t)r * ldc;
                    if (c + 1 < N) {
                        if (bias) { v0 += bias[c]; v1 += bias[c + 1]; }
                        *(float2*)&Crow[c] = make_float2(v0, v1);
                    } else if (c < N) {
                        if (bias) v0 += bias[c];
                        Crow[c] = v0;
                    }
                } else if (EPI == 1) {
                    float* Crow = Cf + (size_t)r * ldc;
                    if (bias && sk == 0) {
                        if (c < N)     v0 += bias[c];
                        if (c + 1 < N) v1 += bias[c + 1];
                    }
                    if (c < N)     atomicAdd(&Crow[c], v0);
                    if (c + 1 < N) atomicAdd(&Crow[c + 1], v1);
                } else if (EPI == 4) {
                    __half* Hrow = C16 + (size_t)r * ldc;
                    if (c < N)     Hrow[c]     = __float2half_rn(v0);
                    if (c + 1 < N) Hrow[c + 1] = __float2half_rn(v1);
                } else {
                    if (c < N) {
                        if (bias) { v0 += bias[c]; v1 += bias[c + 1]; }
                        if (EPI == 2) {
                            v0 = 0.5f * v0 * (1.f + erff(v0 * 0.7071067811865476f));
                            v1 = 0.5f * v1 * (1.f + erff(v1 * 0.7071067811865476f));
                        }
                        uint32_t h, l;
                        splitpack(v0, v1, h, l);
                        size_t idx = (size_t)r * ldc + (c >> 1);
                        Ch[idx] = h;
                        if (Cl) Cl[idx] = l;
                    }
                }
            }
        }
    }
}

#define SM_B(MT, ALO) (STAGES * (((1 + (ALO)) * (MT) * 12) + 128 * 12) * 4)

// ---------------- driver ----------------
extern "C" void kernel_launch(void* const* d_in, const int* in_sizes, int n_in,
                              void* d_out, int out_size) {
    const int*   src   = (const int*)  d_in[0];
    const float* emb   = (const float*)d_in[1];
    const float* rel   = (const float*)d_in[2];
    const float* nin_s = (const float*)d_in[3];
    const float* nin_b = (const float*)d_in[4];
    const float* inW   = (const float*)d_in[5];
    const float* inB   = (const float*)d_in[6];
    const float* outW  = (const float*)d_in[7];
    const float* outB  = (const float*)d_in[8];
    const float* ln1s  = (const float*)d_in[9];
    const float* ln1b  = (const float*)d_in[10];
    const float* ln2s  = (const float*)d_in[11];
    const float* ln2b  = (const float*)d_in[12];
    const float* w1    = (const float*)d_in[13];
    const float* b1    = (const float*)d_in[14];
    const float* w2    = (const float*)d_in[15];
    const float* b2    = (const float*)d_in[16];
    const float* nfs   = (const float*)d_in[17];
    const float* nfb   = (const float*)d_in[18];
    const float* decW  = (const float*)d_in[19];
    const float* decB  = (const float*)d_in[20];
    float* out = (float*)d_out;

    float *x;
    __half *qrH;
    cudaGetSymbolAddress((void**)&x,   g_x);
    cudaGetSymbolAddress((void**)&qrH, g_qr);
    uint32_t *hH,*hL,*qkvH,*prH,*vT,*oH,*oL,*gH,*gL;
    uint32_t *WiH,*WoH,*W1H,*W2H,*WdH,*relH;
    cudaGetSymbolAddress((void**)&hH,   p_h_hi);   cudaGetSymbolAddress((void**)&hL,   p_h_lo);
    cudaGetSymbolAddress((void**)&qkvH, p_qkv_hi);
    cudaGetSymbolAddress((void**)&prH,  p_pr_hi);
    cudaGetSymbolAddress((void**)&vT,   p_vT);
    cudaGetSymbolAddress((void**)&oH,   p_o_hi);   cudaGetSymbolAddress((void**)&oL,   p_o_lo);
    cudaGetSymbolAddress((void**)&gH,   p_g_hi);   cudaGetSymbolAddress((void**)&gL,   p_g_lo);
    cudaGetSymbolAddress((void**)&WiH,  p_Wi_hi);
    cudaGetSymbolAddress((void**)&WoH,  p_Wo_hi);
    cudaGetSymbolAddress((void**)&W1H,  p_W1_hi);
    cudaGetSymbolAddress((void**)&W2H,  p_W2_hi);
    cudaGetSymbolAddress((void**)&WdH,  p_Wd_hi);
    cudaGetSymbolAddress((void**)&relH, p_rel_hi);

    cudaFuncSetAttribute(bgemm<3,1,1,64>,  cudaFuncAttributeMaxDynamicSharedMemorySize, SM_B(64,1));
    cudaFuncSetAttribute(bgemm<4,1,0,128>, cudaFuncAttributeMaxDynamicSharedMemorySize, SM_B(128,0));
    cudaFuncSetAttribute(bgemm<3,1,0,64>,  cudaFuncAttributeMaxDynamicSharedMemorySize, SM_B(64,0));
    cudaFuncSetAttribute(bgemm<1,2,1,64>,  cudaFuncAttributeMaxDynamicSharedMemorySize, SM_B(64,1));
    cudaFuncSetAttribute(bgemm<2,1,1,64>,  cudaFuncAttributeMaxDynamicSharedMemorySize, SM_B(64,1));
    cudaFuncSetAttribute(bgemm<0,1,0,128>, cudaFuncAttributeMaxDynamicSharedMemorySize, SM_B(128,0));
    cudaFuncSetAttribute(attn_k,           cudaFuncAttributeMaxDynamicSharedMemorySize, ATT_SMEM);

    // weight splits (hi-only)
    split_hi_k<<<(4*1536*256/8 + 255)/256, 256>>>(inW,  WiH, 4*1536*256);
    split_hi_k<<<(4*512*256/8  + 255)/256, 256>>>(outW, WoH, 4*512*256);
    split_hi_k<<<(4*2048*256/8 + 255)/256, 256>>>(w1,   W1H, 4*2048*256);
    split_hi_k<<<(4*512*1024/8 + 255)/256, 256>>>(w2,   W2H, 4*512*1024);
    split_hi_k<<<(V_DIM*256/8  + 255)/256, 256>>>(decW, WdH, V_DIM*256);
    split_hi_k<<<(511*256/8    + 255)/256, 256>>>(rel,  relH, 511*256);

    embed_ln_k<<<N_ROWS, 256>>>(src, emb, nin_s, nin_b, x);

    for (int l = 0; l < 4; l++) {
        const uint32_t* WiHl = WiH + (size_t)l * 1536 * 256;
        const uint32_t* WoHl = WoH + (size_t)l * 512 * 256;
        const uint32_t* W1Hl = W1H + (size_t)l * 2048 * 256;
        const uint32_t* W2Hl = W2H + (size_t)l * 512 * 1024;
        const float* inB_l  = inB  + (size_t)l * QKV_DIM;
        const float* outB_l = outB + (size_t)l * E_DIM;
        const float* b1_l   = b1   + (size_t)l * FF_DIM;
        const float* b2_l   = b2   + (size_t)l * E_DIM;

        layernorm_split_k<<<N_ROWS, 256>>>(x, ln1s + l*E_DIM, ln1b + l*E_DIM, hH, hL);

        // qkv hi plane = h @ inW^T + inB   (2-term A, 64x128 tiles)
        bgemm<3,1,1,64><<<dim3(12, 16, 1), 256, SM_B(64,1)>>>(hH, hL, WiHl, inB_l,
            (float*)0, qkvH, (uint32_t*)0, N_ROWS, QKV_DIM, 256, 256, 256, 768,
            0,0, 0,0, 0,0);

        // V transpose
        vtrans_k<<<N_BH, 256>>>(qkvH, vT);

        // qr fp16 = Q @ rel^T  (1-term, 128x128 tiles, fp16 out)
        bgemm<4,1,0,128><<<dim3(4, 2, N_BH), 256, SM_B(128,0)>>>(qkvH, (const uint32_t*)0, relH,
            (const float*)0, (float*)qrH, (uint32_t*)0, (uint32_t*)0,
            S_LEN, 511, 32, 768, 256, 512,
            256*768, 32, 0, 32, 8*131072, 131072);

        // fused scores + bias + mask + softmax
        attn_k<<<dim3(2, N_BH), 256, ATT_SMEM>>>(qkvH, qrH, prH);

        // o planes = probs @ V^T  (1-term, 64x128 tiles)
        bgemm<3,1,0,64><<<dim3(1, 4, N_BH), 256, SM_B(64,0)>>>(prH, (const uint32_t*)0, vT,
            (const float*)0, (float*)0, oH, oL,
            S_LEN, 64, 128, 128, 128, 256,
            8*32768, 32768, 8*8192, 8192, 65536, 32);

        // x += o @ outW^T + outB   (splitK 2, 2-term A)
        bgemm<1,2,1,64><<<dim3(4, 16, 2), 256, SM_B(64,1)>>>(oH, oL, WoHl, outB_l,
            x, (uint32_t*)0, (uint32_t*)0, N_ROWS, E_DIM, 256, 256, 256, E_DIM,
            0,0, 0,0, 0,0);

        layernorm_split_k<<<N_ROWS, 256>>>(x, ln2s + l*E_DIM, ln2b + l*E_DIM, hH, hL);

        // g planes = gelu(h @ w1^T + b1)  (2-term A)
        bgemm<2,1,1,64><<<dim3(16, 16, 1), 256, SM_B(64,1)>>>(hH, hL, W1Hl, b1_l,
            (float*)0, gH, gL, N_ROWS, FF_DIM, 256, 256, 256, 1024,
            0,0, 0,0, 0,0);

        // x += g @ w2^T + b2   (splitK 2, 2-term A)
        bgemm<1,2,1,64><<<dim3(4, 16, 2), 256, SM_B(64,1)>>>(gH, gL, W2Hl, b2_l,
            x, (uint32_t*)0, (uint32_t*)0, N_ROWS, E_DIM, 1024, 1024, 1024, E_DIM,
            0,0, 0,0, 0,0);
    }

    layernorm_split_k<<<N_ROWS, 256>>>(x, nfs, nfb, hH, hL);

    // out f32 = h @ dec_w^T + dec_b   (1-term, 128x128 tiles)
    bgemm<0,1,0,128><<<dim3(250, 8, 1), 256, SM_B(128,0)>>>(hH, (const uint32_t*)0, WdH, decB,
        out, (uint32_t*)0, (uint32_t*)0, N_ROWS, V_DIM, 256, 256, 256, V_DIM,
        0,0, 0,0, 0,0);
}

// round 13
// speedup vs baseline: 1.6081x; 1.0355x over previous
#include <cuda_runtime.h>
#include <cuda_fp16.h>
#include <math.h>
#include <stdint.h>

// ---------------- problem constants ----------------
#define N_ROWS   1024
#define E_DIM    512
#define QKV_DIM  1536
#define FF_DIM   2048
#define V_DIM    32000
#define N_BH     32
#define S_LEN    256

// ---------------- scratch ----------------
__device__ float  g_x [N_ROWS * E_DIM];
__device__ __half g_qr[N_BH * S_LEN * 512];

// ---------------- packed fp16 planes (word = 2 consecutive-k halves) ----------------
__device__ uint32_t p_h_hi  [N_ROWS * 256],  p_h_lo  [N_ROWS * 256];
__device__ uint32_t p_qkv_hi[N_ROWS * 768];
__device__ uint32_t p_pr_hi [N_BH * S_LEN * 128];
__device__ uint32_t p_vT    [N_BH * 64 * 128];
__device__ uint32_t p_o_hi  [N_ROWS * 256],  p_o_lo  [N_ROWS * 256];
__device__ uint32_t p_g_hi  [N_ROWS * 1024], p_g_lo  [N_ROWS * 1024];
__device__ uint32_t p_Wi_hi [4 * 1536 * 256];
__device__ uint32_t p_Wo_hi [4 * 512 * 256];
__device__ uint32_t p_W1_hi [4 * 2048 * 256];
__device__ uint32_t p_W2_hi [4 * 512 * 1024];
__device__ uint32_t p_Wd_hi [V_DIM * 256];
__device__ uint32_t p_rel_hi[511 * 256];

// ---------------- helpers ----------------
__device__ __forceinline__ void splitpack(float v0, float v1, uint32_t& hi, uint32_t& lo) {
    __half h0 = __float2half_rn(v0);
    __half h1 = __float2half_rn(v1);
    float r0 = v0 - __half2float(h0);
    float r1 = v1 - __half2float(h1);
    __half l0 = __float2half_rn(r0);
    __half l1 = __float2half_rn(r1);
    hi = (uint32_t)__half_as_ushort(h0) | ((uint32_t)__half_as_ushort(h1) << 16);
    lo = (uint32_t)__half_as_ushort(l0) | ((uint32_t)__half_as_ushort(l1) << 16);
}
__device__ __forceinline__ uint32_t pack_hi(float v0, float v1) {
    __half h0 = __float2half_rn(v0);
    __half h1 = __float2half_rn(v1);
    return (uint32_t)__half_as_ushort(h0) | ((uint32_t)__half_as_ushort(h1) << 16);
}

__device__ __forceinline__ float warpSum(float v) {
    #pragma unroll
    for (int o = 16; o; o >>= 1) v += __shfl_xor_sync(0xffffffffu, v, o);
    return v;
}
__device__ __forceinline__ float blockSum(float v) {
    __shared__ float sm[8];
    int lane = threadIdx.x & 31, w = threadIdx.x >> 5;
    v = warpSum(v);
    __syncthreads();
    if (lane == 0) sm[w] = v;
    __syncthreads();
    float r = 0.f;
    #pragma unroll
    for (int i = 0; i < 8; i++) r += sm[i];
    return r;
}

// ---------------- f32 -> fp16 hi plane (8 words / 32B out per thread) ----------------
__global__ void split_hi_k(const float* __restrict__ in, uint32_t* __restrict__ hi, int nWords) {
    int i = (blockIdx.x * 256 + threadIdx.x) * 8;
    if (i < nWords) {
        #pragma unroll
        for (int j = 0; j < 2; j++) {
            float4 a = *(const float4*)(in + 2 * (size_t)(i + j * 4));
            float4 b = *(const float4*)(in + 2 * (size_t)(i + j * 4) + 4);
            uint4 o;
            o.x = pack_hi(a.x, a.y); o.y = pack_hi(a.z, a.w);
            o.z = pack_hi(b.x, b.y); o.w = pack_hi(b.z, b.w);
            *(uint4*)(hi + i + j * 4) = o;
        }
    }
}

// ---------------- embed + input layernorm -> f32 x ----------------
__global__ void embed_ln_k(const int* __restrict__ src, const float* __restrict__ emb,
                           const float* __restrict__ s, const float* __restrict__ b,
                           float* __restrict__ out) {
    int row = blockIdx.x, t = threadIdx.x;
    int tok = src[row];
    const float SC = 22.62741699796952f;
    float v0 = emb[(size_t)tok * E_DIM + t]       * SC;
    float v1 = emb[(size_t)tok * E_DIM + t + 256] * SC;
    float mean = blockSum(v0 + v1) * (1.f / E_DIM);
    float d0 = v0 - mean, d1 = v1 - mean;
    float var = blockSum(d0 * d0 + d1 * d1) * (1.f / E_DIM);
    float r = rsqrtf(var + 1e-5f);
    out[(size_t)row * E_DIM + t]       = d0 * r * s[t]       + b[t];
    out[(size_t)row * E_DIM + t + 256] = d1 * r * s[t + 256] + b[t + 256];
}

// ---------------- layernorm f32 -> split planes ----------------
__global__ void layernorm_split_k(const float* __restrict__ in, const float* __restrict__ s,
                                  const float* __restrict__ b,
                                  uint32_t* __restrict__ oh, uint32_t* __restrict__ ol) {
    int row = blockIdx.x, t = threadIdx.x;
    float2 v = *(const float2*)(in + (size_t)row * E_DIM + 2 * t);
    float mean = blockSum(v.x + v.y) * (1.f / E_DIM);
    float d0 = v.x - mean, d1 = v.y - mean;
    float var = blockSum(d0 * d0 + d1 * d1) * (1.f / E_DIM);
    float r = rsqrtf(var + 1e-5f);
    float y0 = d0 * r * s[2 * t]     + b[2 * t];
    float y1 = d1 * r * s[2 * t + 1] + b[2 * t + 1];
    uint32_t h, l;
    splitpack(y0, y1, h, l);
    oh[(size_t)row * 256 + t] = h;
    ol[(size_t)row * 256 + t] = l;
}

// ---------------- mma / ldmatrix / cp.async primitives ----------------
#define MMA_F16(C, A0, A1, A2, A3, B0, B1)                                      \
    asm volatile("mma.sync.aligned.m16n8k16.row.col.f32.f16.f16.f32 "           \
                 "{%0,%1,%2,%3},{%4,%5,%6,%7},{%8,%9},{%0,%1,%2,%3};"           \
                 : "+f"(C[0]), "+f"(C[1]), "+f"(C[2]), "+f"(C[3])               \
                 : "r"(A0), "r"(A1), "r"(A2), "r"(A3), "r"(B0), "r"(B1))

__device__ __forceinline__ void ldsm4(uint32_t& r0, uint32_t& r1, uint32_t& r2, uint32_t& r3,
                                      uint32_t addr) {
    asm volatile("ldmatrix.sync.aligned.m8n8.x4.shared.b16 {%0,%1,%2,%3}, [%4];"
                 : "=r"(r0), "=r"(r1), "=r"(r2), "=r"(r3) : "r"(addr));
}

__device__ __forceinline__ void cp16w(uint32_t* dst, const uint32_t* src, bool pred) {
    uint32_t d = (uint32_t)__cvta_generic_to_shared(dst);
    int sz = pred ? 16 : 0;
    asm volatile("cp.async.cg.shared.global [%0], [%1], 16, %2;"
                 :: "r"(d), "l"(src), "r"(sz));
}

// ---------------- fused attention: scores + rel-bias gather + mask + softmax ----------
#define ATT_STRIDE 36
#define ATT_SMEM ((128 * ATT_STRIDE + 256 * ATT_STRIDE) * 4 + 128 * 4 * 4)
__global__ __launch_bounds__(256, 1)
void attn_k(const uint32_t* __restrict__ qkvH, const __half* __restrict__ qr,
            uint32_t* __restrict__ ph) {
    extern __shared__ uint32_t asm_[];
    uint32_t* qs = asm_;
    uint32_t* ks = asm_ + 128 * ATT_STRIDE;
    float* red = (float*)(ks + 256 * ATT_STRIDE);

    int tile = blockIdx.x;
    int bh = blockIdx.y;
    int zb = bh >> 3, zh = bh & 7;
    const uint32_t* Q = qkvH + (size_t)zb * (256 * 768) + zh * 32;
    const uint32_t* K = Q + 256;
    const __half* qrb = qr + (size_t)bh * (256 * 512);
    int l0 = tile * 128;

    int tid = threadIdx.x, lane = tid & 31, wid = tid >> 5;

    {
        int lrow = tid >> 1, seg = (tid & 1) * 16;
        const uint32_t* qrow = Q + (size_t)(l0 + lrow) * 768 + seg;
        uint32_t* qd = qs + lrow * ATT_STRIDE + seg;
        #pragma unroll
        for (int j = 0; j < 4; j++) cp16w(qd + j * 4, qrow + j * 4, true);
        const uint32_t* krow = K + (size_t)tid * 768;
        uint32_t* kd = ks + tid * ATT_STRIDE;
        #pragma unroll
        for (int j = 0; j < 8; j++) cp16w(kd + j * 4, krow + j * 4, true);
    }
    asm volatile("cp.async.commit_group;");
    asm volatile("cp.async.wait_group 0;");
    __syncthreads();

    int warpM = wid >> 2, warpN = wid & 3;
    int wm0 = warpM * 64, wn0 = warpN * 64;
    int g = lane >> 2, tg = lane & 3;
    uint32_t smQ = (uint32_t)__cvta_generic_to_shared(qs);
    uint32_t smK = (uint32_t)__cvta_generic_to_shared(ks);
    uint32_t a_base = smQ + ((uint32_t)(wm0 + (lane & 15)) * ATT_STRIDE + ((lane & 16) ? 4 : 0)) * 4;
    uint32_t b_base = smK + ((uint32_t)(wn0 + (lane & 7) + ((lane & 16) ? 8 : 0)) * ATT_STRIDE
                             + ((lane & 8) ? 4 : 0)) * 4;

    float acc[4][8][4] = {};
    #pragma unroll
    for (int c = 0; c < 4; c++) {
        uint32_t koff = (uint32_t)c * 32;
        uint32_t Bf[8][2];
        #pragma unroll
        for (int t = 0; t < 4; t++)
            ldsm4(Bf[2 * t][0], Bf[2 * t][1], Bf[2 * t + 1][0], Bf[2 * t + 1][1],
                  b_base + koff + (uint32_t)t * 16 * ATT_STRIDE * 4);
        #pragma unroll
        for (int mi = 0; mi < 4; mi++) {
            uint32_t Af[4];
            ldsm4(Af[0], Af[1], Af[2], Af[3],
                  a_base + koff + (uint32_t)mi * 16 * ATT_STRIDE * 4);
            #pragma unroll
            for (int ni = 0; ni < 8; ni++)
                MMA_F16(acc[mi][ni], Af[0], Af[1], Af[2], Af[3], Bf[ni][0], Bf[ni][1]);
        }
    }
    __syncthreads();

    #pragma unroll
    for (int mi = 0; mi < 4; mi++) {
        #pragma unroll
        for (int rr = 0; rr < 2; rr++) {
            int lrow = wm0 + mi * 16 + g + rr * 8;
            int lglob = l0 + lrow;
            const __half* qrl = qrb + (size_t)lglob * 512 + (255 - lglob);
            #pragma unroll
            for (int ni = 0; ni < 8; ni++) {
                int m = wn0 + ni * 8 + tg * 2;
                float b0 = __half2float(qrl[m]);
                float b1 = __half2float(qrl[m + 1]);
                acc[mi][ni][rr * 2]     = acc[mi][ni][rr * 2]     * 0.125f + b0 + ((m     > lglob) ? 1.f : 0.f);
                acc[mi][ni][rr * 2 + 1] = acc[mi][ni][rr * 2 + 1] * 0.125f + b1 + ((m + 1 > lglob) ? 1.f : 0.f);
            }
        }
    }

    float rmax[4][2];
    #pragma unroll
    for (int mi = 0; mi < 4; mi++)
        #pragma unroll
        for (int rr = 0; rr < 2; rr++) {
            float mx = -3.4e38f;
            #pragma unroll
            for (int ni = 0; ni < 8; ni++) {
                mx = fmaxf(mx, acc[mi][ni][rr * 2]);
                mx = fmaxf(mx, acc[mi][ni][rr * 2 + 1]);
            }
            mx = fmaxf(mx, __shfl_xor_sync(0xffffffffu, mx, 1));
            mx = fmaxf(mx, __shfl_xor_sync(0xffffffffu, mx, 2));
            int lrow = wm0 + mi * 16 + g + rr * 8;
            if (tg == 0) red[lrow * 4 + warpN] = mx;
            rmax[mi][rr] = 0.f;
        }
    __syncthreads();
    #pragma unroll
    for (int mi = 0; mi < 4; mi++)
        #pragma unroll
        for (int rr = 0; rr < 2; rr++) {
            int lrow = wm0 + mi * 16 + g + rr * 8;
            rmax[mi][rr] = fmaxf(fmaxf(red[lrow * 4 + 0], red[lrow * 4 + 1]),
                                 fmaxf(red[lrow * 4 + 2], red[lrow * 4 + 3]));
        }
    __syncthreads();

    float rsum[4][2];
    #pragma unroll
    for (int mi = 0; mi < 4; mi++)
        #pragma unroll
        for (int rr = 0; rr < 2; rr++) {
            float s = 0.f;
            #pragma unroll
            for (int ni = 0; ni < 8; ni++) {
                float e0 = expf(acc[mi][ni][rr * 2]     - rmax[mi][rr]);
                float e1 = expf(acc[mi][ni][rr * 2 + 1] - rmax[mi][rr]);
                acc[mi][ni][rr * 2] = e0; acc[mi][ni][rr * 2 + 1] = e1;
                s += e0 + e1;
            }
            s += __shfl_xor_sync(0xffffffffu, s, 1);
            s += __shfl_xor_sync(0xffffffffu, s, 2);
            int lrow = wm0 + mi * 16 + g + rr * 8;
            if (tg == 0) red[lrow * 4 + warpN] = s;
            rsum[mi][rr] = 0.f;
        }
    __syncthreads();
    #pragma unroll
    for (int mi = 0; mi < 4; mi++)
        #pragma unroll
        for (int rr = 0; rr < 2; rr++) {
            int lrow = wm0 + mi * 16 + g + rr * 8;
            rsum[mi][rr] = red[lrow * 4 + 0] + red[lrow * 4 + 1]
                         + red[lrow * 4 + 2] + red[lrow * 4 + 3];
        }

    uint32_t* pb = ph + (size_t)bh * (S_LEN * 128);
    #pragma unroll
    for (int mi = 0; mi < 4; mi++)
        #pragma unroll
        for (int rr = 0; rr < 2; rr++) {
            int lglob = l0 + wm0 + mi * 16 + g + rr * 8;
            float inv = 1.f / rsum[mi][rr];
            #pragma unroll
            for (int ni = 0; ni < 8; ni++) {
                float p0 = acc[mi][ni][rr * 2] * inv;
                float p1 = acc[mi][ni][rr * 2 + 1] * inv;
                pb[(size_t)lglob * 128 + (wn0 >> 1) + ni * 4 + tg] = pack_hi(p0, p1);
            }
        }
}

// ---------------- V transpose ----------------
__global__ void vtrans_k(const uint32_t* __restrict__ qkvH, uint32_t* __restrict__ vT) {
    __shared__ uint32_t vs[256][33];
    int bh = blockIdx.x;
    int zb = bh >> 3, zh = bh & 7;
    const uint32_t* V = qkvH + (size_t)zb * (256 * 768) + 512 + zh * 32;
    int tid = threadIdx.x;
    #pragma unroll
    for (int j = 0; j < 32; j++) {
        int idx = tid + j * 256;
        int row = idx >> 5, w = idx & 31;
        vs[row][w] = V[(size_t)row * 768 + w];
    }
    __syncthreads();
    uint32_t* o = vT + (size_t)bh * 8192;
    #pragma unroll
    for (int j = 0; j < 32; j++) {
        int idx = tid + j * 256;
        int d = idx >> 7, sw = idx & 127;
        uint32_t w0 = vs[2 * sw][d >> 1], w1 = vs[2 * sw + 1][d >> 1];
        int sh = (d & 1) * 16;
        o[idx] = ((w0 >> sh) & 0xffffu) | (((w1 >> sh) & 0xffffu) << 16);
    }
}

#define STAGES 3

// ---------------- fp16 GEMM, MT x 128 CTA tile, chunk k=16 (8 words) ----------------
// ALO: A hi+lo (2-term) vs hi only. B: pre-split hi plane.
// EPI: 0 f32 out (+bias); 1 f32 splitK atomicAdd (+bias at sk==0);
//      2 planes out bias+GELU; 3 planes out (+bias, Cl optional); 4 fp16 out (no bias).
template<int EPI, int NSPLIT, int ALO, int MT>
__global__ __launch_bounds__(256, 2)
void bgemm(const uint32_t* __restrict__ Ah, const uint32_t* __restrict__ Al,
           const uint32_t* __restrict__ Bh,
           const float* __restrict__ bias,
           float* __restrict__ Cf, uint32_t* __restrict__ Ch, uint32_t* __restrict__ Cl,
           int M, int N, int Kw, int ldaw, int ldbw, int ldc,
           int aOffB, int aOffH, int bOffB, int bOffH, int cOffB, int cOffH) {
    extern __shared__ uint32_t smu[];
    constexpr int APW   = MT * 12;
    constexpr int BPW   = 128 * 12;
    constexpr int BOFFW = (1 + ALO) * APW;
    constexpr int STW   = BOFFW + BPW;
    constexpr int STB   = STW * 4;
    constexpr int WM    = MT / 2;
    constexpr int NMI   = MT / 32;

    int z = blockIdx.z;
    int sk = z % NSPLIT;
    int zz = z / NSPLIT;
    int zb = zz >> 3, zh = zz & 7;
    Ah += (size_t)zb * aOffB + (size_t)zh * aOffH;
    if (ALO) Al += (size_t)zb * aOffB + (size_t)zh * aOffH;
    Bh += (size_t)zb * bOffB + (size_t)zh * bOffH;
    size_t cAdj = (size_t)zb * cOffB + (size_t)zh * cOffH;
    __half* C16 = 0;
    if (EPI == 4) C16 = (__half*)Cf + cAdj;
    else if (EPI <= 1) Cf += cAdj;
    else { Ch += cAdj; if (Cl) Cl += cAdj; }

    int kLenW = Kw / NSPLIT;
    int kw0   = sk * kLenW;
    int nk    = kLenW >> 3;

    int tid  = threadIdx.x;
    int lane = tid & 31, wid = tid >> 5;
    int wm0 = (wid >> 2) * WM;
    int wn0 = (wid & 3) * 32;
    int g   = lane >> 2;
    int tg  = lane & 3;
    int row0 = blockIdx.y * MT, col0 = blockIdx.x * 128;

    uint32_t smBase = (uint32_t)__cvta_generic_to_shared(smu);
    uint32_t a_off = ((uint32_t)(wm0 + (lane & 15)) * 12 + ((lane & 16) ? 4 : 0)) * 4;
    uint32_t b_off = ((uint32_t)(wn0 + (lane & 7) + ((lane & 16) ? 8 : 0)) * 12
                      + ((lane & 8) ? 4 : 0)) * 4;

    float acc[NMI][4][4] = {};

    auto COMPUTE = [&](int buf) {
        uint32_t sb = smBase + (uint32_t)buf * STB;
        uint32_t aH = sb + a_off;
        uint32_t aL = aH + APW * 4;
        uint32_t bH = sb + BOFFW * 4 + b_off;
        uint32_t Bhf[4][2];
        ldsm4(Bhf[0][0], Bhf[0][1], Bhf[1][0], Bhf[1][1], bH);
        ldsm4(Bhf[2][0], Bhf[2][1], Bhf[3][0], Bhf[3][1], bH + 16 * 12 * 4);
        #pragma unroll
        for (int mi = 0; mi < NMI; mi++) {
            uint32_t Af[4];
            ldsm4(Af[0], Af[1], Af[2], Af[3], aH + (uint32_t)mi * 16 * 12 * 4);
            uint32_t Lf[4];
            if (ALO) ldsm4(Lf[0], Lf[1], Lf[2], Lf[3], aL + (uint32_t)mi * 16 * 12 * 4);
            #pragma unroll
            for (int ni = 0; ni < 4; ni++) {
                MMA_F16(acc[mi][ni], Af[0], Af[1], Af[2], Af[3], Bhf[ni][0], Bhf[ni][1]);
                if (ALO)
                    MMA_F16(acc[mi][ni], Lf[0], Lf[1], Lf[2], Lf[3], Bhf[ni][0], Bhf[ni][1]);
            }
        }
    };

    auto LOADNT = [&](int chunk, int buf) {
        int kws = kw0 + (chunk << 3);
        uint32_t* st = smu + buf * STW;
        if (MT == 128) {
            int r = tid >> 1, s = (tid & 1) * 4;
            cp16w(st + r * 12 + s, Ah + (size_t)(row0 + r) * ldaw + kws + s, true);
            if (ALO)
                cp16w(st + APW + r * 12 + s, Al + (size_t)(row0 + r) * ldaw + kws + s, true);
        } else {
            int r = (tid & 127) >> 1, s = (tid & 1) * 4;
            if (!ALO) {
                if (tid < 128)
                    cp16w(st + r * 12 + s, Ah + (size_t)(row0 + r) * ldaw + kws + s, true);
            } else {
                const uint32_t* srcp = (tid < 128) ? Ah : Al;
                uint32_t* dstp = st + ((tid < 128) ? 0 : APW);
                cp16w(dstp + r * 12 + s, srcp + (size_t)(row0 + r) * ldaw + kws + s, true);
            }
        }
        int rb = tid >> 1, sb2 = (tid & 1) * 4;
        bool p = (col0 + rb) < N;
        cp16w(st + BOFFW + rb * 12 + sb2, Bh + (size_t)(col0 + rb) * ldbw + kws + sb2, p);
    };

    int pre = (nk < STAGES - 1) ? nk : (STAGES - 1);
    for (int s = 0; s < pre; s++) {
        LOADNT(s, s);
        asm volatile("cp.async.commit_group;");
    }
    for (int i = 0; i < nk; i++) {
        int buf = i % STAGES;
        asm volatile("cp.async.wait_group %0;" :: "n"(STAGES - 2));
        __syncthreads();
        COMPUTE(buf);
        int nxt = i + STAGES - 1;
        if (nxt < nk) LOADNT(nxt, nxt % STAGES);
        asm volatile("cp.async.commit_group;");
    }

    // ---------------- epilogue ----------------
    #pragma unroll
    for (int mi = 0; mi < NMI; mi++) {
        #pragma unroll
        for (int rr = 0; rr < 2; rr++) {
            int r = row0 + wm0 + mi * 16 + g + rr * 8;
            #pragma unroll
            for (int ni = 0; ni < 4; ni++) {
                int c = col0 + wn0 + ni * 8 + tg * 2;
                float v0 = acc[mi][ni][rr * 2];
                float v1 = acc[mi][ni][rr * 2 + 1];
                if (EPI == 0) {
                    float* Crow = Cf + (size_t)r * ldc;
                    if (c + 1 < N) {
                        if (bias) { v0 += bias[c]; v1 += bias[c + 1]; }
                        *(float2*)&Crow[c] = make_float2(v0, v1);
                    } else if (c < N) {
                        if (bias) v0 += bias[c];
                        Crow[c] = v0;
                    }
                } else if (EPI == 1) {
                    float* Crow = Cf + (size_t)r * ldc;
                    if (bias && sk == 0) {
                        if (c < N)     v0 += bias[c];
                        if (c + 1 < N) v1 += bias[c + 1];
                    }
                    if (c < N)     atomicAdd(&Crow[c], v0);
                    if (c + 1 < N) atomicAdd(&Crow[c + 1], v1);
                } else if (EPI == 4) {
                    __half* Hrow = C16 + (size_t)r * ldc;
                    if (c + 1 < N) {
                        *(uint32_t*)(Hrow + c) = pack_hi(v0, v1);   // one coalesced STG.32
                    } else if (c < N) {
                        Hrow[c] = __float2half_rn(v0);
                    }
                } else {
                    if (c < N) {
                        if (bias) { v0 += bias[c]; v1 += bias[c + 1]; }
                        if (EPI == 2) {
                            v0 = 0.5f * v0 * (1.f + erff(v0 * 0.7071067811865476f));
                            v1 = 0.5f * v1 * (1.f + erff(v1 * 0.7071067811865476f));
                        }
                        uint32_t h, l;
                        splitpack(v0, v1, h, l);
                        size_t idx = (size_t)r * ldc + (c >> 1);
                        Ch[idx] = h;
                        if (Cl) Cl[idx] = l;
                    }
                }
            }
        }
    }
}

#define SM_B(MT, ALO) (STAGES * (((1 + (ALO)) * (MT) * 12) + 128 * 12) * 4)

// ---------------- driver ----------------
extern "C" void kernel_launch(void* const* d_in, const int* in_sizes, int n_in,
                              void* d_out, int out_size) {
    const int*   src   = (const int*)  d_in[0];
    const float* emb   = (const float*)d_in[1];
    const float* rel   = (const float*)d_in[2];
    const float* nin_s = (const float*)d_in[3];
    const float* nin_b = (const float*)d_in[4];
    const float* inW   = (const float*)d_in[5];
    const float* inB   = (const float*)d_in[6];
    const float* outW  = (const float*)d_in[7];
    const float* outB  = (const float*)d_in[8];
    const float* ln1s  = (const float*)d_in[9];
    const float* ln1b  = (const float*)d_in[10];
    const float* ln2s  = (const float*)d_in[11];
    const float* ln2b  = (const float*)d_in[12];
    const float* w1    = (const float*)d_in[13];
    const float* b1    = (const float*)d_in[14];
    const float* w2    = (const float*)d_in[15];
    const float* b2    = (const float*)d_in[16];
    const float* nfs   = (const float*)d_in[17];
    const float* nfb   = (const float*)d_in[18];
    const float* decW  = (const float*)d_in[19];
    const float* decB  = (const float*)d_in[20];
    float* out = (float*)d_out;

    float *x;
    __half *qrH;
    cudaGetSymbolAddress((void**)&x,   g_x);
    cudaGetSymbolAddress((void**)&qrH, g_qr);
    uint32_t *hH,*hL,*qkvH,*prH,*vT,*oH,*oL,*gH,*gL;
    uint32_t *WiH,*WoH,*W1H,*W2H,*WdH,*relH;
    cudaGetSymbolAddress((void**)&hH,   p_h_hi);   cudaGetSymbolAddress((void**)&hL,   p_h_lo);
    cudaGetSymbolAddress((void**)&qkvH, p_qkv_hi);
    cudaGetSymbolAddress((void**)&prH,  p_pr_hi);
    cudaGetSymbolAddress((void**)&vT,   p_vT);
    cudaGetSymbolAddress((void**)&oH,   p_o_hi);   cudaGetSymbolAddress((void**)&oL,   p_o_lo);
    cudaGetSymbolAddress((void**)&gH,   p_g_hi);   cudaGetSymbolAddress((void**)&gL,   p_g_lo);
    cudaGetSymbolAddress((void**)&WiH,  p_Wi_hi);
    cudaGetSymbolAddress((void**)&WoH,  p_Wo_hi);
    cudaGetSymbolAddress((void**)&W1H,  p_W1_hi);
    cudaGetSymbolAddress((void**)&W2H,  p_W2_hi);
    cudaGetSymbolAddress((void**)&WdH,  p_Wd_hi);
    cudaGetSymbolAddress((void**)&relH, p_rel_hi);

    cudaFuncSetAttribute(bgemm<3,1,1,64>,  cudaFuncAttributeMaxDynamicSharedMemorySize, SM_B(64,1));
    cudaFuncSetAttribute(bgemm<4,1,0,128>, cudaFuncAttributeMaxDynamicSharedMemorySize, SM_B(128,0));
    cudaFuncSetAttribute(bgemm<3,1,0,64>,  cudaFuncAttributeMaxDynamicSharedMemorySize, SM_B(64,0));
    cudaFuncSetAttribute(bgemm<1,2,1,64>,  cudaFuncAttributeMaxDynamicSharedMemorySize, SM_B(64,1));
    cudaFuncSetAttribute(bgemm<2,1,1,64>,  cudaFuncAttributeMaxDynamicSharedMemorySize, SM_B(64,1));
    cudaFuncSetAttribute(bgemm<0,1,0,128>, cudaFuncAttributeMaxDynamicSharedMemorySize, SM_B(128,0));
    cudaFuncSetAttribute(attn_k,           cudaFuncAttributeMaxDynamicSharedMemorySize, ATT_SMEM);

    // weight splits (hi-only)
    split_hi_k<<<(4*1536*256/8 + 255)/256, 256>>>(inW,  WiH, 4*1536*256);
    split_hi_k<<<(4*512*256/8  + 255)/256, 256>>>(outW, WoH, 4*512*256);
    split_hi_k<<<(4*2048*256/8 + 255)/256, 256>>>(w1,   W1H, 4*2048*256);
    split_hi_k<<<(4*512*1024/8 + 255)/256, 256>>>(w2,   W2H, 4*512*1024);
    split_hi_k<<<(V_DIM*256/8  + 255)/256, 256>>>(decW, WdH, V_DIM*256);
    split_hi_k<<<(511*256/8    + 255)/256, 256>>>(rel,  relH, 511*256);

    embed_ln_k<<<N_ROWS, 256>>>(src, emb, nin_s, nin_b, x);

    for (int l = 0; l < 4; l++) {
        const uint32_t* WiHl = WiH + (size_t)l * 1536 * 256;
        const uint32_t* WoHl = WoH + (size_t)l * 512 * 256;
        const uint32_t* W1Hl = W1H + (size_t)l * 2048 * 256;
        const uint32_t* W2Hl = W2H + (size_t)l * 512 * 1024;
        const float* inB_l  = inB  + (size_t)l * QKV_DIM;
        const float* outB_l = outB + (size_t)l * E_DIM;
        const float* b1_l   = b1   + (size_t)l * FF_DIM;
        const float* b2_l   = b2   + (size_t)l * E_DIM;

        layernorm_split_k<<<N_ROWS, 256>>>(x, ln1s + l*E_DIM, ln1b + l*E_DIM, hH, hL);

        // qkv hi plane = h @ inW^T + inB   (2-term A, 64x128 tiles)
        bgemm<3,1,1,64><<<dim3(12, 16, 1), 256, SM_B(64,1)>>>(hH, hL, WiHl, inB_l,
            (float*)0, qkvH, (uint32_t*)0, N_ROWS, QKV_DIM, 256, 256, 256, 768,
            0,0, 0,0, 0,0);

        // V transpose
        vtrans_k<<<N_BH, 256>>>(qkvH, vT);

        // qr fp16 = Q @ rel^T  (1-term, 128x128 tiles, packed fp16 out)
        bgemm<4,1,0,128><<<dim3(4, 2, N_BH), 256, SM_B(128,0)>>>(qkvH, (const uint32_t*)0, relH,
            (const float*)0, (float*)qrH, (uint32_t*)0, (uint32_t*)0,
            S_LEN, 511, 32, 768, 256, 512,
            256*768, 32, 0, 32, 8*131072, 131072);

        // fused scores + bias + mask + softmax
        attn_k<<<dim3(2, N_BH), 256, ATT_SMEM>>>(qkvH, qrH, prH);

        // o planes = probs @ V^T  (1-term, 64x128 tiles)
        bgemm<3,1,0,64><<<dim3(1, 4, N_BH), 256, SM_B(64,0)>>>(prH, (const uint32_t*)0, vT,
            (const float*)0, (float*)0, oH, oL,
            S_LEN, 64, 128, 128, 128, 256,
            8*32768, 32768, 8*8192, 8192, 65536, 32);

        // x += o @ outW^T + outB   (splitK 2, 2-term A)
        bgemm<1,2,1,64><<<dim3(4, 16, 2), 256, SM_B(64,1)>>>(oH, oL, WoHl, outB_l,
            x, (uint32_t*)0, (uint32_t*)0, N_ROWS, E_DIM, 256, 256, 256, E_DIM,
            0,0, 0,0, 0,0);

        layernorm_split_k<<<N_ROWS, 256>>>(x, ln2s + l*E_DIM, ln2b + l*E_DIM, hH, hL);

        // g planes = gelu(h @ w1^T + b1)  (2-term A)
        bgemm<2,1,1,64><<<dim3(16, 16, 1), 256, SM_B(64,1)>>>(hH, hL, W1Hl, b1_l,
            (float*)0, gH, gL, N_ROWS, FF_DIM, 256, 256, 256, 1024,
            0,0, 0,0, 0,0);

        // x += g @ w2^T + b2   (splitK 2, 2-term A)
        bgemm<1,2,1,64><<<dim3(4, 16, 2), 256, SM_B(64,1)>>>(gH, gL, W2Hl, b2_l,
            x, (uint32_t*)0, (uint32_t*)0, N_ROWS, E_DIM, 1024, 1024, 1024, E_DIM,
            0,0, 0,0, 0,0);
    }

    layernorm_split_k<<<N_ROWS, 256>>>(x, nfs, nfb, hH, hL);

    // out f32 = h @ dec_w^T + dec_b   (1-term, 128x128 tiles)
    bgemm<0,1,0,128><<<dim3(250, 8, 1), 256, SM_B(128,0)>>>(hH, (const uint32_t*)0, WdH, decB,
        out, (uint32_t*)0, (uint32_t*)0, N_ROWS, V_DIM, 256, 256, 256, V_DIM,
        0,0, 0,0, 0,0);
}

// round 14
// speedup vs baseline: 1.6713x; 1.0393x over previous
#include <cuda_runtime.h>
#include <cuda_fp16.h>
#include <math.h>
#include <stdint.h>

// ---------------- problem constants ----------------
#define N_ROWS   1024
#define E_DIM    512
#define QKV_DIM  1536
#define FF_DIM   2048
#define V_DIM    32000
#define N_BH     32
#define S_LEN    256

// ---------------- scratch ----------------
__device__ float g_x [N_ROWS * E_DIM];
__device__ float g_qr[N_BH * S_LEN * 512];

// ---------------- packed fp16 planes (word = 2 consecutive-k halves) ----------------
__device__ uint32_t p_h_hi  [N_ROWS * 256],  p_h_lo  [N_ROWS * 256];
__device__ uint32_t p_qkv_hi[N_ROWS * 768];
__device__ uint32_t p_pr_hi [N_BH * S_LEN * 128];
__device__ uint32_t p_vT    [N_BH * 64 * 128];
__device__ uint32_t p_o_hi  [N_ROWS * 256],  p_o_lo  [N_ROWS * 256];
__device__ uint32_t p_g_hi  [N_ROWS * 1024], p_g_lo  [N_ROWS * 1024];
__device__ uint32_t p_Wi_hi [4 * 1536 * 256];
__device__ uint32_t p_Wo_hi [4 * 512 * 256];
__device__ uint32_t p_W1_hi [4 * 2048 * 256];
__device__ uint32_t p_W2_hi [4 * 512 * 1024];
__device__ uint32_t p_Wd_hi [V_DIM * 256];
__device__ uint32_t p_rel_hi[511 * 256];

// ---------------- helpers ----------------
__device__ __forceinline__ void splitpack(float v0, float v1, uint32_t& hi, uint32_t& lo) {
    __half h0 = __float2half_rn(v0);
    __half h1 = __float2half_rn(v1);
    float r0 = v0 - __half2float(h0);
    float r1 = v1 - __half2float(h1);
    __half l0 = __float2half_rn(r0);
    __half l1 = __float2half_rn(r1);
    hi = (uint32_t)__half_as_ushort(h0) | ((uint32_t)__half_as_ushort(h1) << 16);
    lo = (uint32_t)__half_as_ushort(l0) | ((uint32_t)__half_as_ushort(l1) << 16);
}
__device__ __forceinline__ uint32_t pack_hi(float v0, float v1) {
    __half h0 = __float2half_rn(v0);
    __half h1 = __float2half_rn(v1);
    return (uint32_t)__half_as_ushort(h0) | ((uint32_t)__half_as_ushort(h1) << 16);
}

__device__ __forceinline__ float warpSum(float v) {
    #pragma unroll
    for (int o = 16; o; o >>= 1) v += __shfl_xor_sync(0xffffffffu, v, o);
    return v;
}
__device__ __forceinline__ float blockSum(float v) {
    __shared__ float sm[8];
    int lane = threadIdx.x & 31, w = threadIdx.x >> 5;
    v = warpSum(v);
    __syncthreads();
    if (lane == 0) sm[w] = v;
    __syncthreads();
    float r = 0.f;
    #pragma unroll
    for (int i = 0; i < 8; i++) r += sm[i];
    return r;
}

// ---------------- merged f32 -> fp16 hi-plane split (6 segments, one launch) ----------
__global__ void split_all_k(const float* __restrict__ s0, const float* __restrict__ s1,
                            const float* __restrict__ s2, const float* __restrict__ s3,
                            const float* __restrict__ s4, const float* __restrict__ s5,
                            uint32_t* __restrict__ d0, uint32_t* __restrict__ d1,
                            uint32_t* __restrict__ d2, uint32_t* __restrict__ d3,
                            uint32_t* __restrict__ d4, uint32_t* __restrict__ d5,
                            int n0, int n1, int n2, int n3, int n4, int n5) {
    long long w = ((long long)blockIdx.x * 256 + threadIdx.x) * 8;
    const float* src; uint32_t* dst; long long loc = w;
    if (loc < n0)            { src = s0; dst = d0; }
    else { loc -= n0; if (loc < n1) { src = s1; dst = d1; }
    else { loc -= n1; if (loc < n2) { src = s2; dst = d2; }
    else { loc -= n2; if (loc < n3) { src = s3; dst = d3; }
    else { loc -= n3; if (loc < n4) { src = s4; dst = d4; }
    else { loc -= n4; if (loc < n5) { src = s5; dst = d5; }
    else return; }}}}}
    #pragma unroll
    for (int j = 0; j < 2; j++) {
        float4 a = *(const float4*)(src + 2 * (loc + j * 4));
        float4 b = *(const float4*)(src + 2 * (loc + j * 4) + 4);
        uint4 o;
        o.x = pack_hi(a.x, a.y); o.y = pack_hi(a.z, a.w);
        o.z = pack_hi(b.x, b.y); o.w = pack_hi(b.z, b.w);
        *(uint4*)(dst + loc + j * 4) = o;
    }
}

// ---------------- embed + input layernorm -> f32 x ----------------
__global__ void embed_ln_k(const int* __restrict__ src, const float* __restrict__ emb,
                           const float* __restrict__ s, const float* __restrict__ b,
                           float* __restrict__ out) {
    int row = blockIdx.x, t = threadIdx.x;
    int tok = src[row];
    const float SC = 22.62741699796952f;
    float v0 = emb[(size_t)tok * E_DIM + t]       * SC;
    float v1 = emb[(size_t)tok * E_DIM + t + 256] * SC;
    float mean = blockSum(v0 + v1) * (1.f / E_DIM);
    float d0 = v0 - mean, d1 = v1 - mean;
    float var = blockSum(d0 * d0 + d1 * d1) * (1.f / E_DIM);
    float r = rsqrtf(var + 1e-5f);
    out[(size_t)row * E_DIM + t]       = d0 * r * s[t]       + b[t];
    out[(size_t)row * E_DIM + t + 256] = d1 * r * s[t + 256] + b[t + 256];
}

// ---------------- layernorm f32 -> split planes ----------------
__global__ void layernorm_split_k(const float* __restrict__ in, const float* __restrict__ s,
                                  const float* __restrict__ b,
                                  uint32_t* __restrict__ oh, uint32_t* __restrict__ ol) {
    int row = blockIdx.x, t = threadIdx.x;
    float2 v = *(const float2*)(in + (size_t)row * E_DIM + 2 * t);
    float mean = blockSum(v.x + v.y) * (1.f / E_DIM);
    float d0 = v.x - mean, d1 = v.y - mean;
    float var = blockSum(d0 * d0 + d1 * d1) * (1.f / E_DIM);
    float r = rsqrtf(var + 1e-5f);
    float y0 = d0 * r * s[2 * t]     + b[2 * t];
    float y1 = d1 * r * s[2 * t + 1] + b[2 * t + 1];
    uint32_t h, l;
    splitpack(y0, y1, h, l);
    oh[(size_t)row * 256 + t] = h;
    ol[(size_t)row * 256 + t] = l;
}

// ---------------- mma / ldmatrix / cp.async primitives ----------------
#define MMA_F16(C, A0, A1, A2, A3, B0, B1)                                      \
    asm volatile("mma.sync.aligned.m16n8k16.row.col.f32.f16.f16.f32 "           \
                 "{%0,%1,%2,%3},{%4,%5,%6,%7},{%8,%9},{%0,%1,%2,%3};"           \
                 : "+f"(C[0]), "+f"(C[1]), "+f"(C[2]), "+f"(C[3])               \
                 : "r"(A0), "r"(A1), "r"(A2), "r"(A3), "r"(B0), "r"(B1))

__device__ __forceinline__ void ldsm4(uint32_t& r0, uint32_t& r1, uint32_t& r2, uint32_t& r3,
                                      uint32_t addr) {
    asm volatile("ldmatrix.sync.aligned.m8n8.x4.shared.b16 {%0,%1,%2,%3}, [%4];"
                 : "=r"(r0), "=r"(r1), "=r"(r2), "=r"(r3) : "r"(addr));
}

__device__ __forceinline__ void cp16w(uint32_t* dst, const uint32_t* src, bool pred) {
    uint32_t d = (uint32_t)__cvta_generic_to_shared(dst);
    int sz = pred ? 16 : 0;
    asm volatile("cp.async.cg.shared.global [%0], [%1], 16, %2;"
                 :: "r"(d), "l"(src), "r"(sz));
}

// ---------------- fused attention: scores + rel-bias gather + mask + softmax ----------
#define ATT_STRIDE 36
#define ATT_SMEM ((128 * ATT_STRIDE + 256 * ATT_STRIDE) * 4 + 128 * 4 * 4)
__global__ __launch_bounds__(256, 1)
void attn_k(const uint32_t* __restrict__ qkvH, const float* __restrict__ qr,
            uint32_t* __restrict__ ph) {
    extern __shared__ uint32_t asm_[];
    uint32_t* qs = asm_;
    uint32_t* ks = asm_ + 128 * ATT_STRIDE;
    float* red = (float*)(ks + 256 * ATT_STRIDE);

    int tile = blockIdx.x;
    int bh = blockIdx.y;
    int zb = bh >> 3, zh = bh & 7;
    const uint32_t* Q = qkvH + (size_t)zb * (256 * 768) + zh * 32;
    const uint32_t* K = Q + 256;
    const float* qrb = qr + (size_t)bh * (256 * 512);
    int l0 = tile * 128;

    int tid = threadIdx.x, lane = tid & 31, wid = tid >> 5;

    {
        int lrow = tid >> 1, seg = (tid & 1) * 16;
        const uint32_t* qrow = Q + (size_t)(l0 + lrow) * 768 + seg;
        uint32_t* qd = qs + lrow * ATT_STRIDE + seg;
        #pragma unroll
        for (int j = 0; j < 4; j++) cp16w(qd + j * 4, qrow + j * 4, true);
        const uint32_t* krow = K + (size_t)tid * 768;
        uint32_t* kd = ks + tid * ATT_STRIDE;
        #pragma unroll
        for (int j = 0; j < 8; j++) cp16w(kd + j * 4, krow + j * 4, true);
    }
    asm volatile("cp.async.commit_group;");
    asm volatile("cp.async.wait_group 0;");
    __syncthreads();

    int warpM = wid >> 2, warpN = wid & 3;
    int wm0 = warpM * 64, wn0 = warpN * 64;
    int g = lane >> 2, tg = lane & 3;
    uint32_t smQ = (uint32_t)__cvta_generic_to_shared(qs);
    uint32_t smK = (uint32_t)__cvta_generic_to_shared(ks);
    uint32_t a_base = smQ + ((uint32_t)(wm0 + (lane & 15)) * ATT_STRIDE + ((lane & 16) ? 4 : 0)) * 4;
    uint32_t b_base = smK + ((uint32_t)(wn0 + (lane & 7) + ((lane & 16) ? 8 : 0)) * ATT_STRIDE
                             + ((lane & 8) ? 4 : 0)) * 4;

    float acc[4][8][4] = {};
    #pragma unroll
    for (int c = 0; c < 4; c++) {
        uint32_t koff = (uint32_t)c * 32;
        uint32_t Bf[8][2];
        #pragma unroll
        for (int t = 0; t < 4; t++)
            ldsm4(Bf[2 * t][0], Bf[2 * t][1], Bf[2 * t + 1][0], Bf[2 * t + 1][1],
                  b_base + koff + (uint32_t)t * 16 * ATT_STRIDE * 4);
        #pragma unroll
        for (int mi = 0; mi < 4; mi++) {
            uint32_t Af[4];
            ldsm4(Af[0], Af[1], Af[2], Af[3],
                  a_base + koff + (uint32_t)mi * 16 * ATT_STRIDE * 4);
            #pragma unroll
            for (int ni = 0; ni < 8; ni++)
                MMA_F16(acc[mi][ni], Af[0], Af[1], Af[2], Af[3], Bf[ni][0], Bf[ni][1]);
        }
    }
    __syncthreads();

    #pragma unroll
    for (int mi = 0; mi < 4; mi++) {
        #pragma unroll
        for (int rr = 0; rr < 2; rr++) {
            int lrow = wm0 + mi * 16 + g + rr * 8;
            int lglob = l0 + lrow;
            const float* qrl = qrb + (size_t)lglob * 512 + (255 - lglob);
            #pragma unroll
            for (int ni = 0; ni < 8; ni++) {
                int m = wn0 + ni * 8 + tg * 2;
                float b0 = qrl[m], b1 = qrl[m + 1];
                acc[mi][ni][rr * 2]     = acc[mi][ni][rr * 2]     * 0.125f + b0 + ((m     > lglob) ? 1.f : 0.f);
                acc[mi][ni][rr * 2 + 1] = acc[mi][ni][rr * 2 + 1] * 0.125f + b1 + ((m + 1 > lglob) ? 1.f : 0.f);
            }
        }
    }

    float rmax[4][2];
    #pragma unroll
    for (int mi = 0; mi < 4; mi++)
        #pragma unroll
        for (int rr = 0; rr < 2; rr++) {
            float mx = -3.4e38f;
            #pragma unroll
            for (int ni = 0; ni < 8; ni++) {
                mx = fmaxf(mx, acc[mi][ni][rr * 2]);
                mx = fmaxf(mx, acc[mi][ni][rr * 2 + 1]);
            }
            mx = fmaxf(mx, __shfl_xor_sync(0xffffffffu, mx, 1));
            mx = fmaxf(mx, __shfl_xor_sync(0xffffffffu, mx, 2));
            int lrow = wm0 + mi * 16 + g + rr * 8;
            if (tg == 0) red[lrow * 4 + warpN] = mx;
            rmax[mi][rr] = 0.f;
        }
    __syncthreads();
    #pragma unroll
    for (int mi = 0; mi < 4; mi++)
        #pragma unroll
        for (int rr = 0; rr < 2; rr++) {
            int lrow = wm0 + mi * 16 + g + rr * 8;
            rmax[mi][rr] = fmaxf(fmaxf(red[lrow * 4 + 0], red[lrow * 4 + 1]),
                                 fmaxf(red[lrow * 4 + 2], red[lrow * 4 + 3]));
        }
    __syncthreads();

    float rsum[4][2];
    #pragma unroll
    for (int mi = 0; mi < 4; mi++)
        #pragma unroll
        for (int rr = 0; rr < 2; rr++) {
            float s = 0.f;
            #pragma unroll
            for (int ni = 0; ni < 8; ni++) {
                float e0 = expf(acc[mi][ni][rr * 2]     - rmax[mi][rr]);
                float e1 = expf(acc[mi][ni][rr * 2 + 1] - rmax[mi][rr]);
                acc[mi][ni][rr * 2] = e0; acc[mi][ni][rr * 2 + 1] = e1;
                s += e0 + e1;
            }
            s += __shfl_xor_sync(0xffffffffu, s, 1);
            s += __shfl_xor_sync(0xffffffffu, s, 2);
            int lrow = wm0 + mi * 16 + g + rr * 8;
            if (tg == 0) red[lrow * 4 + warpN] = s;
            rsum[mi][rr] = 0.f;
        }
    __syncthreads();
    #pragma unroll
    for (int mi = 0; mi < 4; mi++)
        #pragma unroll
        for (int rr = 0; rr < 2; rr++) {
            int lrow = wm0 + mi * 16 + g + rr * 8;
            rsum[mi][rr] = red[lrow * 4 + 0] + red[lrow * 4 + 1]
                         + red[lrow * 4 + 2] + red[lrow * 4 + 3];
        }

    uint32_t* pb = ph + (size_t)bh * (S_LEN * 128);
    #pragma unroll
    for (int mi = 0; mi < 4; mi++)
        #pragma unroll
        for (int rr = 0; rr < 2; rr++) {
            int lglob = l0 + wm0 + mi * 16 + g + rr * 8;
            float inv = 1.f / rsum[mi][rr];
            #pragma unroll
            for (int ni = 0; ni < 8; ni++) {
                float p0 = acc[mi][ni][rr * 2] * inv;
                float p1 = acc[mi][ni][rr * 2 + 1] * inv;
                pb[(size_t)lglob * 128 + (wn0 >> 1) + ni * 4 + tg] = pack_hi(p0, p1);
            }
        }
}

#define STAGES 3

// ---------------- fp16 GEMM, MT x 128 CTA tile, chunk k=16 (8 words) ----------------
// ALO: A hi+lo (2-term) vs hi only. B: pre-split hi plane.
// EPI: 0 f32 out (+bias); 1 f32 splitK atomicAdd (+bias at sk==0);
//      2 planes out bias+GELU; 3 planes out (+bias, Cl optional);
//      5 planes-hi out (+bias) with fused V-transpose side store (Cl = vT half buffer).
template<int EPI, int NSPLIT, int ALO, int MT>
__global__ __launch_bounds__(256, 2)
void bgemm(const uint32_t* __restrict__ Ah, const uint32_t* __restrict__ Al,
           const uint32_t* __restrict__ Bh,
           const float* __restrict__ bias,
           float* __restrict__ Cf, uint32_t* __restrict__ Ch, uint32_t* __restrict__ Cl,
           int M, int N, int Kw, int ldaw, int ldbw, int ldc,
           int aOffB, int aOffH, int bOffB, int bOffH, int cOffB, int cOffH) {
    extern __shared__ uint32_t smu[];
    constexpr int APW   = MT * 12;
    constexpr int BPW   = 128 * 12;
    constexpr int BOFFW = (1 + ALO) * APW;
    constexpr int STW   = BOFFW + BPW;
    constexpr int STB   = STW * 4;
    constexpr int WM    = MT / 2;
    constexpr int NMI   = MT / 32;

    int z = blockIdx.z;
    int sk = z % NSPLIT;
    int zz = z / NSPLIT;
    int zb = zz >> 3, zh = zz & 7;
    Ah += (size_t)zb * aOffB + (size_t)zh * aOffH;
    if (ALO) Al += (size_t)zb * aOffB + (size_t)zh * aOffH;
    Bh += (size_t)zb * bOffB + (size_t)zh * bOffH;
    size_t cAdj = (size_t)zb * cOffB + (size_t)zh * cOffH;
    if (EPI <= 1) Cf += cAdj;
    else if (EPI != 5) { Ch += cAdj; if (Cl) Cl += cAdj; }
    else Ch += cAdj;   // EPI==5: Cl is the vT half buffer (no batch adjust)

    int kLenW = Kw / NSPLIT;
    int kw0   = sk * kLenW;
    int nk    = kLenW >> 3;

    int tid  = threadIdx.x;
    int lane = tid & 31, wid = tid >> 5;
    int wm0 = (wid >> 2) * WM;
    int wn0 = (wid & 3) * 32;
    int g   = lane >> 2;
    int tg  = lane & 3;
    int row0 = blockIdx.y * MT, col0 = blockIdx.x * 128;

    uint32_t smBase = (uint32_t)__cvta_generic_to_shared(smu);
    uint32_t a_off = ((uint32_t)(wm0 + (lane & 15)) * 12 + ((lane & 16) ? 4 : 0)) * 4;
    uint32_t b_off = ((uint32_t)(wn0 + (lane & 7) + ((lane & 16) ? 8 : 0)) * 12
                      + ((lane & 8) ? 4 : 0)) * 4;

    float acc[NMI][4][4] = {};

    auto COMPUTE = [&](int buf) {
        uint32_t sb = smBase + (uint32_t)buf * STB;
        uint32_t aH = sb + a_off;
        uint32_t aL = aH + APW * 4;
        uint32_t bH = sb + BOFFW * 4 + b_off;
        uint32_t Bhf[4][2];
        ldsm4(Bhf[0][0], Bhf[0][1], Bhf[1][0], Bhf[1][1], bH);
        ldsm4(Bhf[2][0], Bhf[2][1], Bhf[3][0], Bhf[3][1], bH + 16 * 12 * 4);
        #pragma unroll
        for (int mi = 0; mi < NMI; mi++) {
            uint32_t Af[4];
            ldsm4(Af[0], Af[1], Af[2], Af[3], aH + (uint32_t)mi * 16 * 12 * 4);
            uint32_t Lf[4];
            if (ALO) ldsm4(Lf[0], Lf[1], Lf[2], Lf[3], aL + (uint32_t)mi * 16 * 12 * 4);
            #pragma unroll
            for (int ni = 0; ni < 4; ni++) {
                MMA_F16(acc[mi][ni], Af[0], Af[1], Af[2], Af[3], Bhf[ni][0], Bhf[ni][1]);
                if (ALO)
                    MMA_F16(acc[mi][ni], Lf[0], Lf[1], Lf[2], Lf[3], Bhf[ni][0], Bhf[ni][1]);
            }
        }
    };

    auto LOADNT = [&](int chunk, int buf) {
        int kws = kw0 + (chunk << 3);
        uint32_t* st = smu + buf * STW;
        if (MT == 128) {
            int r = tid >> 1, s = (tid & 1) * 4;
            cp16w(st + r * 12 + s, Ah + (size_t)(row0 + r) * ldaw + kws + s, true);
            if (ALO)
                cp16w(st + APW + r * 12 + s, Al + (size_t)(row0 + r) * ldaw + kws + s, true);
        } else {
            int r = (tid & 127) >> 1, s = (tid & 1) * 4;
            if (!ALO) {
                if (tid < 128)
                    cp16w(st + r * 12 + s, Ah + (size_t)(row0 + r) * ldaw + kws + s, true);
            } else {
                const uint32_t* srcp = (tid < 128) ? Ah : Al;
                uint32_t* dstp = st + ((tid < 128) ? 0 : APW);
                cp16w(dstp + r * 12 + s, srcp + (size_t)(row0 + r) * ldaw + kws + s, true);
            }
        }
        int rb = tid >> 1, sb2 = (tid & 1) * 4;
        bool p = (col0 + rb) < N;
        cp16w(st + BOFFW + rb * 12 + sb2, Bh + (size_t)(col0 + rb) * ldbw + kws + sb2, p);
    };

    int pre = (nk < STAGES - 1) ? nk : (STAGES - 1);
    for (int s = 0; s < pre; s++) {
        LOADNT(s, s);
        asm volatile("cp.async.commit_group;");
    }
    for (int i = 0; i < nk; i++) {
        int buf = i % STAGES;
        asm volatile("cp.async.wait_group %0;" :: "n"(STAGES - 2));
        __syncthreads();
        COMPUTE(buf);
        int nxt = i + STAGES - 1;
        if (nxt < nk) LOADNT(nxt, nxt % STAGES);
        asm volatile("cp.async.commit_group;");
    }

    // ---------------- epilogue ----------------
    #pragma unroll
    for (int mi = 0; mi < NMI; mi++) {
        #pragma unroll
        for (int rr = 0; rr < 2; rr++) {
            int r = row0 + wm0 + mi * 16 + g + rr * 8;
            #pragma unroll
            for (int ni = 0; ni < 4; ni++) {
                int c = col0 + wn0 + ni * 8 + tg * 2;
                float v0 = acc[mi][ni][rr * 2];
                float v1 = acc[mi][ni][rr * 2 + 1];
                if (EPI == 0) {
                    float* Crow = Cf + (size_t)r * ldc;
                    if (c + 1 < N) {
                        if (bias) { v0 += bias[c]; v1 += bias[c + 1]; }
                        *(float2*)&Crow[c] = make_float2(v0, v1);
                    } else if (c < N) {
                        if (bias) v0 += bias[c];
                        Crow[c] = v0;
                    }
                } else if (EPI == 1) {
                    float* Crow = Cf + (size_t)r * ldc;
                    if (bias && sk == 0) {
                        if (c < N)     v0 += bias[c];
                        if (c + 1 < N) v1 += bias[c + 1];
                    }
                    if (c < N)     atomicAdd(&Crow[c], v0);
                    if (c + 1 < N) atomicAdd(&Crow[c + 1], v1);
                } else if (EPI == 5) {
                    if (c < N) {
                        if (bias) { v0 += bias[c]; v1 += bias[c + 1]; }
                        uint32_t h = pack_hi(v0, v1);
                        Ch[(size_t)r * ldc + (c >> 1)] = h;
                        if (c >= 1024) {            // V range: side-store transposed halves
                            int d = c - 1024;
                            int b = r >> 8, s = r & 255;
                            __half* vTh = (__half*)Cl;
                            size_t base = ((size_t)(b * 8 + (d >> 6)) * 64 + (d & 63)) * 256 + s;
                            vTh[base]       = __ushort_as_half((unsigned short)(h & 0xffffu));
                            vTh[base + 256] = __ushort_as_half((unsigned short)(h >> 16));
                        }
                    }
                } else {
                    if (c < N) {
                        if (bias) { v0 += bias[c]; v1 += bias[c + 1]; }
                        if (EPI == 2) {
                            v0 = 0.5f * v0 * (1.f + erff(v0 * 0.7071067811865476f));
                            v1 = 0.5f * v1 * (1.f + erff(v1 * 0.7071067811865476f));
                        }
                        uint32_t h, l;
                        splitpack(v0, v1, h, l);
                        size_t idx = (size_t)r * ldc + (c >> 1);
                        Ch[idx] = h;
                        if (Cl) Cl[idx] = l;
                    }
                }
            }
        }
    }
}

#define SM_B(MT, ALO) (STAGES * (((1 + (ALO)) * (MT) * 12) + 128 * 12) * 4)

// ---------------- driver ----------------
extern "C" void kernel_launch(void* const* d_in, const int* in_sizes, int n_in,
                              void* d_out, int out_size) {
    const int*   src   = (const int*)  d_in[0];
    const float* emb   = (const float*)d_in[1];
    const float* rel   = (const float*)d_in[2];
    const float* nin_s = (const float*)d_in[3];
    const float* nin_b = (const float*)d_in[4];
    const float* inW   = (const float*)d_in[5];
    const float* inB   = (const float*)d_in[6];
    const float* outW  = (const float*)d_in[7];
    const float* outB  = (const float*)d_in[8];
    const float* ln1s  = (const float*)d_in[9];
    const float* ln1b  = (const float*)d_in[10];
    const float* ln2s  = (const float*)d_in[11];
    const float* ln2b  = (const float*)d_in[12];
    const float* w1    = (const float*)d_in[13];
    const float* b1    = (const float*)d_in[14];
    const float* w2    = (const float*)d_in[15];
    const float* b2    = (const float*)d_in[16];
    const float* nfs   = (const float*)d_in[17];
    const float* nfb   = (const float*)d_in[18];
    const float* decW  = (const float*)d_in[19];
    const float* decB  = (const float*)d_in[20];
    float* out = (float*)d_out;

    float *x, *qr;
    cudaGetSymbolAddress((void**)&x,  g_x);
    cudaGetSymbolAddress((void**)&qr, g_qr);
    uint32_t *hH,*hL,*qkvH,*prH,*vT,*oH,*oL,*gH,*gL;
    uint32_t *WiH,*WoH,*W1H,*W2H,*WdH,*relH;
    cudaGetSymbolAddress((void**)&hH,   p_h_hi);   cudaGetSymbolAddress((void**)&hL,   p_h_lo);
    cudaGetSymbolAddress((void**)&qkvH, p_qkv_hi);
    cudaGetSymbolAddress((void**)&prH,  p_pr_hi);
    cudaGetSymbolAddress((void**)&vT,   p_vT);
    cudaGetSymbolAddress((void**)&oH,   p_o_hi);   cudaGetSymbolAddress((void**)&oL,   p_o_lo);
    cudaGetSymbolAddress((void**)&gH,   p_g_hi);   cudaGetSymbolAddress((void**)&gL,   p_g_lo);
    cudaGetSymbolAddress((void**)&WiH,  p_Wi_hi);
    cudaGetSymbolAddress((void**)&WoH,  p_Wo_hi);
    cudaGetSymbolAddress((void**)&W1H,  p_W1_hi);
    cudaGetSymbolAddress((void**)&W2H,  p_W2_hi);
    cudaGetSymbolAddress((void**)&WdH,  p_Wd_hi);
    cudaGetSymbolAddress((void**)&relH, p_rel_hi);

    cudaFuncSetAttribute(bgemm<5,1,1,64>,  cudaFuncAttributeMaxDynamicSharedMemorySize, SM_B(64,1));
    cudaFuncSetAttribute(bgemm<0,1,0,128>, cudaFuncAttributeMaxDynamicSharedMemorySize, SM_B(128,0));
    cudaFuncSetAttribute(bgemm<3,1,0,64>,  cudaFuncAttributeMaxDynamicSharedMemorySize, SM_B(64,0));
    cudaFuncSetAttribute(bgemm<1,2,1,64>,  cudaFuncAttributeMaxDynamicSharedMemorySize, SM_B(64,1));
    cudaFuncSetAttribute(bgemm<2,1,1,64>,  cudaFuncAttributeMaxDynamicSharedMemorySize, SM_B(64,1));
    cudaFuncSetAttribute(attn_k,           cudaFuncAttributeMaxDynamicSharedMemorySize, ATT_SMEM);

    // single merged weight split: inW, outW, w1, w2, decW, rel
    {
        int n0 = 4*1536*256, n1 = 4*512*256, n2 = 4*2048*256,
            n3 = 4*512*1024, n4 = V_DIM*256, n5 = 511*256;
        long long total = (long long)n0 + n1 + n2 + n3 + n4 + n5;
        int blocks = (int)((total / 8 + 255) / 256);
        split_all_k<<<blocks, 256>>>(inW, outW, w1, w2, decW, rel,
                                     WiH, WoH, W1H, W2H, WdH, relH,
                                     n0, n1, n2, n3, n4, n5);
    }

    embed_ln_k<<<N_ROWS, 256>>>(src, emb, nin_s, nin_b, x);

    for (int l = 0; l < 4; l++) {
        const uint32_t* WiHl = WiH + (size_t)l * 1536 * 256;
        const uint32_t* WoHl = WoH + (size_t)l * 512 * 256;
        const uint32_t* W1Hl = W1H + (size_t)l * 2048 * 256;
        const uint32_t* W2Hl = W2H + (size_t)l * 512 * 1024;
        const float* inB_l  = inB  + (size_t)l * QKV_DIM;
        const float* outB_l = outB + (size_t)l * E_DIM;
        const float* b1_l   = b1   + (size_t)l * FF_DIM;
        const float* b2_l   = b2   + (size_t)l * E_DIM;

        layernorm_split_k<<<N_ROWS, 256>>>(x, ln1s + l*E_DIM, ln1b + l*E_DIM, hH, hL);

        // qkv hi plane = h @ inW^T + inB  (2-term A) + fused V-transpose side store
        bgemm<5,1,1,64><<<dim3(12, 16, 1), 256, SM_B(64,1)>>>(hH, hL, WiHl, inB_l,
            (float*)0, qkvH, vT, N_ROWS, QKV_DIM, 256, 256, 256, 768,
            0,0, 0,0, 0,0);

        // qr f32 = Q @ rel^T  (1-term, 128x128 tiles)
        bgemm<0,1,0,128><<<dim3(4, 2, N_BH), 256, SM_B(128,0)>>>(qkvH, (const uint32_t*)0, relH,
            (const float*)0, qr, (uint32_t*)0, (uint32_t*)0,
            S_LEN, 511, 32, 768, 256, 512,
            256*768, 32, 0, 32, 8*131072, 131072);

        // fused scores + bias + mask + softmax
        attn_k<<<dim3(2, N_BH), 256, ATT_SMEM>>>(qkvH, qr, prH);

        // o planes = probs @ V^T  (1-term, 64x128 tiles)
        bgemm<3,1,0,64><<<dim3(1, 4, N_BH), 256, SM_B(64,0)>>>(prH, (const uint32_t*)0, vT,
            (const float*)0, (float*)0, oH, oL,
            S_LEN, 64, 128, 128, 128, 256,
            8*32768, 32768, 8*8192, 8192, 65536, 32);

        // x += o @ outW^T + outB   (splitK 2, 2-term A)
        bgemm<1,2,1,64><<<dim3(4, 16, 2), 256, SM_B(64,1)>>>(oH, oL, WoHl, outB_l,
            x, (uint32_t*)0, (uint32_t*)0, N_ROWS, E_DIM, 256, 256, 256, E_DIM,
            0,0, 0,0, 0,0);

        layernorm_split_k<<<N_ROWS, 256>>>(x, ln2s + l*E_DIM, ln2b + l*E_DIM, hH, hL);

        // g planes = gelu(h @ w1^T + b1)  (2-term A)
        bgemm<2,1,1,64><<<dim3(16, 16, 1), 256, SM_B(64,1)>>>(hH, hL, W1Hl, b1_l,
            (float*)0, gH, gL, N_ROWS, FF_DIM, 256, 256, 256, 1024,
            0,0, 0,0, 0,0);

        // x += g @ w2^T + b2   (splitK 2, 2-term A)
        bgemm<1,2,1,64><<<dim3(4, 16, 2), 256, SM_B(64,1)>>>(gH, gL, W2Hl, b2_l,
            x, (uint32_t*)0, (uint32_t*)0, N_ROWS, E_DIM, 1024, 1024, 1024, E_DIM,
            0,0, 0,0, 0,0);
    }

    layernorm_split_k<<<N_ROWS, 256>>>(x, nfs, nfb, hH, hL);

    // out f32 = h @ dec_w^T + dec_b   (1-term, 128x128 tiles)
    bgemm<0,1,0,128><<<dim3(250, 8, 1), 256, SM_B(128,0)>>>(hH, (const uint32_t*)0, WdH, decB,
        out, (uint32_t*)0, (uint32_t*)0, N_ROWS, V_DIM, 256, 256, 256, V_DIM,
        0,0, 0,0, 0,0);
}

// round 15
// speedup vs baseline: 1.7395x; 1.0408x over previous
#include <cuda_runtime.h>
#include <cuda_fp16.h>
#include <math.h>
#include <stdint.h>

// ---------------- problem constants ----------------
#define N_ROWS   1024
#define E_DIM    512
#define QKV_DIM  1536
#define FF_DIM   2048
#define V_DIM    32000
#define N_BH     32
#define S_LEN    256

// ---------------- scratch ----------------
__device__ float g_x [N_ROWS * E_DIM];
__device__ float g_qr[N_BH * S_LEN * 512];

// ---------------- packed fp16 planes (word = 2 consecutive-k halves) ----------------
__device__ uint32_t p_h_hi  [N_ROWS * 256],  p_h_lo  [N_ROWS * 256];
__device__ uint32_t p_qkv_hi[N_ROWS * 768];
__device__ uint32_t p_pr_hi [N_BH * S_LEN * 128];
__device__ uint32_t p_vT    [N_BH * 64 * 128];
__device__ uint32_t p_o_hi  [N_ROWS * 256],  p_o_lo  [N_ROWS * 256];
__device__ uint32_t p_g_hi  [N_ROWS * 1024], p_g_lo  [N_ROWS * 1024];
__device__ uint32_t p_Wi_hi [4 * 1536 * 256];
__device__ uint32_t p_Wo_hi [4 * 512 * 256];
__device__ uint32_t p_W1_hi [4 * 2048 * 256];
__device__ uint32_t p_W2_hi [4 * 512 * 1024];
__device__ uint32_t p_Wd_hi [V_DIM * 256];
__device__ uint32_t p_rel_hi[511 * 256];

// ---------------- helpers ----------------
__device__ __forceinline__ void splitpack(float v0, float v1, uint32_t& hi, uint32_t& lo) {
    __half h0 = __float2half_rn(v0);
    __half h1 = __float2half_rn(v1);
    float r0 = v0 - __half2float(h0);
    float r1 = v1 - __half2float(h1);
    __half l0 = __float2half_rn(r0);
    __half l1 = __float2half_rn(r1);
    hi = (uint32_t)__half_as_ushort(h0) | ((uint32_t)__half_as_ushort(h1) << 16);
    lo = (uint32_t)__half_as_ushort(l0) | ((uint32_t)__half_as_ushort(l1) << 16);
}
__device__ __forceinline__ uint32_t pack_hi(float v0, float v1) {
    __half h0 = __float2half_rn(v0);
    __half h1 = __float2half_rn(v1);
    return (uint32_t)__half_as_ushort(h0) | ((uint32_t)__half_as_ushort(h1) << 16);
}

__device__ __forceinline__ float warpSum(float v) {
    #pragma unroll
    for (int o = 16; o; o >>= 1) v += __shfl_xor_sync(0xffffffffu, v, o);
    return v;
}
__device__ __forceinline__ float blockSum(float v) {
    __shared__ float sm[8];
    int lane = threadIdx.x & 31, w = threadIdx.x >> 5;
    v = warpSum(v);
    __syncthreads();
    if (lane == 0) sm[w] = v;
    __syncthreads();
    float r = 0.f;
    #pragma unroll
    for (int i = 0; i < 8; i++) r += sm[i];
    return r;
}

// ---------------- merged f32 -> fp16 hi-plane split (6 segments, one launch) ----------
__global__ void split_all_k(const float* __restrict__ s0, const float* __restrict__ s1,
                            const float* __restrict__ s2, const float* __restrict__ s3,
                            const float* __restrict__ s4, const float* __restrict__ s5,
                            uint32_t* __restrict__ d0, uint32_t* __restrict__ d1,
                            uint32_t* __restrict__ d2, uint32_t* __restrict__ d3,
                            uint32_t* __restrict__ d4, uint32_t* __restrict__ d5,
                            int n0, int n1, int n2, int n3, int n4, int n5) {
    long long w = ((long long)blockIdx.x * 256 + threadIdx.x) * 8;
    const float* src; uint32_t* dst; long long loc = w;
    if (loc < n0)            { src = s0; dst = d0; }
    else { loc -= n0; if (loc < n1) { src = s1; dst = d1; }
    else { loc -= n1; if (loc < n2) { src = s2; dst = d2; }
    else { loc -= n2; if (loc < n3) { src = s3; dst = d3; }
    else { loc -= n3; if (loc < n4) { src = s4; dst = d4; }
    else { loc -= n4; if (loc < n5) { src = s5; dst = d5; }
    else return; }}}}}
    #pragma unroll
    for (int j = 0; j < 2; j++) {
        float4 a = *(const float4*)(src + 2 * (loc + j * 4));
        float4 b = *(const float4*)(src + 2 * (loc + j * 4) + 4);
        uint4 o;
        o.x = pack_hi(a.x, a.y); o.y = pack_hi(a.z, a.w);
        o.z = pack_hi(b.x, b.y); o.w = pack_hi(b.z, b.w);
        *(uint4*)(dst + loc + j * 4) = o;
    }
}

// ---------------- embed + input layernorm -> f32 x ----------------
__global__ void embed_ln_k(const int* __restrict__ src, const float* __restrict__ emb,
                           const float* __restrict__ s, const float* __restrict__ b,
                           float* __restrict__ out) {
    int row = blockIdx.x, t = threadIdx.x;
    int tok = src[row];
    const float SC = 22.62741699796952f;
    float v0 = emb[(size_t)tok * E_DIM + t]       * SC;
    float v1 = emb[(size_t)tok * E_DIM + t + 256] * SC;
    float mean = blockSum(v0 + v1) * (1.f / E_DIM);
    float d0 = v0 - mean, d1 = v1 - mean;
    float var = blockSum(d0 * d0 + d1 * d1) * (1.f / E_DIM);
    float r = rsqrtf(var + 1e-5f);
    out[(size_t)row * E_DIM + t]       = d0 * r * s[t]       + b[t];
    out[(size_t)row * E_DIM + t + 256] = d1 * r * s[t + 256] + b[t + 256];
}

// ---------------- layernorm f32 -> split planes ----------------
__global__ void layernorm_split_k(const float* __restrict__ in, const float* __restrict__ s,
                                  const float* __restrict__ b,
                                  uint32_t* __restrict__ oh, uint32_t* __restrict__ ol) {
    int row = blockIdx.x, t = threadIdx.x;
    float2 v = *(const float2*)(in + (size_t)row * E_DIM + 2 * t);
    float mean = blockSum(v.x + v.y) * (1.f / E_DIM);
    float d0 = v.x - mean, d1 = v.y - mean;
    float var = blockSum(d0 * d0 + d1 * d1) * (1.f / E_DIM);
    float r = rsqrtf(var + 1e-5f);
    float y0 = d0 * r * s[2 * t]     + b[2 * t];
    float y1 = d1 * r * s[2 * t + 1] + b[2 * t + 1];
    uint32_t h, l;
    splitpack(y0, y1, h, l);
    oh[(size_t)row * 256 + t] = h;
    ol[(size_t)row * 256 + t] = l;
}

// ---------------- mma / ldmatrix / cp.async primitives ----------------
#define MMA_F16(C, A0, A1, A2, A3, B0, B1)                                      \
    asm volatile("mma.sync.aligned.m16n8k16.row.col.f32.f16.f16.f32 "           \
                 "{%0,%1,%2,%3},{%4,%5,%6,%7},{%8,%9},{%0,%1,%2,%3};"           \
                 : "+f"(C[0]), "+f"(C[1]), "+f"(C[2]), "+f"(C[3])               \
                 : "r"(A0), "r"(A1), "r"(A2), "r"(A3), "r"(B0), "r"(B1))

__device__ __forceinline__ void ldsm4(uint32_t& r0, uint32_t& r1, uint32_t& r2, uint32_t& r3,
                                      uint32_t addr) {
    asm volatile("ldmatrix.sync.aligned.m8n8.x4.shared.b16 {%0,%1,%2,%3}, [%4];"
                 : "=r"(r0), "=r"(r1), "=r"(r2), "=r"(r3) : "r"(addr));
}

__device__ __forceinline__ void cp16w(uint32_t* dst, const uint32_t* src, bool pred) {
    uint32_t d = (uint32_t)__cvta_generic_to_shared(dst);
    int sz = pred ? 16 : 0;
    asm volatile("cp.async.cg.shared.global [%0], [%1], 16, %2;"
                 :: "r"(d), "l"(src), "r"(sz));
}

// ---------------- fused attention: scores + rel-bias gather + mask + softmax ----------
#define ATT_STRIDE 36
#define ATT_SMEM ((128 * ATT_STRIDE + 256 * ATT_STRIDE) * 4 + 128 * 4 * 4)
__global__ __launch_bounds__(256, 1)
void attn_k(const uint32_t* __restrict__ qkvH, const float* __restrict__ qr,
            uint32_t* __restrict__ ph) {
    extern __shared__ uint32_t asm_[];
    uint32_t* qs = asm_;
    uint32_t* ks = asm_ + 128 * ATT_STRIDE;
    float* red = (float*)(ks + 256 * ATT_STRIDE);

    int tile = blockIdx.x;
    int bh = blockIdx.y;
    int zb = bh >> 3, zh = bh & 7;
    const uint32_t* Q = qkvH + (size_t)zb * (256 * 768) + zh * 32;
    const uint32_t* K = Q + 256;
    const float* qrb = qr + (size_t)bh * (256 * 512);
    int l0 = tile * 128;

    int tid = threadIdx.x, lane = tid & 31, wid = tid >> 5;

    {
        int lrow = tid >> 1, seg = (tid & 1) * 16;
        const uint32_t* qrow = Q + (size_t)(l0 + lrow) * 768 + seg;
        uint32_t* qd = qs + lrow * ATT_STRIDE + seg;
        #pragma unroll
        for (int j = 0; j < 4; j++) cp16w(qd + j * 4, qrow + j * 4, true);
        const uint32_t* krow = K + (size_t)tid * 768;
        uint32_t* kd = ks + tid * ATT_STRIDE;
        #pragma unroll
        for (int j = 0; j < 8; j++) cp16w(kd + j * 4, krow + j * 4, true);
    }
    asm volatile("cp.async.commit_group;");
    asm volatile("cp.async.wait_group 0;");
    __syncthreads();

    int warpM = wid >> 2, warpN = wid & 3;
    int wm0 = warpM * 64, wn0 = warpN * 64;
    int g = lane >> 2, tg = lane & 3;
    uint32_t smQ = (uint32_t)__cvta_generic_to_shared(qs);
    uint32_t smK = (uint32_t)__cvta_generic_to_shared(ks);
    uint32_t a_base = smQ + ((uint32_t)(wm0 + (lane & 15)) * ATT_STRIDE + ((lane & 16) ? 4 : 0)) * 4;
    uint32_t b_base = smK + ((uint32_t)(wn0 + (lane & 7) + ((lane & 16) ? 8 : 0)) * ATT_STRIDE
                             + ((lane & 8) ? 4 : 0)) * 4;

    float acc[4][8][4] = {};
    #pragma unroll
    for (int c = 0; c < 4; c++) {
        uint32_t koff = (uint32_t)c * 32;
        uint32_t Bf[8][2];
        #pragma unroll
        for (int t = 0; t < 4; t++)
            ldsm4(Bf[2 * t][0], Bf[2 * t][1], Bf[2 * t + 1][0], Bf[2 * t + 1][1],
                  b_base + koff + (uint32_t)t * 16 * ATT_STRIDE * 4);
        #pragma unroll
        for (int mi = 0; mi < 4; mi++) {
            uint32_t Af[4];
            ldsm4(Af[0], Af[1], Af[2], Af[3],
                  a_base + koff + (uint32_t)mi * 16 * ATT_STRIDE * 4);
            #pragma unroll
            for (int ni = 0; ni < 8; ni++)
                MMA_F16(acc[mi][ni], Af[0], Af[1], Af[2], Af[3], Bf[ni][0], Bf[ni][1]);
        }
    }
    __syncthreads();

    #pragma unroll
    for (int mi = 0; mi < 4; mi++) {
        #pragma unroll
        for (int rr = 0; rr < 2; rr++) {
            int lrow = wm0 + mi * 16 + g + rr * 8;
            int lglob = l0 + lrow;
            const float* qrl = qrb + (size_t)lglob * 512 + (255 - lglob);
            #pragma unroll
            for (int ni = 0; ni < 8; ni++) {
                int m = wn0 + ni * 8 + tg * 2;
                float b0 = qrl[m], b1 = qrl[m + 1];
                acc[mi][ni][rr * 2]     = acc[mi][ni][rr * 2]     * 0.125f + b0 + ((m     > lglob) ? 1.f : 0.f);
                acc[mi][ni][rr * 2 + 1] = acc[mi][ni][rr * 2 + 1] * 0.125f + b1 + ((m + 1 > lglob) ? 1.f : 0.f);
            }
        }
    }

    float rmax[4][2];
    #pragma unroll
    for (int mi = 0; mi < 4; mi++)
        #pragma unroll
        for (int rr = 0; rr < 2; rr++) {
            float mx = -3.4e38f;
            #pragma unroll
            for (int ni = 0; ni < 8; ni++) {
                mx = fmaxf(mx, acc[mi][ni][rr * 2]);
                mx = fmaxf(mx, acc[mi][ni][rr * 2 + 1]);
            }
            mx = fmaxf(mx, __shfl_xor_sync(0xffffffffu, mx, 1));
            mx = fmaxf(mx, __shfl_xor_sync(0xffffffffu, mx, 2));
            int lrow = wm0 + mi * 16 + g + rr * 8;
            if (tg == 0) red[lrow * 4 + warpN] = mx;
            rmax[mi][rr] = 0.f;
        }
    __syncthreads();
    #pragma unroll
    for (int mi = 0; mi < 4; mi++)
        #pragma unroll
        for (int rr = 0; rr < 2; rr++) {
            int lrow = wm0 + mi * 16 + g + rr * 8;
            rmax[mi][rr] = fmaxf(fmaxf(red[lrow * 4 + 0], red[lrow * 4 + 1]),
                                 fmaxf(red[lrow * 4 + 2], red[lrow * 4 + 3]));
        }
    __syncthreads();

    float rsum[4][2];
    #pragma unroll
    for (int mi = 0; mi < 4; mi++)
        #pragma unroll
        for (int rr = 0; rr < 2; rr++) {
            float s = 0.f;
            #pragma unroll
            for (int ni = 0; ni < 8; ni++) {
                float e0 = expf(acc[mi][ni][rr * 2]     - rmax[mi][rr]);
                float e1 = expf(acc[mi][ni][rr * 2 + 1] - rmax[mi][rr]);
                acc[mi][ni][rr * 2] = e0; acc[mi][ni][rr * 2 + 1] = e1;
                s += e0 + e1;
            }
            s += __shfl_xor_sync(0xffffffffu, s, 1);
            s += __shfl_xor_sync(0xffffffffu, s, 2);
            int lrow = wm0 + mi * 16 + g + rr * 8;
            if (tg == 0) red[lrow * 4 + warpN] = s;
            rsum[mi][rr] = 0.f;
        }
    __syncthreads();
    #pragma unroll
    for (int mi = 0; mi < 4; mi++)
        #pragma unroll
        for (int rr = 0; rr < 2; rr++) {
            int lrow = wm0 + mi * 16 + g + rr * 8;
            rsum[mi][rr] = red[lrow * 4 + 0] + red[lrow * 4 + 1]
                         + red[lrow * 4 + 2] + red[lrow * 4 + 3];
        }

    uint32_t* pb = ph + (size_t)bh * (S_LEN * 128);
    #pragma unroll
    for (int mi = 0; mi < 4; mi++)
        #pragma unroll
        for (int rr = 0; rr < 2; rr++) {
            int lglob = l0 + wm0 + mi * 16 + g + rr * 8;
            float inv = 1.f / rsum[mi][rr];
            #pragma unroll
            for (int ni = 0; ni < 8; ni++) {
                float p0 = acc[mi][ni][rr * 2] * inv;
                float p1 = acc[mi][ni][rr * 2 + 1] * inv;
                pb[(size_t)lglob * 128 + (wn0 >> 1) + ni * 4 + tg] = pack_hi(p0, p1);
            }
        }
}

#define STAGES 5

// ---------------- fp16 GEMM, MT x 128 CTA tile, chunk k=16 (8 words) ----------------
// ALO: A hi+lo (2-term) vs hi only. B: pre-split hi plane.
// EPI: 0 f32 out (+bias); 1 f32 splitK atomicAdd (+bias at sk==0);
//      2 planes out bias+GELU; 3 planes out (+bias, Cl optional);
//      5 planes-hi out (+bias) with fused V-transpose side store (Cl = vT half buffer).
template<int EPI, int NSPLIT, int ALO, int MT>
__global__ __launch_bounds__(256, 2)
void bgemm(const uint32_t* __restrict__ Ah, const uint32_t* __restrict__ Al,
           const uint32_t* __restrict__ Bh,
           const float* __restrict__ bias,
           float* __restrict__ Cf, uint32_t* __restrict__ Ch, uint32_t* __restrict__ Cl,
           int M, int N, int Kw, int ldaw, int ldbw, int ldc,
           int aOffB, int aOffH, int bOffB, int bOffH, int cOffB, int cOffH) {
    extern __shared__ uint32_t smu[];
    constexpr int APW   = MT * 12;
    constexpr int BPW   = 128 * 12;
    constexpr int BOFFW = (1 + ALO) * APW;
    constexpr int STW   = BOFFW + BPW;
    constexpr int STB   = STW * 4;
    constexpr int WM    = MT / 2;
    constexpr int NMI   = MT / 32;

    int z = blockIdx.z;
    int sk = z % NSPLIT;
    int zz = z / NSPLIT;
    int zb = zz >> 3, zh = zz & 7;
    Ah += (size_t)zb * aOffB + (size_t)zh * aOffH;
    if (ALO) Al += (size_t)zb * aOffB + (size_t)zh * aOffH;
    Bh += (size_t)zb * bOffB + (size_t)zh * bOffH;
    size_t cAdj = (size_t)zb * cOffB + (size_t)zh * cOffH;
    if (EPI <= 1) Cf += cAdj;
    else if (EPI != 5) { Ch += cAdj; if (Cl) Cl += cAdj; }
    else Ch += cAdj;   // EPI==5: Cl is the vT half buffer (no batch adjust)

    int kLenW = Kw / NSPLIT;
    int kw0   = sk * kLenW;
    int nk    = kLenW >> 3;

    int tid  = threadIdx.x;
    int lane = tid & 31, wid = tid >> 5;
    int wm0 = (wid >> 2) * WM;
    int wn0 = (wid & 3) * 32;
    int g   = lane >> 2;
    int tg  = lane & 3;
    int row0 = blockIdx.y * MT, col0 = blockIdx.x * 128;

    uint32_t smBase = (uint32_t)__cvta_generic_to_shared(smu);
    uint32_t a_off = ((uint32_t)(wm0 + (lane & 15)) * 12 + ((lane & 16) ? 4 : 0)) * 4;
    uint32_t b_off = ((uint32_t)(wn0 + (lane & 7) + ((lane & 16) ? 8 : 0)) * 12
                      + ((lane & 8) ? 4 : 0)) * 4;

    float acc[NMI][4][4] = {};

    auto COMPUTE = [&](int buf) {
        uint32_t sb = smBase + (uint32_t)buf * STB;
        uint32_t aH = sb + a_off;
        uint32_t aL = aH + APW * 4;
        uint32_t bH = sb + BOFFW * 4 + b_off;
        uint32_t Bhf[4][2];
        ldsm4(Bhf[0][0], Bhf[0][1], Bhf[1][0], Bhf[1][1], bH);
        ldsm4(Bhf[2][0], Bhf[2][1], Bhf[3][0], Bhf[3][1], bH + 16 * 12 * 4);
        #pragma unroll
        for (int mi = 0; mi < NMI; mi++) {
            uint32_t Af[4];
            ldsm4(Af[0], Af[1], Af[2], Af[3], aH + (uint32_t)mi * 16 * 12 * 4);
            uint32_t Lf[4];
            if (ALO) ldsm4(Lf[0], Lf[1], Lf[2], Lf[3], aL + (uint32_t)mi * 16 * 12 * 4);
            #pragma unroll
            for (int ni = 0; ni < 4; ni++) {
                MMA_F16(acc[mi][ni], Af[0], Af[1], Af[2], Af[3], Bhf[ni][0], Bhf[ni][1]);
                if (ALO)
                    MMA_F16(acc[mi][ni], Lf[0], Lf[1], Lf[2], Lf[3], Bhf[ni][0], Bhf[ni][1]);
            }
        }
    };

    auto LOADNT = [&](int chunk, int buf) {
        int kws = kw0 + (chunk << 3);
        uint32_t* st = smu + buf * STW;
        if (MT == 128) {
            int r = tid >> 1, s = (tid & 1) * 4;
            cp16w(st + r * 12 + s, Ah + (size_t)(row0 + r) * ldaw + kws + s, true);
            if (ALO)
                cp16w(st + APW + r * 12 + s, Al + (size_t)(row0 + r) * ldaw + kws + s, true);
        } else {
            int r = (tid & 127) >> 1, s = (tid & 1) * 4;
            if (!ALO) {
                if (tid < 128)
                    cp16w(st + r * 12 + s, Ah + (size_t)(row0 + r) * ldaw + kws + s, true);
            } else {
                const uint32_t* srcp = (tid < 128) ? Ah : Al;
                uint32_t* dstp = st + ((tid < 128) ? 0 : APW);
                cp16w(dstp + r * 12 + s, srcp + (size_t)(row0 + r) * ldaw + kws + s, true);
            }
        }
        int rb = tid >> 1, sb2 = (tid & 1) * 4;
        bool p = (col0 + rb) < N;
        cp16w(st + BOFFW + rb * 12 + sb2, Bh + (size_t)(col0 + rb) * ldbw + kws + sb2, p);
    };

    int pre = (nk < STAGES - 1) ? nk : (STAGES - 1);
    for (int s = 0; s < pre; s++) {
        LOADNT(s, s);
        asm volatile("cp.async.commit_group;");
    }
    for (int i = 0; i < nk; i++) {
        int buf = i % STAGES;
        asm volatile("cp.async.wait_group %0;" :: "n"(STAGES - 2));
        __syncthreads();
        COMPUTE(buf);
        int nxt = i + STAGES - 1;
        if (nxt < nk) LOADNT(nxt, nxt % STAGES);
        asm volatile("cp.async.commit_group;");
    }

    // ---------------- epilogue ----------------
    #pragma unroll
    for (int mi = 0; mi < NMI; mi++) {
        #pragma unroll
        for (int rr = 0; rr < 2; rr++) {
            int r = row0 + wm0 + mi * 16 + g + rr * 8;
            #pragma unroll
            for (int ni = 0; ni < 4; ni++) {
                int c = col0 + wn0 + ni * 8 + tg * 2;
                float v0 = acc[mi][ni][rr * 2];
                float v1 = acc[mi][ni][rr * 2 + 1];
                if (EPI == 0) {
                    float* Crow = Cf + (size_t)r * ldc;
                    if (c + 1 < N) {
                        if (bias) { v0 += bias[c]; v1 += bias[c + 1]; }
                        *(float2*)&Crow[c] = make_float2(v0, v1);
                    } else if (c < N) {
                        if (bias) v0 += bias[c];
                        Crow[c] = v0;
                    }
                } else if (EPI == 1) {
                    float* Crow = Cf + (size_t)r * ldc;
                    if (bias && sk == 0) {
                        if (c < N)     v0 += bias[c];
                        if (c + 1 < N) v1 += bias[c + 1];
                    }
                    if (c < N)     atomicAdd(&Crow[c], v0);
                    if (c + 1 < N) atomicAdd(&Crow[c + 1], v1);
                } else if (EPI == 5) {
                    if (c < N) {
                        if (bias) { v0 += bias[c]; v1 += bias[c + 1]; }
                        uint32_t h = pack_hi(v0, v1);
                        Ch[(size_t)r * ldc + (c >> 1)] = h;
                        if (c >= 1024) {            // V range: side-store transposed halves
                            int d = c - 1024;
                            int b = r >> 8, s = r & 255;
                            __half* vTh = (__half*)Cl;
                            size_t base = ((size_t)(b * 8 + (d >> 6)) * 64 + (d & 63)) * 256 + s;
                            vTh[base]       = __ushort_as_half((unsigned short)(h & 0xffffu));
                            vTh[base + 256] = __ushort_as_half((unsigned short)(h >> 16));
                        }
                    }
                } else {
                    if (c < N) {
                        if (bias) { v0 += bias[c]; v1 += bias[c + 1]; }
                        if (EPI == 2) {
                            v0 = 0.5f * v0 * (1.f + erff(v0 * 0.7071067811865476f));
                            v1 = 0.5f * v1 * (1.f + erff(v1 * 0.7071067811865476f));
                        }
                        uint32_t h, l;
                        splitpack(v0, v1, h, l);
                        size_t idx = (size_t)r * ldc + (c >> 1);
                        Ch[idx] = h;
                        if (Cl) Cl[idx] = l;
                    }
                }
            }
        }
    }
}

#define SM_B(MT, ALO) (STAGES * (((1 + (ALO)) * (MT) * 12) + 128 * 12) * 4)

// ---------------- driver ----------------
extern "C" void kernel_launch(void* const* d_in, const int* in_sizes, int n_in,
                              void* d_out, int out_size) {
    const int*   src   = (const int*)  d_in[0];
    const float* emb   = (const float*)d_in[1];
    const float* rel   = (const float*)d_in[2];
    const float* nin_s = (const float*)d_in[3];
    const float* nin_b = (const float*)d_in[4];
    const float* inW   = (const float*)d_in[5];
    const float* inB   = (const float*)d_in[6];
    const float* outW  = (const float*)d_in[7];
    const float* outB  = (const float*)d_in[8];
    const float* ln1s  = (const float*)d_in[9];
    const float* ln1b  = (const float*)d_in[10];
    const float* ln2s  = (const float*)d_in[11];
    const float* ln2b  = (const float*)d_in[12];
    const float* w1    = (const float*)d_in[13];
    const float* b1    = (const float*)d_in[14];
    const float* w2    = (const float*)d_in[15];
    const float* b2    = (const float*)d_in[16];
    const float* nfs   = (const float*)d_in[17];
    const float* nfb   = (const float*)d_in[18];
    const float* decW  = (const float*)d_in[19];
    const float* decB  = (const float*)d_in[20];
    float* out = (float*)d_out;

    float *x, *qr;
    cudaGetSymbolAddress((void**)&x,  g_x);
    cudaGetSymbolAddress((void**)&qr, g_qr);
    uint32_t *hH,*hL,*qkvH,*prH,*vT,*oH,*oL,*gH,*gL;
    uint32_t *WiH,*WoH,*W1H,*W2H,*WdH,*relH;
    cudaGetSymbolAddress((void**)&hH,   p_h_hi);   cudaGetSymbolAddress((void**)&hL,   p_h_lo);
    cudaGetSymbolAddress((void**)&qkvH, p_qkv_hi);
    cudaGetSymbolAddress((void**)&prH,  p_pr_hi);
    cudaGetSymbolAddress((void**)&vT,   p_vT);
    cudaGetSymbolAddress((void**)&oH,   p_o_hi);   cudaGetSymbolAddress((void**)&oL,   p_o_lo);
    cudaGetSymbolAddress((void**)&gH,   p_g_hi);   cudaGetSymbolAddress((void**)&gL,   p_g_lo);
    cudaGetSymbolAddress((void**)&WiH,  p_Wi_hi);
    cudaGetSymbolAddress((void**)&WoH,  p_Wo_hi);
    cudaGetSymbolAddress((void**)&W1H,  p_W1_hi);
    cudaGetSymbolAddress((void**)&W2H,  p_W2_hi);
    cudaGetSymbolAddress((void**)&WdH,  p_Wd_hi);
    cudaGetSymbolAddress((void**)&relH, p_rel_hi);

    cudaFuncSetAttribute(bgemm<5,1,1,64>,  cudaFuncAttributeMaxDynamicSharedMemorySize, SM_B(64,1));
    cudaFuncSetAttribute(bgemm<0,1,0,128>, cudaFuncAttributeMaxDynamicSharedMemorySize, SM_B(128,0));
    cudaFuncSetAttribute(bgemm<3,1,0,64>,  cudaFuncAttributeMaxDynamicSharedMemorySize, SM_B(64,0));
    cudaFuncSetAttribute(bgemm<1,2,1,64>,  cudaFuncAttributeMaxDynamicSharedMemorySize, SM_B(64,1));
    cudaFuncSetAttribute(bgemm<2,1,1,64>,  cudaFuncAttributeMaxDynamicSharedMemorySize, SM_B(64,1));
    cudaFuncSetAttribute(attn_k,           cudaFuncAttributeMaxDynamicSharedMemorySize, ATT_SMEM);

    // single merged weight split: inW, outW, w1, w2, decW, rel
    {
        int n0 = 4*1536*256, n1 = 4*512*256, n2 = 4*2048*256,
            n3 = 4*512*1024, n4 = V_DIM*256, n5 = 511*256;
        long long total = (long long)n0 + n1 + n2 + n3 + n4 + n5;
        int blocks = (int)((total / 8 + 255) / 256);
        split_all_k<<<blocks, 256>>>(inW, outW, w1, w2, decW, rel,
                                     WiH, WoH, W1H, W2H, WdH, relH,
                                     n0, n1, n2, n3, n4, n5);
    }

    embed_ln_k<<<N_ROWS, 256>>>(src, emb, nin_s, nin_b, x);

    for (int l = 0; l < 4; l++) {
        const uint32_t* WiHl = WiH + (size_t)l * 1536 * 256;
        const uint32_t* WoHl = WoH + (size_t)l * 512 * 256;
        const uint32_t* W1Hl = W1H + (size_t)l * 2048 * 256;
        const uint32_t* W2Hl = W2H + (size_t)l * 512 * 1024;
        const float* inB_l  = inB  + (size_t)l * QKV_DIM;
        const float* outB_l = outB + (size_t)l * E_DIM;
        const float* b1_l   = b1   + (size_t)l * FF_DIM;
        const float* b2_l   = b2   + (size_t)l * E_DIM;

        layernorm_split_k<<<N_ROWS, 256>>>(x, ln1s + l*E_DIM, ln1b + l*E_DIM, hH, hL);

        // qkv hi plane = h @ inW^T + inB  (2-term A) + fused V-transpose side store
        bgemm<5,1,1,64><<<dim3(12, 16, 1), 256, SM_B(64,1)>>>(hH, hL, WiHl, inB_l,
            (float*)0, qkvH, vT, N_ROWS, QKV_DIM, 256, 256, 256, 768,
            0,0, 0,0, 0,0);

        // qr f32 = Q @ rel^T  (1-term, 128x128 tiles)
        bgemm<0,1,0,128><<<dim3(4, 2, N_BH), 256, SM_B(128,0)>>>(qkvH, (const uint32_t*)0, relH,
            (const float*)0, qr, (uint32_t*)0, (uint32_t*)0,
            S_LEN, 511, 32, 768, 256, 512,
            256*768, 32, 0, 32, 8*131072, 131072);

        // fused scores + bias + mask + softmax
        attn_k<<<dim3(2, N_BH), 256, ATT_SMEM>>>(qkvH, qr, prH);

        // o planes = probs @ V^T  (1-term, 64x128 tiles)
        bgemm<3,1,0,64><<<dim3(1, 4, N_BH), 256, SM_B(64,0)>>>(prH, (const uint32_t*)0, vT,
            (const float*)0, (float*)0, oH, oL,
            S_LEN, 64, 128, 128, 128, 256,
            8*32768, 32768, 8*8192, 8192, 65536, 32);

        // x += o @ outW^T + outB   (splitK 2, 2-term A)
        bgemm<1,2,1,64><<<dim3(4, 16, 2), 256, SM_B(64,1)>>>(oH, oL, WoHl, outB_l,
            x, (uint32_t*)0, (uint32_t*)0, N_ROWS, E_DIM, 256, 256, 256, E_DIM,
            0,0, 0,0, 0,0);

        layernorm_split_k<<<N_ROWS, 256>>>(x, ln2s + l*E_DIM, ln2b + l*E_DIM, hH, hL);

        // g planes = gelu(h @ w1^T + b1)  (2-term A)
        bgemm<2,1,1,64><<<dim3(16, 16, 1), 256, SM_B(64,1)>>>(hH, hL, W1Hl, b1_l,
            (float*)0, gH, gL, N_ROWS, FF_DIM, 256, 256, 256, 1024,
            0,0, 0,0, 0,0);

        // x += g @ w2^T + b2   (splitK 2, 2-term A)
        bgemm<1,2,1,64><<<dim3(4, 16, 2), 256, SM_B(64,1)>>>(gH, gL, W2Hl, b2_l,
            x, (uint32_t*)0, (uint32_t*)0, N_ROWS, E_DIM, 1024, 1024, 1024, E_DIM,
            0,0, 0,0, 0,0);
    }

    layernorm_split_k<<<N_ROWS, 256>>>(x, nfs, nfb, hH, hL);

    // out f32 = h @ dec_w^T + dec_b   (1-term, 128x128 tiles)
    bgemm<0,1,0,128><<<dim3(250, 8, 1), 256, SM_B(128,0)>>>(hH, (const uint32_t*)0, WdH, decB,
        out, (uint32_t*)0, (uint32_t*)0, N_ROWS, V_DIM, 256, 256, 256, V_DIM,
        0,0, 0,0, 0,0);
}

// round 16
// speedup vs baseline: 1.7620x; 1.0130x over previous
#include <cuda_runtime.h>
#include <cuda_fp16.h>
#include <math.h>
#include <stdint.h>

// ---------------- problem constants ----------------
#define N_ROWS   1024
#define E_DIM    512
#define QKV_DIM  1536
#define FF_DIM   2048
#define V_DIM    32000
#define N_BH     32
#define S_LEN    256

// ---------------- scratch ----------------
__device__ float g_x [N_ROWS * E_DIM];
__device__ float g_qr[N_BH * S_LEN * 512];

// ---------------- packed fp16 planes (word = 2 consecutive-k halves) ----------------
__device__ uint32_t p_h_hi  [N_ROWS * 256],  p_h_lo  [N_ROWS * 256];
__device__ uint32_t p_qkv_hi[N_ROWS * 768];
__device__ uint32_t p_pr_hi [N_BH * S_LEN * 128];
__device__ uint32_t p_vT    [N_BH * 64 * 128];
__device__ uint32_t p_o_hi  [N_ROWS * 256],  p_o_lo  [N_ROWS * 256];
__device__ uint32_t p_g_hi  [N_ROWS * 1024], p_g_lo  [N_ROWS * 1024];
__device__ uint32_t p_Wi_hi [4 * 1536 * 256];
__device__ uint32_t p_Wo_hi [4 * 512 * 256];
__device__ uint32_t p_W1_hi [4 * 2048 * 256];
__device__ uint32_t p_W2_hi [4 * 512 * 1024];
__device__ uint32_t p_Wd_hi [V_DIM * 256];
__device__ uint32_t p_rel_hi[511 * 256];

// ---------------- helpers ----------------
__device__ __forceinline__ void splitpack(float v0, float v1, uint32_t& hi, uint32_t& lo) {
    __half h0 = __float2half_rn(v0);
    __half h1 = __float2half_rn(v1);
    float r0 = v0 - __half2float(h0);
    float r1 = v1 - __half2float(h1);
    __half l0 = __float2half_rn(r0);
    __half l1 = __float2half_rn(r1);
    hi = (uint32_t)__half_as_ushort(h0) | ((uint32_t)__half_as_ushort(h1) << 16);
    lo = (uint32_t)__half_as_ushort(l0) | ((uint32_t)__half_as_ushort(l1) << 16);
}
__device__ __forceinline__ uint32_t pack_hi(float v0, float v1) {
    __half h0 = __float2half_rn(v0);
    __half h1 = __float2half_rn(v1);
    return (uint32_t)__half_as_ushort(h0) | ((uint32_t)__half_as_ushort(h1) << 16);
}

__device__ __forceinline__ float warpSum(float v) {
    #pragma unroll
    for (int o = 16; o; o >>= 1) v += __shfl_xor_sync(0xffffffffu, v, o);
    return v;
}
__device__ __forceinline__ float blockSum(float v) {
    __shared__ float sm[8];
    int lane = threadIdx.x & 31, w = threadIdx.x >> 5;
    v = warpSum(v);
    __syncthreads();
    if (lane == 0) sm[w] = v;
    __syncthreads();
    float r = 0.f;
    #pragma unroll
    for (int i = 0; i < 8; i++) r += sm[i];
    return r;
}

// ---------------- merged f32 -> fp16 hi-plane split (6 segments, one launch) ----------
__global__ void split_all_k(const float* __restrict__ s0, const float* __restrict__ s1,
                            const float* __restrict__ s2, const float* __restrict__ s3,
                            const float* __restrict__ s4, const float* __restrict__ s5,
                            uint32_t* __restrict__ d0, uint32_t* __restrict__ d1,
                            uint32_t* __restrict__ d2, uint32_t* __restrict__ d3,
                            uint32_t* __restrict__ d4, uint32_t* __restrict__ d5,
                            int n0, int n1, int n2, int n3, int n4, int n5) {
    long long w = ((long long)blockIdx.x * 256 + threadIdx.x) * 8;
    const float* src; uint32_t* dst; long long loc = w;
    if (loc < n0)            { src = s0; dst = d0; }
    else { loc -= n0; if (loc < n1) { src = s1; dst = d1; }
    else { loc -= n1; if (loc < n2) { src = s2; dst = d2; }
    else { loc -= n2; if (loc < n3) { src = s3; dst = d3; }
    else { loc -= n3; if (loc < n4) { src = s4; dst = d4; }
    else { loc -= n4; if (loc < n5) { src = s5; dst = d5; }
    else return; }}}}}
    #pragma unroll
    for (int j = 0; j < 2; j++) {
        float4 a = *(const float4*)(src + 2 * (loc + j * 4));
        float4 b = *(const float4*)(src + 2 * (loc + j * 4) + 4);
        uint4 o;
        o.x = pack_hi(a.x, a.y); o.y = pack_hi(a.z, a.w);
        o.z = pack_hi(b.x, b.y); o.w = pack_hi(b.z, b.w);
        *(uint4*)(dst + loc + j * 4) = o;
    }
}

// ---------------- embed + input layernorm -> f32 x ----------------
__global__ void embed_ln_k(const int* __restrict__ src, const float* __restrict__ emb,
                           const float* __restrict__ s, const float* __restrict__ b,
                           float* __restrict__ out) {
    int row = blockIdx.x, t = threadIdx.x;
    int tok = src[row];
    const float SC = 22.62741699796952f;
    float v0 = emb[(size_t)tok * E_DIM + t]       * SC;
    float v1 = emb[(size_t)tok * E_DIM + t + 256] * SC;
    float mean = blockSum(v0 + v1) * (1.f / E_DIM);
    float d0 = v0 - mean, d1 = v1 - mean;
    float var = blockSum(d0 * d0 + d1 * d1) * (1.f / E_DIM);
    float r = rsqrtf(var + 1e-5f);
    out[(size_t)row * E_DIM + t]       = d0 * r * s[t]       + b[t];
    out[(size_t)row * E_DIM + t + 256] = d1 * r * s[t + 256] + b[t + 256];
}

// ---------------- layernorm f32 -> split planes ----------------
__global__ void layernorm_split_k(const float* __restrict__ in, const float* __restrict__ s,
                                  const float* __restrict__ b,
                                  uint32_t* __restrict__ oh, uint32_t* __restrict__ ol) {
    int row = blockIdx.x, t = threadIdx.x;
    float2 v = *(const float2*)(in + (size_t)row * E_DIM + 2 * t);
    float mean = blockSum(v.x + v.y) * (1.f / E_DIM);
    float d0 = v.x - mean, d1 = v.y - mean;
    float var = blockSum(d0 * d0 + d1 * d1) * (1.f / E_DIM);
    float r = rsqrtf(var + 1e-5f);
    float y0 = d0 * r * s[2 * t]     + b[2 * t];
    float y1 = d1 * r * s[2 * t + 1] + b[2 * t + 1];
    uint32_t h, l;
    splitpack(y0, y1, h, l);
    oh[(size_t)row * 256 + t] = h;
    ol[(size_t)row * 256 + t] = l;
}

// ---------------- mma / ldmatrix / cp.async primitives ----------------
#define MMA_F16(C, A0, A1, A2, A3, B0, B1)                                      \
    asm volatile("mma.sync.aligned.m16n8k16.row.col.f32.f16.f16.f32 "           \
                 "{%0,%1,%2,%3},{%4,%5,%6,%7},{%8,%9},{%0,%1,%2,%3};"           \
                 : "+f"(C[0]), "+f"(C[1]), "+f"(C[2]), "+f"(C[3])               \
                 : "r"(A0), "r"(A1), "r"(A2), "r"(A3), "r"(B0), "r"(B1))

__device__ __forceinline__ void ldsm4(uint32_t& r0, uint32_t& r1, uint32_t& r2, uint32_t& r3,
                                      uint32_t addr) {
    asm volatile("ldmatrix.sync.aligned.m8n8.x4.shared.b16 {%0,%1,%2,%3}, [%4];"
                 : "=r"(r0), "=r"(r1), "=r"(r2), "=r"(r3) : "r"(addr));
}

__device__ __forceinline__ void cp16w(uint32_t* dst, const uint32_t* src, bool pred) {
    uint32_t d = (uint32_t)__cvta_generic_to_shared(dst);
    int sz = pred ? 16 : 0;
    asm volatile("cp.async.cg.shared.global [%0], [%1], 16, %2;"
                 :: "r"(d), "l"(src), "r"(sz));
}

// ---------------- fused attention: scores + rel-bias gather + mask + softmax ----------
#define ATT_STRIDE 36
#define ATT_SMEM ((128 * ATT_STRIDE + 256 * ATT_STRIDE) * 4 + 128 * 4 * 4)
__global__ __launch_bounds__(256, 1)
void attn_k(const uint32_t* __restrict__ qkvH, const float* __restrict__ qr,
            uint32_t* __restrict__ ph) {
    extern __shared__ uint32_t asm_[];
    uint32_t* qs = asm_;
    uint32_t* ks = asm_ + 128 * ATT_STRIDE;
    float* red = (float*)(ks + 256 * ATT_STRIDE);

    int tile = blockIdx.x;
    int bh = blockIdx.y;
    int zb = bh >> 3, zh = bh & 7;
    const uint32_t* Q = qkvH + (size_t)zb * (256 * 768) + zh * 32;
    const uint32_t* K = Q + 256;
    const float* qrb = qr + (size_t)bh * (256 * 512);
    int l0 = tile * 128;

    int tid = threadIdx.x, lane = tid & 31, wid = tid >> 5;

    {
        int lrow = tid >> 1, seg = (tid & 1) * 16;
        const uint32_t* qrow = Q + (size_t)(l0 + lrow) * 768 + seg;
        uint32_t* qd = qs + lrow * ATT_STRIDE + seg;
        #pragma unroll
        for (int j = 0; j < 4; j++) cp16w(qd + j * 4, qrow + j * 4, true);
        const uint32_t* krow = K + (size_t)tid * 768;
        uint32_t* kd = ks + tid * ATT_STRIDE;
        #pragma unroll
        for (int j = 0; j < 8; j++) cp16w(kd + j * 4, krow + j * 4, true);
    }
    asm volatile("cp.async.commit_group;");
    asm volatile("cp.async.wait_group 0;");
    __syncthreads();

    int warpM = wid >> 2, warpN = wid & 3;
    int wm0 = warpM * 64, wn0 = warpN * 64;
    int g = lane >> 2, tg = lane & 3;
    uint32_t smQ = (uint32_t)__cvta_generic_to_shared(qs);
    uint32_t smK = (uint32_t)__cvta_generic_to_shared(ks);
    uint32_t a_base = smQ + ((uint32_t)(wm0 + (lane & 15)) * ATT_STRIDE + ((lane & 16) ? 4 : 0)) * 4;
    uint32_t b_base = smK + ((uint32_t)(wn0 + (lane & 7) + ((lane & 16) ? 8 : 0)) * ATT_STRIDE
                             + ((lane & 8) ? 4 : 0)) * 4;

    float acc[4][8][4] = {};
    #pragma unroll
    for (int c = 0; c < 4; c++) {
        uint32_t koff = (uint32_t)c * 32;
        uint32_t Bf[8][2];
        #pragma unroll
        for (int t = 0; t < 4; t++)
            ldsm4(Bf[2 * t][0], Bf[2 * t][1], Bf[2 * t + 1][0], Bf[2 * t + 1][1],
                  b_base + koff + (uint32_t)t * 16 * ATT_STRIDE * 4);
        #pragma unroll
        for (int mi = 0; mi < 4; mi++) {
            uint32_t Af[4];
            ldsm4(Af[0], Af[1], Af[2], Af[3],
                  a_base + koff + (uint32_t)mi * 16 * ATT_STRIDE * 4);
            #pragma unroll
            for (int ni = 0; ni < 8; ni++)
                MMA_F16(acc[mi][ni], Af[0], Af[1], Af[2], Af[3], Bf[ni][0], Bf[ni][1]);
        }
    }
    __syncthreads();

    #pragma unroll
    for (int mi = 0; mi < 4; mi++) {
        #pragma unroll
        for (int rr = 0; rr < 2; rr++) {
            int lrow = wm0 + mi * 16 + g + rr * 8;
            int lglob = l0 + lrow;
            const float* qrl = qrb + (size_t)lglob * 512 + (255 - lglob);
            #pragma unroll
            for (int ni = 0; ni < 8; ni++) {
                int m = wn0 + ni * 8 + tg * 2;
                float b0 = qrl[m], b1 = qrl[m + 1];
                acc[mi][ni][rr * 2]     = acc[mi][ni][rr * 2]     * 0.125f + b0 + ((m     > lglob) ? 1.f : 0.f);
                acc[mi][ni][rr * 2 + 1] = acc[mi][ni][rr * 2 + 1] * 0.125f + b1 + ((m + 1 > lglob) ? 1.f : 0.f);
            }
        }
    }

    float rmax[4][2];
    #pragma unroll
    for (int mi = 0; mi < 4; mi++)
        #pragma unroll
        for (int rr = 0; rr < 2; rr++) {
            float mx = -3.4e38f;
            #pragma unroll
            for (int ni = 0; ni < 8; ni++) {
                mx = fmaxf(mx, acc[mi][ni][rr * 2]);
                mx = fmaxf(mx, acc[mi][ni][rr * 2 + 1]);
            }
            mx = fmaxf(mx, __shfl_xor_sync(0xffffffffu, mx, 1));
            mx = fmaxf(mx, __shfl_xor_sync(0xffffffffu, mx, 2));
            int lrow = wm0 + mi * 16 + g + rr * 8;
            if (tg == 0) red[lrow * 4 + warpN] = mx;
            rmax[mi][rr] = 0.f;
        }
    __syncthreads();
    #pragma unroll
    for (int mi = 0; mi < 4; mi++)
        #pragma unroll
        for (int rr = 0; rr < 2; rr++) {
            int lrow = wm0 + mi * 16 + g + rr * 8;
            rmax[mi][rr] = fmaxf(fmaxf(red[lrow * 4 + 0], red[lrow * 4 + 1]),
                                 fmaxf(red[lrow * 4 + 2], red[lrow * 4 + 3]));
        }
    __syncthreads();

    float rsum[4][2];
    #pragma unroll
    for (int mi = 0; mi < 4; mi++)
        #pragma unroll
        for (int rr = 0; rr < 2; rr++) {
            float s = 0.f;
            #pragma unroll
            for (int ni = 0; ni < 8; ni++) {
                float e0 = expf(acc[mi][ni][rr * 2]     - rmax[mi][rr]);
                float e1 = expf(acc[mi][ni][rr * 2 + 1] - rmax[mi][rr]);
                acc[mi][ni][rr * 2] = e0; acc[mi][ni][rr * 2 + 1] = e1;
                s += e0 + e1;
            }
            s += __shfl_xor_sync(0xffffffffu, s, 1);
            s += __shfl_xor_sync(0xffffffffu, s, 2);
            int lrow = wm0 + mi * 16 + g + rr * 8;
            if (tg == 0) red[lrow * 4 + warpN] = s;
            rsum[mi][rr] = 0.f;
        }
    __syncthreads();
    #pragma unroll
    for (int mi = 0; mi < 4; mi++)
        #pragma unroll
        for (int rr = 0; rr < 2; rr++) {
            int lrow = wm0 + mi * 16 + g + rr * 8;
            rsum[mi][rr] = red[lrow * 4 + 0] + red[lrow * 4 + 1]
                         + red[lrow * 4 + 2] + red[lrow * 4 + 3];
        }

    uint32_t* pb = ph + (size_t)bh * (S_LEN * 128);
    #pragma unroll
    for (int mi = 0; mi < 4; mi++)
        #pragma unroll
        for (int rr = 0; rr < 2; rr++) {
            int lglob = l0 + wm0 + mi * 16 + g + rr * 8;
            float inv = 1.f / rsum[mi][rr];
            #pragma unroll
            for (int ni = 0; ni < 8; ni++) {
                float p0 = acc[mi][ni][rr * 2] * inv;
                float p1 = acc[mi][ni][rr * 2 + 1] * inv;
                pb[(size_t)lglob * 128 + (wn0 >> 1) + ni * 4 + tg] = pack_hi(p0, p1);
            }
        }
}

#define STAGES 5

// ---------------- fp16 GEMM, MT x 128 CTA tile, chunk k=16 (8 words) ----------------
// ALO: A hi+lo (2-term) vs hi only. B: pre-split hi plane.
// EPI: 0 f32 out (+bias); 1 f32 splitK atomicAdd (+bias at sk==0);
//      2 planes out bias+GELU; 3 planes out (+bias, Cl optional);
//      5 planes-hi out (+bias) with fused V-transpose side store (Cl = vT half buffer).
// MT==64 kernels target 3 CTAs/SM (latency-bound); MT==128 keep 2.
template<int EPI, int NSPLIT, int ALO, int MT>
__global__ __launch_bounds__(256, MT == 64 ? 3 : 2)
void bgemm(const uint32_t* __restrict__ Ah, const uint32_t* __restrict__ Al,
           const uint32_t* __restrict__ Bh,
           const float* __restrict__ bias,
           float* __restrict__ Cf, uint32_t* __restrict__ Ch, uint32_t* __restrict__ Cl,
           int M, int N, int Kw, int ldaw, int ldbw, int ldc,
           int aOffB, int aOffH, int bOffB, int bOffH, int cOffB, int cOffH) {
    extern __shared__ uint32_t smu[];
    constexpr int APW   = MT * 12;
    constexpr int BPW   = 128 * 12;
    constexpr int BOFFW = (1 + ALO) * APW;
    constexpr int STW   = BOFFW + BPW;
    constexpr int STB   = STW * 4;
    constexpr int WM    = MT / 2;
    constexpr int NMI   = MT / 32;

    int z = blockIdx.z;
    int sk = z % NSPLIT;
    int zz = z / NSPLIT;
    int zb = zz >> 3, zh = zz & 7;
    Ah += (size_t)zb * aOffB + (size_t)zh * aOffH;
    if (ALO) Al += (size_t)zb * aOffB + (size_t)zh * aOffH;
    Bh += (size_t)zb * bOffB + (size_t)zh * bOffH;
    size_t cAdj = (size_t)zb * cOffB + (size_t)zh * cOffH;
    if (EPI <= 1) Cf += cAdj;
    else if (EPI != 5) { Ch += cAdj; if (Cl) Cl += cAdj; }
    else Ch += cAdj;   // EPI==5: Cl is the vT half buffer (no batch adjust)

    int kLenW = Kw / NSPLIT;
    int kw0   = sk * kLenW;
    int nk    = kLenW >> 3;

    int tid  = threadIdx.x;
    int lane = tid & 31, wid = tid >> 5;
    int wm0 = (wid >> 2) * WM;
    int wn0 = (wid & 3) * 32;
    int g   = lane >> 2;
    int tg  = lane & 3;
    int row0 = blockIdx.y * MT, col0 = blockIdx.x * 128;

    uint32_t smBase = (uint32_t)__cvta_generic_to_shared(smu);
    uint32_t a_off = ((uint32_t)(wm0 + (lane & 15)) * 12 + ((lane & 16) ? 4 : 0)) * 4;
    uint32_t b_off = ((uint32_t)(wn0 + (lane & 7) + ((lane & 16) ? 8 : 0)) * 12
                      + ((lane & 8) ? 4 : 0)) * 4;

    float acc[NMI][4][4] = {};

    auto COMPUTE = [&](int buf) {
        uint32_t sb = smBase + (uint32_t)buf * STB;
        uint32_t aH = sb + a_off;
        uint32_t aL = aH + APW * 4;
        uint32_t bH = sb + BOFFW * 4 + b_off;
        uint32_t Bhf[4][2];
        ldsm4(Bhf[0][0], Bhf[0][1], Bhf[1][0], Bhf[1][1], bH);
        ldsm4(Bhf[2][0], Bhf[2][1], Bhf[3][0], Bhf[3][1], bH + 16 * 12 * 4);
        #pragma unroll
        for (int mi = 0; mi < NMI; mi++) {
            uint32_t Af[4];
            ldsm4(Af[0], Af[1], Af[2], Af[3], aH + (uint32_t)mi * 16 * 12 * 4);
            uint32_t Lf[4];
            if (ALO) ldsm4(Lf[0], Lf[1], Lf[2], Lf[3], aL + (uint32_t)mi * 16 * 12 * 4);
            #pragma unroll
            for (int ni = 0; ni < 4; ni++) {
                MMA_F16(acc[mi][ni], Af[0], Af[1], Af[2], Af[3], Bhf[ni][0], Bhf[ni][1]);
                if (ALO)
                    MMA_F16(acc[mi][ni], Lf[0], Lf[1], Lf[2], Lf[3], Bhf[ni][0], Bhf[ni][1]);
            }
        }
    };

    auto LOADNT = [&](int chunk, int buf) {
        int kws = kw0 + (chunk << 3);
        uint32_t* st = smu + buf * STW;
        if (MT == 128) {
            int r = tid >> 1, s = (tid & 1) * 4;
            cp16w(st + r * 12 + s, Ah + (size_t)(row0 + r) * ldaw + kws + s, true);
            if (ALO)
                cp16w(st + APW + r * 12 + s, Al + (size_t)(row0 + r) * ldaw + kws + s, true);
        } else {
            int r = (tid & 127) >> 1, s = (tid & 1) * 4;
            if (!ALO) {
                if (tid < 128)
                    cp16w(st + r * 12 + s, Ah + (size_t)(row0 + r) * ldaw + kws + s, true);
            } else {
                const uint32_t* srcp = (tid < 128) ? Ah : Al;
                uint32_t* dstp = st + ((tid < 128) ? 0 : APW);
                cp16w(dstp + r * 12 + s, srcp + (size_t)(row0 + r) * ldaw + kws + s, true);
            }
        }
        int rb = tid >> 1, sb2 = (tid & 1) * 4;
        bool p = (col0 + rb) < N;
        cp16w(st + BOFFW + rb * 12 + sb2, Bh + (size_t)(col0 + rb) * ldbw + kws + sb2, p);
    };

    int pre = (nk < STAGES - 1) ? nk : (STAGES - 1);
    for (int s = 0; s < pre; s++) {
        LOADNT(s, s);
        asm volatile("cp.async.commit_group;");
    }
    for (int i = 0; i < nk; i++) {
        int buf = i % STAGES;
        asm volatile("cp.async.wait_group %0;" :: "n"(STAGES - 2));
        __syncthreads();
        COMPUTE(buf);
        int nxt = i + STAGES - 1;
        if (nxt < nk) LOADNT(nxt, nxt % STAGES);
        asm volatile("cp.async.commit_group;");
    }

    // ---------------- epilogue ----------------
    #pragma unroll
    for (int mi = 0; mi < NMI; mi++) {
        #pragma unroll
        for (int rr = 0; rr < 2; rr++) {
            int r = row0 + wm0 + mi * 16 + g + rr * 8;
            #pragma unroll
            for (int ni = 0; ni < 4; ni++) {
                int c = col0 + wn0 + ni * 8 + tg * 2;
                float v0 = acc[mi][ni][rr * 2];
                float v1 = acc[mi][ni][rr * 2 + 1];
                if (EPI == 0) {
                    float* Crow = Cf + (size_t)r * ldc;
                    if (c + 1 < N) {
                        if (bias) { v0 += bias[c]; v1 += bias[c + 1]; }
                        *(float2*)&Crow[c] = make_float2(v0, v1);
                    } else if (c < N) {
                        if (bias) v0 += bias[c];
                        Crow[c] = v0;
                    }
                } else if (EPI == 1) {
                    float* Crow = Cf + (size_t)r * ldc;
                    if (bias && sk == 0) {
                        if (c < N)     v0 += bias[c];
                        if (c + 1 < N) v1 += bias[c + 1];
                    }
                    if (c < N)     atomicAdd(&Crow[c], v0);
                    if (c + 1 < N) atomicAdd(&Crow[c + 1], v1);
                } else if (EPI == 5) {
                    if (c < N) {
                        if (bias) { v0 += bias[c]; v1 += bias[c + 1]; }
                        uint32_t h = pack_hi(v0, v1);
                        Ch[(size_t)r * ldc + (c >> 1)] = h;
                        if (c >= 1024) {            // V range: side-store transposed halves
                            int d = c - 1024;
                            int b = r >> 8, s = r & 255;
                            __half* vTh = (__half*)Cl;
                            size_t base = ((size_t)(b * 8 + (d >> 6)) * 64 + (d & 63)) * 256 + s;
                            vTh[base]       = __ushort_as_half((unsigned short)(h & 0xffffu));
                            vTh[base + 256] = __ushort_as_half((unsigned short)(h >> 16));
                        }
                    }
                } else {
                    if (c < N) {
                        if (bias) { v0 += bias[c]; v1 += bias[c + 1]; }
                        if (EPI == 2) {
                            v0 = 0.5f * v0 * (1.f + erff(v0 * 0.7071067811865476f));
                            v1 = 0.5f * v1 * (1.f + erff(v1 * 0.7071067811865476f));
                        }
                        uint32_t h, l;
                        splitpack(v0, v1, h, l);
                        size_t idx = (size_t)r * ldc + (c >> 1);
                        Ch[idx] = h;
                        if (Cl) Cl[idx] = l;
                    }
                }
            }
        }
    }
}

#define SM_B(MT, ALO) (STAGES * (((1 + (ALO)) * (MT) * 12) + 128 * 12) * 4)

// ---------------- driver ----------------
extern "C" void kernel_launch(void* const* d_in, const int* in_sizes, int n_in,
                              void* d_out, int out_size) {
    const int*   src   = (const int*)  d_in[0];
    const float* emb   = (const float*)d_in[1];
    const float* rel   = (const float*)d_in[2];
    const float* nin_s = (const float*)d_in[3];
    const float* nin_b = (const float*)d_in[4];
    const float* inW   = (const float*)d_in[5];
    const float* inB   = (const float*)d_in[6];
    const float* outW  = (const float*)d_in[7];
    const float* outB  = (const float*)d_in[8];
    const float* ln1s  = (const float*)d_in[9];
    const float* ln1b  = (const float*)d_in[10];
    const float* ln2s  = (const float*)d_in[11];
    const float* ln2b  = (const float*)d_in[12];
    const float* w1    = (const float*)d_in[13];
    const float* b1    = (const float*)d_in[14];
    const float* w2    = (const float*)d_in[15];
    const float* b2    = (const float*)d_in[16];
    const float* nfs   = (const float*)d_in[17];
    const float* nfb   = (const float*)d_in[18];
    const float* decW  = (const float*)d_in[19];
    const float* decB  = (const float*)d_in[20];
    float* out = (float*)d_out;

    float *x, *qr;
    cudaGetSymbolAddress((void**)&x,  g_x);
    cudaGetSymbolAddress((void**)&qr, g_qr);
    uint32_t *hH,*hL,*qkvH,*prH,*vT,*oH,*oL,*gH,*gL;
    uint32_t *WiH,*WoH,*W1H,*W2H,*WdH,*relH;
    cudaGetSymbolAddress((void**)&hH,   p_h_hi);   cudaGetSymbolAddress((void**)&hL,   p_h_lo);
    cudaGetSymbolAddress((void**)&qkvH, p_qkv_hi);
    cudaGetSymbolAddress((void**)&prH,  p_pr_hi);
    cudaGetSymbolAddress((void**)&vT,   p_vT);
    cudaGetSymbolAddress((void**)&oH,   p_o_hi);   cudaGetSymbolAddress((void**)&oL,   p_o_lo);
    cudaGetSymbolAddress((void**)&gH,   p_g_hi);   cudaGetSymbolAddress((void**)&gL,   p_g_lo);
    cudaGetSymbolAddress((void**)&WiH,  p_Wi_hi);
    cudaGetSymbolAddress((void**)&WoH,  p_Wo_hi);
    cudaGetSymbolAddress((void**)&W1H,  p_W1_hi);
    cudaGetSymbolAddress((void**)&W2H,  p_W2_hi);
    cudaGetSymbolAddress((void**)&WdH,  p_Wd_hi);
    cudaGetSymbolAddress((void**)&relH, p_rel_hi);

    cudaFuncSetAttribute(bgemm<5,1,1,64>,  cudaFuncAttributeMaxDynamicSharedMemorySize, SM_B(64,1));
    cudaFuncSetAttribute(bgemm<0,1,0,128>, cudaFuncAttributeMaxDynamicSharedMemorySize, SM_B(128,0));
    cudaFuncSetAttribute(bgemm<3,1,0,64>,  cudaFuncAttributeMaxDynamicSharedMemorySize, SM_B(64,0));
    cudaFuncSetAttribute(bgemm<1,2,1,64>,  cudaFuncAttributeMaxDynamicSharedMemorySize, SM_B(64,1));
    cudaFuncSetAttribute(bgemm<2,1,1,64>,  cudaFuncAttributeMaxDynamicSharedMemorySize, SM_B(64,1));
    cudaFuncSetAttribute(attn_k,           cudaFuncAttributeMaxDynamicSharedMemorySize, ATT_SMEM);

    // single merged weight split: inW, outW, w1, w2, decW, rel
    {
        int n0 = 4*1536*256, n1 = 4*512*256, n2 = 4*2048*256,
            n3 = 4*512*1024, n4 = V_DIM*256, n5 = 511*256;
        long long total = (long long)n0 + n1 + n2 + n3 + n4 + n5;
        int blocks = (int)((total / 8 + 255) / 256);
        split_all_k<<<blocks, 256>>>(inW, outW, w1, w2, decW, rel,
                                     WiH, WoH, W1H, W2H, WdH, relH,
                                     n0, n1, n2, n3, n4, n5);
    }

    embed_ln_k<<<N_ROWS, 256>>>(src, emb, nin_s, nin_b, x);

    for (int l = 0; l < 4; l++) {
        const uint32_t* WiHl = WiH + (size_t)l * 1536 * 256;
        const uint32_t* WoHl = WoH + (size_t)l * 512 * 256;
        const uint32_t* W1Hl = W1H + (size_t)l * 2048 * 256;
        const uint32_t* W2Hl = W2H + (size_t)l * 512 * 1024;
        const float* inB_l  = inB  + (size_t)l * QKV_DIM;
        const float* outB_l = outB + (size_t)l * E_DIM;
        const float* b1_l   = b1   + (size_t)l * FF_DIM;
        const float* b2_l   = b2   + (size_t)l * E_DIM;

        layernorm_split_k<<<N_ROWS, 256>>>(x, ln1s + l*E_DIM, ln1b + l*E_DIM, hH, hL);

        // qkv hi plane = h @ inW^T + inB  (2-term A) + fused V-transpose side store
        bgemm<5,1,1,64><<<dim3(12, 16, 1), 256, SM_B(64,1)>>>(hH, hL, WiHl, inB_l,
            (float*)0, qkvH, vT, N_ROWS, QKV_DIM, 256, 256, 256, 768,
            0,0, 0,0, 0,0);

        // qr f32 = Q @ rel^T  (1-term, 128x128 tiles)
        bgemm<0,1,0,128><<<dim3(4, 2, N_BH), 256, SM_B(128,0)>>>(qkvH, (const uint32_t*)0, relH,
            (const float*)0, qr, (uint32_t*)0, (uint32_t*)0,
            S_LEN, 511, 32, 768, 256, 512,
            256*768, 32, 0, 32, 8*131072, 131072);

        // fused scores + bias + mask + softmax
        attn_k<<<dim3(2, N_BH), 256, ATT_SMEM>>>(qkvH, qr, prH);

        // o planes = probs @ V^T  (1-term, 64x128 tiles)
        bgemm<3,1,0,64><<<dim3(1, 4, N_BH), 256, SM_B(64,0)>>>(prH, (const uint32_t*)0, vT,
            (const float*)0, (float*)0, oH, oL,
            S_LEN, 64, 128, 128, 128, 256,
            8*32768, 32768, 8*8192, 8192, 65536, 32);

        // x += o @ outW^T + outB   (splitK 2, 2-term A)
        bgemm<1,2,1,64><<<dim3(4, 16, 2), 256, SM_B(64,1)>>>(oH, oL, WoHl, outB_l,
            x, (uint32_t*)0, (uint32_t*)0, N_ROWS, E_DIM, 256, 256, 256, E_DIM,
            0,0, 0,0, 0,0);

        layernorm_split_k<<<N_ROWS, 256>>>(x, ln2s + l*E_DIM, ln2b + l*E_DIM, hH, hL);

        // g planes = gelu(h @ w1^T + b1)  (2-term A)
        bgemm<2,1,1,64><<<dim3(16, 16, 1), 256, SM_B(64,1)>>>(hH, hL, W1Hl, b1_l,
            (float*)0, gH, gL, N_ROWS, FF_DIM, 256, 256, 256, 1024,
            0,0, 0,0, 0,0);

        // x += g @ w2^T + b2   (splitK 2, 2-term A)
        bgemm<1,2,1,64><<<dim3(4, 16, 2), 256, SM_B(64,1)>>>(gH, gL, W2Hl, b2_l,
            x, (uint32_t*)0, (uint32_t*)0, N_ROWS, E_DIM, 1024, 1024, 1024, E_DIM,
            0,0, 0,0, 0,0);
    }

    layernorm_split_k<<<N_ROWS, 256>>>(x, nfs, nfb, hH, hL);

    // out f32 = h @ dec_w^T + dec_b   (1-term, 128x128 tiles)
    bgemm<0,1,0,128><<<dim3(250, 8, 1), 256, SM_B(128,0)>>>(hH, (const uint32_t*)0, WdH, decB,
        out, (uint32_t*)0, (uint32_t*)0, N_ROWS, V_DIM, 256, 256, 256, V_DIM,
        0,0, 0,0, 0,0);
}

// round 17
// speedup vs baseline: 1.8133x; 1.0291x over previous
#include <cuda_runtime.h>
#include <cuda_fp16.h>
#include <math.h>
#include <stdint.h>

// ---------------- problem constants ----------------
#define N_ROWS   1024
#define E_DIM    512
#define QKV_DIM  1536
#define FF_DIM   2048
#define V_DIM    32000
#define N_BH     32
#define S_LEN    256

// ---------------- scratch ----------------
__device__ float g_x [N_ROWS * E_DIM];
__device__ float g_qr[N_BH * S_LEN * 512];

// ---------------- packed fp16 planes (word = 2 consecutive-k halves) ----------------
__device__ uint32_t p_h_hi  [N_ROWS * 256],  p_h_lo  [N_ROWS * 256];
__device__ uint32_t p_qkv_hi[N_ROWS * 768];
__device__ uint32_t p_pr_hi [N_BH * S_LEN * 128];
__device__ uint32_t p_vT    [N_BH * 64 * 128];
__device__ uint32_t p_o_hi  [N_ROWS * 256],  p_o_lo  [N_ROWS * 256];
__device__ uint32_t p_g_hi  [N_ROWS * 1024], p_g_lo  [N_ROWS * 1024];
__device__ uint32_t p_Wi_hi [4 * 1536 * 256];
__device__ uint32_t p_Wo_hi [4 * 512 * 256];
__device__ uint32_t p_W1_hi [4 * 2048 * 256];
__device__ uint32_t p_W2_hi [4 * 512 * 1024];
__device__ uint32_t p_Wd_hi [V_DIM * 256];
__device__ uint32_t p_rel_hi[511 * 256];

// ---------------- helpers ----------------
__device__ __forceinline__ void splitpack(float v0, float v1, uint32_t& hi, uint32_t& lo) {
    __half h0 = __float2half_rn(v0);
    __half h1 = __float2half_rn(v1);
    float r0 = v0 - __half2float(h0);
    float r1 = v1 - __half2float(h1);
    __half l0 = __float2half_rn(r0);
    __half l1 = __float2half_rn(r1);
    hi = (uint32_t)__half_as_ushort(h0) | ((uint32_t)__half_as_ushort(h1) << 16);
    lo = (uint32_t)__half_as_ushort(l0) | ((uint32_t)__half_as_ushort(l1) << 16);
}
__device__ __forceinline__ uint32_t pack_hi(float v0, float v1) {
    __half h0 = __float2half_rn(v0);
    __half h1 = __float2half_rn(v1);
    return (uint32_t)__half_as_ushort(h0) | ((uint32_t)__half_as_ushort(h1) << 16);
}

__device__ __forceinline__ float warpSum(float v) {
    #pragma unroll
    for (int o = 16; o; o >>= 1) v += __shfl_xor_sync(0xffffffffu, v, o);
    return v;
}
__device__ __forceinline__ float blockSum(float v) {
    __shared__ float sm[8];
    int lane = threadIdx.x & 31, w = threadIdx.x >> 5;
    v = warpSum(v);
    __syncthreads();
    if (lane == 0) sm[w] = v;
    __syncthreads();
    float r = 0.f;
    #pragma unroll
    for (int i = 0; i < 8; i++) r += sm[i];
    return r;
}

// ---------------- merged f32 -> fp16 hi-plane split (6 segments, one launch) ----------
__global__ void split_all_k(const float* __restrict__ s0, const float* __restrict__ s1,
                            const float* __restrict__ s2, const float* __restrict__ s3,
                            const float* __restrict__ s4, const float* __restrict__ s5,
                            uint32_t* __restrict__ d0, uint32_t* __restrict__ d1,
                            uint32_t* __restrict__ d2, uint32_t* __restrict__ d3,
                            uint32_t* __restrict__ d4, uint32_t* __restrict__ d5,
                            int n0, int n1, int n2, int n3, int n4, int n5) {
    long long w = ((long long)blockIdx.x * 256 + threadIdx.x) * 8;
    const float* src; uint32_t* dst; long long loc = w;
    if (loc < n0)            { src = s0; dst = d0; }
    else { loc -= n0; if (loc < n1) { src = s1; dst = d1; }
    else { loc -= n1; if (loc < n2) { src = s2; dst = d2; }
    else { loc -= n2; if (loc < n3) { src = s3; dst = d3; }
    else { loc -= n3; if (loc < n4) { src = s4; dst = d4; }
    else { loc -= n4; if (loc < n5) { src = s5; dst = d5; }
    else return; }}}}}
    #pragma unroll
    for (int j = 0; j < 2; j++) {
        float4 a = *(const float4*)(src + 2 * (loc + j * 4));
        float4 b = *(const float4*)(src + 2 * (loc + j * 4) + 4);
        uint4 o;
        o.x = pack_hi(a.x, a.y); o.y = pack_hi(a.z, a.w);
        o.z = pack_hi(b.x, b.y); o.w = pack_hi(b.z, b.w);
        *(uint4*)(dst + loc + j * 4) = o;
    }
}

// ---------------- embed + input layernorm -> f32 x ----------------
__global__ void embed_ln_k(const int* __restrict__ src, const float* __restrict__ emb,
                           const float* __restrict__ s, const float* __restrict__ b,
                           float* __restrict__ out) {
    int row = blockIdx.x, t = threadIdx.x;
    int tok = src[row];
    const float SC = 22.62741699796952f;
    float v0 = emb[(size_t)tok * E_DIM + t]       * SC;
    float v1 = emb[(size_t)tok * E_DIM + t + 256] * SC;
    float mean = blockSum(v0 + v1) * (1.f / E_DIM);
    float d0 = v0 - mean, d1 = v1 - mean;
    float var = blockSum(d0 * d0 + d1 * d1) * (1.f / E_DIM);
    float r = rsqrtf(var + 1e-5f);
    out[(size_t)row * E_DIM + t]       = d0 * r * s[t]       + b[t];
    out[(size_t)row * E_DIM + t + 256] = d1 * r * s[t + 256] + b[t + 256];
}

// ---------------- layernorm f32 -> split planes ----------------
__global__ void layernorm_split_k(const float* __restrict__ in, const float* __restrict__ s,
                                  const float* __restrict__ b,
                                  uint32_t* __restrict__ oh, uint32_t* __restrict__ ol) {
    int row = blockIdx.x, t = threadIdx.x;
    float2 v = *(const float2*)(in + (size_t)row * E_DIM + 2 * t);
    float mean = blockSum(v.x + v.y) * (1.f / E_DIM);
    float d0 = v.x - mean, d1 = v.y - mean;
    float var = blockSum(d0 * d0 + d1 * d1) * (1.f / E_DIM);
    float r = rsqrtf(var + 1e-5f);
    float y0 = d0 * r * s[2 * t]     + b[2 * t];
    float y1 = d1 * r * s[2 * t + 1] + b[2 * t + 1];
    uint32_t h, l;
    splitpack(y0, y1, h, l);
    oh[(size_t)row * 256 + t] = h;
    ol[(size_t)row * 256 + t] = l;
}

// ---------------- mma / ldmatrix / cp.async primitives ----------------
#define MMA_F16(C, A0, A1, A2, A3, B0, B1)                                      \
    asm volatile("mma.sync.aligned.m16n8k16.row.col.f32.f16.f16.f32 "           \
                 "{%0,%1,%2,%3},{%4,%5,%6,%7},{%8,%9},{%0,%1,%2,%3};"           \
                 : "+f"(C[0]), "+f"(C[1]), "+f"(C[2]), "+f"(C[3])               \
                 : "r"(A0), "r"(A1), "r"(A2), "r"(A3), "r"(B0), "r"(B1))

__device__ __forceinline__ void ldsm4(uint32_t& r0, uint32_t& r1, uint32_t& r2, uint32_t& r3,
                                      uint32_t addr) {
    asm volatile("ldmatrix.sync.aligned.m8n8.x4.shared.b16 {%0,%1,%2,%3}, [%4];"
                 : "=r"(r0), "=r"(r1), "=r"(r2), "=r"(r3) : "r"(addr));
}

__device__ __forceinline__ void cp16w(uint32_t* dst, const uint32_t* src, bool pred) {
    uint32_t d = (uint32_t)__cvta_generic_to_shared(dst);
    int sz = pred ? 16 : 0;
    asm volatile("cp.async.cg.shared.global [%0], [%1], 16, %2;"
                 :: "r"(d), "l"(src), "r"(sz));
}

// ---------------- fused attention: scores + rel-bias gather + mask + softmax ----------
// 64-row tiles: grid (4, 32), 2 CTAs/SM for chip fill.
#define ATT_STRIDE 36
#define ATT_SMEM ((64 * ATT_STRIDE + 256 * ATT_STRIDE) * 4 + 64 * 4 * 4)   // 47104
__global__ __launch_bounds__(256, 2)
void attn_k(const uint32_t* __restrict__ qkvH, const float* __restrict__ qr,
            uint32_t* __restrict__ ph) {
    extern __shared__ uint32_t asm_[];
    uint32_t* qs = asm_;
    uint32_t* ks = asm_ + 64 * ATT_STRIDE;
    float* red = (float*)(ks + 256 * ATT_STRIDE);   // [64][4]

    int tile = blockIdx.x;
    int bh = blockIdx.y;
    int zb = bh >> 3, zh = bh & 7;
    const uint32_t* Q = qkvH + (size_t)zb * (256 * 768) + zh * 32;
    const uint32_t* K = Q + 256;
    const float* qrb = qr + (size_t)bh * (256 * 512);
    int l0 = tile * 64;

    int tid = threadIdx.x, lane = tid & 31, wid = tid >> 5;

    {
        int qrow = tid >> 2, qseg = (tid & 3) * 8;   // 64 rows x 32 words
        const uint32_t* qsrc = Q + (size_t)(l0 + qrow) * 768 + qseg;
        uint32_t* qd = qs + qrow * ATT_STRIDE + qseg;
        cp16w(qd,     qsrc,     true);
        cp16w(qd + 4, qsrc + 4, true);
        const uint32_t* krow = K + (size_t)tid * 768;
        uint32_t* kd = ks + tid * ATT_STRIDE;
        #pragma unroll
        for (int j = 0; j < 8; j++) cp16w(kd + j * 4, krow + j * 4, true);
    }
    asm volatile("cp.async.commit_group;");
    asm volatile("cp.async.wait_group 0;");
    __syncthreads();

    int warpM = wid >> 2, warpN = wid & 3;
    int wm0 = warpM * 32, wn0 = warpN * 64;
    int g = lane >> 2, tg = lane & 3;
    uint32_t smQ = (uint32_t)__cvta_generic_to_shared(qs);
    uint32_t smK = (uint32_t)__cvta_generic_to_shared(ks);
    uint32_t a_base = smQ + ((uint32_t)(wm0 + (lane & 15)) * ATT_STRIDE + ((lane & 16) ? 4 : 0)) * 4;
    uint32_t b_base = smK + ((uint32_t)(wn0 + (lane & 7) + ((lane & 16) ? 8 : 0)) * ATT_STRIDE
                             + ((lane & 8) ? 4 : 0)) * 4;

    float acc[2][8][4] = {};
    #pragma unroll
    for (int c = 0; c < 4; c++) {
        uint32_t koff = (uint32_t)c * 32;
        uint32_t Bf[8][2];
        #pragma unroll
        for (int t = 0; t < 4; t++)
            ldsm4(Bf[2 * t][0], Bf[2 * t][1], Bf[2 * t + 1][0], Bf[2 * t + 1][1],
                  b_base + koff + (uint32_t)t * 16 * ATT_STRIDE * 4);
        #pragma unroll
        for (int mi = 0; mi < 2; mi++) {
            uint32_t Af[4];
            ldsm4(Af[0], Af[1], Af[2], Af[3],
                  a_base + koff + (uint32_t)mi * 16 * ATT_STRIDE * 4);
            #pragma unroll
            for (int ni = 0; ni < 8; ni++)
                MMA_F16(acc[mi][ni], Af[0], Af[1], Af[2], Af[3], Bf[ni][0], Bf[ni][1]);
        }
    }
    __syncthreads();

    #pragma unroll
    for (int mi = 0; mi < 2; mi++) {
        #pragma unroll
        for (int rr = 0; rr < 2; rr++) {
            int lrow = wm0 + mi * 16 + g + rr * 8;
            int lglob = l0 + lrow;
            const float* qrl = qrb + (size_t)lglob * 512 + (255 - lglob);
            #pragma unroll
            for (int ni = 0; ni < 8; ni++) {
                int m = wn0 + ni * 8 + tg * 2;
                float b0 = qrl[m], b1 = qrl[m + 1];
                acc[mi][ni][rr * 2]     = acc[mi][ni][rr * 2]     * 0.125f + b0 + ((m     > lglob) ? 1.f : 0.f);
                acc[mi][ni][rr * 2 + 1] = acc[mi][ni][rr * 2 + 1] * 0.125f + b1 + ((m + 1 > lglob) ? 1.f : 0.f);
            }
        }
    }

    float rmax[2][2];
    #pragma unroll
    for (int mi = 0; mi < 2; mi++)
        #pragma unroll
        for (int rr = 0; rr < 2; rr++) {
            float mx = -3.4e38f;
            #pragma unroll
            for (int ni = 0; ni < 8; ni++) {
                mx = fmaxf(mx, acc[mi][ni][rr * 2]);
                mx = fmaxf(mx, acc[mi][ni][rr * 2 + 1]);
            }
            mx = fmaxf(mx, __shfl_xor_sync(0xffffffffu, mx, 1));
            mx = fmaxf(mx, __shfl_xor_sync(0xffffffffu, mx, 2));
            int lrow = wm0 + mi * 16 + g + rr * 8;
            if (tg == 0) red[lrow * 4 + warpN] = mx;
            rmax[mi][rr] = 0.f;
        }
    __syncthreads();
    #pragma unroll
    for (int mi = 0; mi < 2; mi++)
        #pragma unroll
        for (int rr = 0; rr < 2; rr++) {
            int lrow = wm0 + mi * 16 + g + rr * 8;
            rmax[mi][rr] = fmaxf(fmaxf(red[lrow * 4 + 0], red[lrow * 4 + 1]),
                                 fmaxf(red[lrow * 4 + 2], red[lrow * 4 + 3]));
        }
    __syncthreads();

    float rsum[2][2];
    #pragma unroll
    for (int mi = 0; mi < 2; mi++)
        #pragma unroll
        for (int rr = 0; rr < 2; rr++) {
            float s = 0.f;
            #pragma unroll
            for (int ni = 0; ni < 8; ni++) {
                float e0 = expf(acc[mi][ni][rr * 2]     - rmax[mi][rr]);
                float e1 = expf(acc[mi][ni][rr * 2 + 1] - rmax[mi][rr]);
                acc[mi][ni][rr * 2] = e0; acc[mi][ni][rr * 2 + 1] = e1;
                s += e0 + e1;
            }
            s += __shfl_xor_sync(0xffffffffu, s, 1);
            s += __shfl_xor_sync(0xffffffffu, s, 2);
            int lrow = wm0 + mi * 16 + g + rr * 8;
            if (tg == 0) red[lrow * 4 + warpN] = s;
            rsum[mi][rr] = 0.f;
        }
    __syncthreads();
    #pragma unroll
    for (int mi = 0; mi < 2; mi++)
        #pragma unroll
        for (int rr = 0; rr < 2; rr++) {
            int lrow = wm0 + mi * 16 + g + rr * 8;
            rsum[mi][rr] = red[lrow * 4 + 0] + red[lrow * 4 + 1]
                         + red[lrow * 4 + 2] + red[lrow * 4 + 3];
        }

    uint32_t* pb = ph + (size_t)bh * (S_LEN * 128);
    #pragma unroll
    for (int mi = 0; mi < 2; mi++)
        #pragma unroll
        for (int rr = 0; rr < 2; rr++) {
            int lglob = l0 + wm0 + mi * 16 + g + rr * 8;
            float inv = 1.f / rsum[mi][rr];
            #pragma unroll
            for (int ni = 0; ni < 8; ni++) {
                float p0 = acc[mi][ni][rr * 2] * inv;
                float p1 = acc[mi][ni][rr * 2 + 1] * inv;
                pb[(size_t)lglob * 128 + (wn0 >> 1) + ni * 4 + tg] = pack_hi(p0, p1);
            }
        }
}

#define STAGES 5

// ---------------- fp16 GEMM, MT x 128 CTA tile, chunk k=16 (8 words) ----------------
// ALO: A hi+lo (2-term) vs hi only. B: pre-split hi plane.
// EPI: 0 f32 out (+bias); 1 f32 splitK atomicAdd (+bias at sk==0);
//      2 planes out bias+GELU; 3 planes out (+bias, Cl optional);
//      5 planes-hi out (+bias) with fused V-transpose side store (Cl = vT half buffer).
template<int EPI, int NSPLIT, int ALO, int MT>
__global__ __launch_bounds__(256, MT == 64 ? 3 : 2)
void bgemm(const uint32_t* __restrict__ Ah, const uint32_t* __restrict__ Al,
           const uint32_t* __restrict__ Bh,
           const float* __restrict__ bias,
           float* __restrict__ Cf, uint32_t* __restrict__ Ch, uint32_t* __restrict__ Cl,
           int M, int N, int Kw, int ldaw, int ldbw, int ldc,
           int aOffB, int aOffH, int bOffB, int bOffH, int cOffB, int cOffH) {
    extern __shared__ uint32_t smu[];
    constexpr int APW   = MT * 12;
    constexpr int BPW   = 128 * 12;
    constexpr int BOFFW = (1 + ALO) * APW;
    constexpr int STW   = BOFFW + BPW;
    constexpr int STB   = STW * 4;
    constexpr int WM    = MT / 2;
    constexpr int NMI   = MT / 32;

    int z = blockIdx.z;
    int sk = z % NSPLIT;
    int zz = z / NSPLIT;
    int zb = zz >> 3, zh = zz & 7;
    Ah += (size_t)zb * aOffB + (size_t)zh * aOffH;
    if (ALO) Al += (size_t)zb * aOffB + (size_t)zh * aOffH;
    Bh += (size_t)zb * bOffB + (size_t)zh * bOffH;
    size_t cAdj = (size_t)zb * cOffB + (size_t)zh * cOffH;
    if (EPI <= 1) Cf += cAdj;
    else if (EPI != 5) { Ch += cAdj; if (Cl) Cl += cAdj; }
    else Ch += cAdj;   // EPI==5: Cl is the vT half buffer (no batch adjust)

    int kLenW = Kw / NSPLIT;
    int kw0   = sk * kLenW;
    int nk    = kLenW >> 3;

    int tid  = threadIdx.x;
    int lane = tid & 31, wid = tid >> 5;
    int wm0 = (wid >> 2) * WM;
    int wn0 = (wid & 3) * 32;
    int g   = lane >> 2;
    int tg  = lane & 3;
    int row0 = blockIdx.y * MT, col0 = blockIdx.x * 128;

    uint32_t smBase = (uint32_t)__cvta_generic_to_shared(smu);
    uint32_t a_off = ((uint32_t)(wm0 + (lane & 15)) * 12 + ((lane & 16) ? 4 : 0)) * 4;
    uint32_t b_off = ((uint32_t)(wn0 + (lane & 7) + ((lane & 16) ? 8 : 0)) * 12
                      + ((lane & 8) ? 4 : 0)) * 4;

    float acc[NMI][4][4] = {};

    auto COMPUTE = [&](int buf) {
        uint32_t sb = smBase + (uint32_t)buf * STB;
        uint32_t aH = sb + a_off;
        uint32_t aL = aH + APW * 4;
        uint32_t bH = sb + BOFFW * 4 + b_off;
        uint32_t Bhf[4][2];
        ldsm4(Bhf[0][0], Bhf[0][1], Bhf[1][0], Bhf[1][1], bH);
        ldsm4(Bhf[2][0], Bhf[2][1], Bhf[3][0], Bhf[3][1], bH + 16 * 12 * 4);
        #pragma unroll
        for (int mi = 0; mi < NMI; mi++) {
            uint32_t Af[4];
            ldsm4(Af[0], Af[1], Af[2], Af[3], aH + (uint32_t)mi * 16 * 12 * 4);
            uint32_t Lf[4];
            if (ALO) ldsm4(Lf[0], Lf[1], Lf[2], Lf[3], aL + (uint32_t)mi * 16 * 12 * 4);
            #pragma unroll
            for (int ni = 0; ni < 4; ni++) {
                MMA_F16(acc[mi][ni], Af[0], Af[1], Af[2], Af[3], Bhf[ni][0], Bhf[ni][1]);
                if (ALO)
                    MMA_F16(acc[mi][ni], Lf[0], Lf[1], Lf[2], Lf[3], Bhf[ni][0], Bhf[ni][1]);
            }
        }
    };

    auto LOADNT = [&](int chunk, int buf) {
        int kws = kw0 + (chunk << 3);
        uint32_t* st = smu + buf * STW;
        if (MT == 128) {
            int r = tid >> 1, s = (tid & 1) * 4;
            cp16w(st + r * 12 + s, Ah + (size_t)(row0 + r) * ldaw + kws + s, true);
            if (ALO)
                cp16w(st + APW + r * 12 + s, Al + (size_t)(row0 + r) * ldaw + kws + s, true);
        } else {
            int r = (tid & 127) >> 1, s = (tid & 1) * 4;
            if (!ALO) {
                if (tid < 128)
                    cp16w(st + r * 12 + s, Ah + (size_t)(row0 + r) * ldaw + kws + s, true);
            } else {
                const uint32_t* srcp = (tid < 128) ? Ah : Al;
                uint32_t* dstp = st + ((tid < 128) ? 0 : APW);
                cp16w(dstp + r * 12 + s, srcp + (size_t)(row0 + r) * ldaw + kws + s, true);
            }
        }
        int rb = tid >> 1, sb2 = (tid & 1) * 4;
        bool p = (col0 + rb) < N;
        cp16w(st + BOFFW + rb * 12 + sb2, Bh + (size_t)(col0 + rb) * ldbw + kws + sb2, p);
    };

    int pre = (nk < STAGES - 1) ? nk : (STAGES - 1);
    for (int s = 0; s < pre; s++) {
        LOADNT(s, s);
        asm volatile("cp.async.commit_group;");
    }
    for (int i = 0; i < nk; i++) {
        int buf = i % STAGES;
        asm volatile("cp.async.wait_group %0;" :: "n"(STAGES - 2));
        __syncthreads();
        COMPUTE(buf);
        int nxt = i + STAGES - 1;
        if (nxt < nk) LOADNT(nxt, nxt % STAGES);
        asm volatile("cp.async.commit_group;");
    }

    // ---------------- epilogue ----------------
    #pragma unroll
    for (int mi = 0; mi < NMI; mi++) {
        #pragma unroll
        for (int rr = 0; rr < 2; rr++) {
            int r = row0 + wm0 + mi * 16 + g + rr * 8;
            #pragma unroll
            for (int ni = 0; ni < 4; ni++) {
                int c = col0 + wn0 + ni * 8 + tg * 2;
                float v0 = acc[mi][ni][rr * 2];
                float v1 = acc[mi][ni][rr * 2 + 1];
                if (EPI == 0) {
                    float* Crow = Cf + (size_t)r * ldc;
                    if (c + 1 < N) {
                        if (bias) { v0 += bias[c]; v1 += bias[c + 1]; }
                        *(float2*)&Crow[c] = make_float2(v0, v1);
                    } else if (c < N) {
                        if (bias) v0 += bias[c];
                        Crow[c] = v0;
                    }
                } else if (EPI == 1) {
                    float* Crow = Cf + (size_t)r * ldc;
                    if (bias && sk == 0) {
                        if (c < N)     v0 += bias[c];
                        if (c + 1 < N) v1 += bias[c + 1];
                    }
                    if (c < N)     atomicAdd(&Crow[c], v0);
                    if (c + 1 < N) atomicAdd(&Crow[c + 1], v1);
                } else if (EPI == 5) {
                    if (c < N) {
                        if (bias) { v0 += bias[c]; v1 += bias[c + 1]; }
                        uint32_t h = pack_hi(v0, v1);
                        Ch[(size_t)r * ldc + (c >> 1)] = h;
                        if (c >= 1024) {            // V range: side-store transposed halves
                            int d = c - 1024;
                            int b = r >> 8, s = r & 255;
                            __half* vTh = (__half*)Cl;
                            size_t base = ((size_t)(b * 8 + (d >> 6)) * 64 + (d & 63)) * 256 + s;
                            vTh[base]       = __ushort_as_half((unsigned short)(h & 0xffffu));
                            vTh[base + 256] = __ushort_as_half((unsigned short)(h >> 16));
                        }
                    }
                } else {
                    if (c < N) {
                        if (bias) { v0 += bias[c]; v1 += bias[c + 1]; }
                        if (EPI == 2) {
                            v0 = 0.5f * v0 * (1.f + erff(v0 * 0.7071067811865476f));
                            v1 = 0.5f * v1 * (1.f + erff(v1 * 0.7071067811865476f));
                        }
                        uint32_t h, l;
                        splitpack(v0, v1, h, l);
                        size_t idx = (size_t)r * ldc + (c >> 1);
                        Ch[idx] = h;
                        if (Cl) Cl[idx] = l;
                    }
                }
            }
        }
    }
}

#define SM_B(MT, ALO) (STAGES * (((1 + (ALO)) * (MT) * 12) + 128 * 12) * 4)

// ---------------- driver ----------------
extern "C" void kernel_launch(void* const* d_in, const int* in_sizes, int n_in,
                              void* d_out, int out_size) {
    const int*   src   = (const int*)  d_in[0];
    const float* emb   = (const float*)d_in[1];
    const float* rel   = (const float*)d_in[2];
    const float* nin_s = (const float*)d_in[3];
    const float* nin_b = (const float*)d_in[4];
    const float* inW   = (const float*)d_in[5];
    const float* inB   = (const float*)d_in[6];
    const float* outW  = (const float*)d_in[7];
    const float* outB  = (const float*)d_in[8];
    const float* ln1s  = (const float*)d_in[9];
    const float* ln1b  = (const float*)d_in[10];
    const float* ln2s  = (const float*)d_in[11];
    const float* ln2b  = (const float*)d_in[12];
    const float* w1    = (const float*)d_in[13];
    const float* b1    = (const float*)d_in[14];
    const float* w2    = (const float*)d_in[15];
    const float* b2    = (const float*)d_in[16];
    const float* nfs   = (const float*)d_in[17];
    const float* nfb   = (const float*)d_in[18];
    const float* decW  = (const float*)d_in[19];
    const float* decB  = (const float*)d_in[20];
    float* out = (float*)d_out;

    float *x, *qr;
    cudaGetSymbolAddress((void**)&x,  g_x);
    cudaGetSymbolAddress((void**)&qr, g_qr);
    uint32_t *hH,*hL,*qkvH,*prH,*vT,*oH,*oL,*gH,*gL;
    uint32_t *WiH,*WoH,*W1H,*W2H,*WdH,*relH;
    cudaGetSymbolAddress((void**)&hH,   p_h_hi);   cudaGetSymbolAddress((void**)&hL,   p_h_lo);
    cudaGetSymbolAddress((void**)&qkvH, p_qkv_hi);
    cudaGetSymbolAddress((void**)&prH,  p_pr_hi);
    cudaGetSymbolAddress((void**)&vT,   p_vT);
    cudaGetSymbolAddress((void**)&oH,   p_o_hi);   cudaGetSymbolAddress((void**)&oL,   p_o_lo);
    cudaGetSymbolAddress((void**)&gH,   p_g_hi);   cudaGetSymbolAddress((void**)&gL,   p_g_lo);
    cudaGetSymbolAddress((void**)&WiH,  p_Wi_hi);
    cudaGetSymbolAddress((void**)&WoH,  p_Wo_hi);
    cudaGetSymbolAddress((void**)&W1H,  p_W1_hi);
    cudaGetSymbolAddress((void**)&W2H,  p_W2_hi);
    cudaGetSymbolAddress((void**)&WdH,  p_Wd_hi);
    cudaGetSymbolAddress((void**)&relH, p_rel_hi);

    cudaFuncSetAttribute(bgemm<5,1,1,64>,  cudaFuncAttributeMaxDynamicSharedMemorySize, SM_B(64,1));
    cudaFuncSetAttribute(bgemm<0,1,0,128>, cudaFuncAttributeMaxDynamicSharedMemorySize, SM_B(128,0));
    cudaFuncSetAttribute(bgemm<3,1,0,64>,  cudaFuncAttributeMaxDynamicSharedMemorySize, SM_B(64,0));
    cudaFuncSetAttribute(bgemm<1,2,1,64>,  cudaFuncAttributeMaxDynamicSharedMemorySize, SM_B(64,1));
    cudaFuncSetAttribute(bgemm<2,1,1,64>,  cudaFuncAttributeMaxDynamicSharedMemorySize, SM_B(64,1));
    cudaFuncSetAttribute(attn_k,           cudaFuncAttributeMaxDynamicSharedMemorySize, ATT_SMEM);

    // single merged weight split: inW, outW, w1, w2, decW, rel
    {
        int n0 = 4*1536*256, n1 = 4*512*256, n2 = 4*2048*256,
            n3 = 4*512*1024, n4 = V_DIM*256, n5 = 511*256;
        long long total = (long long)n0 + n1 + n2 + n3 + n4 + n5;
        int blocks = (int)((total / 8 + 255) / 256);
        split_all_k<<<blocks, 256>>>(inW, outW, w1, w2, decW, rel,
                                     WiH, WoH, W1H, W2H, WdH, relH,
                                     n0, n1, n2, n3, n4, n5);
    }

    embed_ln_k<<<N_ROWS, 256>>>(src, emb, nin_s, nin_b, x);

    for (int l = 0; l < 4; l++) {
        const uint32_t* WiHl = WiH + (size_t)l * 1536 * 256;
        const uint32_t* WoHl = WoH + (size_t)l * 512 * 256;
        const uint32_t* W1Hl = W1H + (size_t)l * 2048 * 256;
        const uint32_t* W2Hl = W2H + (size_t)l * 512 * 1024;
        const float* inB_l  = inB  + (size_t)l * QKV_DIM;
        const float* outB_l = outB + (size_t)l * E_DIM;
        const float* b1_l   = b1   + (size_t)l * FF_DIM;
        const float* b2_l   = b2   + (size_t)l * E_DIM;

        layernorm_split_k<<<N_ROWS, 256>>>(x, ln1s + l*E_DIM, ln1b + l*E_DIM, hH, hL);

        // qkv hi plane = h @ inW^T + inB  (2-term A) + fused V-transpose side store
        bgemm<5,1,1,64><<<dim3(12, 16, 1), 256, SM_B(64,1)>>>(hH, hL, WiHl, inB_l,
            (float*)0, qkvH, vT, N_ROWS, QKV_DIM, 256, 256, 256, 768,
            0,0, 0,0, 0,0);

        // qr f32 = Q @ rel^T  (1-term, 128x128 tiles)
        bgemm<0,1,0,128><<<dim3(4, 2, N_BH), 256, SM_B(128,0)>>>(qkvH, (const uint32_t*)0, relH,
            (const float*)0, qr, (uint32_t*)0, (uint32_t*)0,
            S_LEN, 511, 32, 768, 256, 512,
            256*768, 32, 0, 32, 8*131072, 131072);

        // fused scores + bias + mask + softmax  (64-row tiles, 128 CTAs)
        attn_k<<<dim3(4, N_BH), 256, ATT_SMEM>>>(qkvH, qr, prH);

        // o planes = probs @ V^T  (1-term, 64x128 tiles)
        bgemm<3,1,0,64><<<dim3(1, 4, N_BH), 256, SM_B(64,0)>>>(prH, (const uint32_t*)0, vT,
            (const float*)0, (float*)0, oH, oL,
            S_LEN, 64, 128, 128, 128, 256,
            8*32768, 32768, 8*8192, 8192, 65536, 32);

        // x += o @ outW^T + outB   (splitK 2, 2-term A)
        bgemm<1,2,1,64><<<dim3(4, 16, 2), 256, SM_B(64,1)>>>(oH, oL, WoHl, outB_l,
            x, (uint32_t*)0, (uint32_t*)0, N_ROWS, E_DIM, 256, 256, 256, E_DIM,
            0,0, 0,0, 0,0);

        layernorm_split_k<<<N_ROWS, 256>>>(x, ln2s + l*E_DIM, ln2b + l*E_DIM, hH, hL);

        // g planes = gelu(h @ w1^T + b1)  (2-term A)
        bgemm<2,1,1,64><<<dim3(16, 16, 1), 256, SM_B(64,1)>>>(hH, hL, W1Hl, b1_l,
            (float*)0, gH, gL, N_ROWS, FF_DIM, 256, 256, 256, 1024,
            0,0, 0,0, 0,0);

        // x += g @ w2^T + b2   (splitK 2, 2-term A)
        bgemm<1,2,1,64><<<dim3(4, 16, 2), 256, SM_B(64,1)>>>(gH, gL, W2Hl, b2_l,
            x, (uint32_t*)0, (uint32_t*)0, N_ROWS, E_DIM, 1024, 1024, 1024, E_DIM,
            0,0, 0,0, 0,0);
    }

    layernorm_split_k<<<N_ROWS, 256>>>(x, nfs, nfb, hH, hL);

    // out f32 = h @ dec_w^T + dec_b   (1-term, 128x128 tiles)
    bgemm<0,1,0,128><<<dim3(250, 8, 1), 256, SM_B(128,0)>>>(hH, (const uint32_t*)0, WdH, decB,
        out, (uint32_t*)0, (uint32_t*)0, N_ROWS, V_DIM, 256, 256, 256, V_DIM,
        0,0, 0,0, 0,0);
}